// round 6
// baseline (speedup 1.0000x reference)
#include <cuda_runtime.h>
#include <math.h>

#define NB 4
#define NC 256
#define HWP 25600
#define NS 1024
#define NT 4096   // NB*NS

typedef unsigned long long u64;

__device__ __forceinline__ u64 dup2(float v) {
    u64 r; asm("mov.b64 %0, {%1, %1};" : "=l"(r) : "f"(v)); return r;
}
__device__ __forceinline__ void fma2(u64& d, u64 a, u64 b) {
    asm("fma.rn.f32x2 %0, %1, %2, %0;" : "+l"(d) : "l"(a), "l"(b));
}
__device__ __forceinline__ float2 unpk(u64 v) {
    float2 f; asm("mov.b64 {%0, %1}, %2;" : "=f"(f.x), "=f"(f.y) : "l"(v)); return f;
}

// ---------- scratch ----------
__device__ float d_G[NC*NT];        // gathered feats [c][col]
__device__ float d_Hp[2*NC*NT];     // gemm1 split-K partials
__device__ float d_H[NC*NT];        // relu(Hp0+Hp1+b1)
__device__ float d_Pp[2*NC*NT];     // gemm2 split-K partials
__device__ float d_P[NC*NT];        // Pp0+Pp1+b2
__device__ float d_attn[NT];
__device__ float d_ss[NT];
__device__ int   d_idx[NT];
__device__ int   d_sel[NT];
__device__ int   d_spv[NT];
__device__ int   d_vlist[NT];
__device__ int   d_ilist[NT];
__device__ float d_rowA[NT];
__device__ float d_rowB[NT];
__device__ float d_rowD[NT];

// ---------- fused selection ----------
__global__ void k_prep(const long long* __restrict__ labels, const long long* __restrict__ sp) {
    int b = blockIdx.x, t = threadIdx.x;          // 1024 threads
    const long long* lb = labels + (long long)b*HWP;
    int base = t*25;
    unsigned flags = 0; int cnt = 0;
    #pragma unroll
    for (int j = 0; j < 25; j++) {
        int f = (lb[base+j] == 1);
        flags |= (unsigned)f << j; cnt += f;
    }
    __shared__ int wsum[32];
    __shared__ int s_nv;
    int lane = t & 31, w = t >> 5;
    int incl = cnt;
    #pragma unroll
    for (int o = 1; o < 32; o <<= 1) {
        int n = __shfl_up_sync(0xffffffffu, incl, o);
        if (lane >= o) incl += n;
    }
    if (lane == 31) wsum[w] = incl;
    __syncthreads();
    if (t < 32) {
        int v = wsum[t]; int inc2 = v;
        #pragma unroll
        for (int o = 1; o < 32; o <<= 1) {
            int n = __shfl_up_sync(0xffffffffu, inc2, o);
            if (t >= o) inc2 += n;
        }
        wsum[t] = inc2 - v;
        if (t == 31) s_nv = inc2;
    }
    __syncthreads();
    int v_run = (incl - cnt) + wsum[w];
    #pragma unroll
    for (int j = 0; j < 25; j++) {
        int p = base + j;
        if ((flags >> j) & 1u) {
            if (v_run < NS) d_vlist[b*NS + v_run] = p;
            v_run++;
        } else {
            int ir = p - v_run;
            if (ir < NS) d_ilist[b*NS + ir] = p;
        }
    }
    __syncthreads();
    int nv = s_nv; if (nv > NS) nv = NS;
    int s = t;
    int p, se;
    if (s < nv) { p = d_vlist[b*NS + s];        se = 1; }
    else        { p = d_ilist[b*NS + (s - nv)]; se = 0; }
    int col = b*NS + s;
    d_idx[col] = p;
    d_sel[col] = se;
    d_spv[col] = (int)sp[(long long)b*HWP + p];
    d_rowA[col] = 0.f; d_rowB[col] = 0.f; d_rowD[col] = 0.f; d_ss[col] = 0.f;
}

// ---------- gather feats -> G[c][col] ----------
__global__ void k_gather(const float* __restrict__ feats) {
    int t = threadIdx.x;
    int s = blockIdx.x*256 + t;
    int b = blockIdx.z;
    int c0 = blockIdx.y*16;
    int col = b*NS + s;
    int p = d_idx[col];
    const float* fb = feats + ((long long)b*NC + c0)*HWP + p;
    float* g = d_G + (long long)c0*NT + col;
    #pragma unroll
    for (int cc = 0; cc < 16; cc++) {
        g[(long long)cc*NT] = __ldg(&fb[(long long)cc*HWP]);
    }
}

// ---------- split-K 64x128 tile, 128 threads, 8x8/thread, double-buffered ----------
// Writes RAW partial sums (no bias/activation) to Yp.
__device__ __forceinline__ void gemm_sk(const float* __restrict__ W,
                                        const float* __restrict__ X, float* __restrict__ Yp,
                                        int m0, int n0, int k0) {
    __shared__ float As[2][16][68];      // [stage][k][m 0..63]
    __shared__ float Bs[2][16][132];     // [stage][k][col 0..127]
    int t = threadIdx.x;
    int tx = t & 15, ty = t >> 4;        // cols tx*8, rows ty*8
    int am = t >> 1, ak = (t & 1) * 8;
    int bk = t >> 3, bc = (t & 7) * 16;

    float4 pa0 = *(const float4*)&W[(m0+am)*NC + k0 + ak];
    float4 pa1 = *(const float4*)&W[(m0+am)*NC + k0 + ak + 4];
    float4 pb0 = *(const float4*)&X[(k0+bk)*NT + n0 + bc];
    float4 pb1 = *(const float4*)&X[(k0+bk)*NT + n0 + bc + 4];
    float4 pb2 = *(const float4*)&X[(k0+bk)*NT + n0 + bc + 8];
    float4 pb3 = *(const float4*)&X[(k0+bk)*NT + n0 + bc + 12];
    {
        float av[8]; *(float4*)av = pa0; *(float4*)(av+4) = pa1;
        #pragma unroll
        for (int i = 0; i < 8; i++) As[0][ak+i][am] = av[i];
        *(float4*)&Bs[0][bk][bc]    = pb0;
        *(float4*)&Bs[0][bk][bc+4]  = pb1;
        *(float4*)&Bs[0][bk][bc+8]  = pb2;
        *(float4*)&Bs[0][bk][bc+12] = pb3;
    }
    __syncthreads();

    u64 acc2[8][4] = {};
    for (int c = 0; c < 8; c++) {        // 8 chunks of 16 = K 128
        int cur = c & 1;
        if (c < 7) {
            int kk = k0 + (c+1)*16;
            pa0 = *(const float4*)&W[(m0+am)*NC + kk + ak];
            pa1 = *(const float4*)&W[(m0+am)*NC + kk + ak + 4];
            pb0 = *(const float4*)&X[(kk+bk)*NT + n0 + bc];
            pb1 = *(const float4*)&X[(kk+bk)*NT + n0 + bc + 4];
            pb2 = *(const float4*)&X[(kk+bk)*NT + n0 + bc + 8];
            pb3 = *(const float4*)&X[(kk+bk)*NT + n0 + bc + 12];
        }
        #pragma unroll
        for (int k = 0; k < 16; k++) {
            float4 a0 = *(float4*)&As[cur][k][ty*8];
            float4 a1 = *(float4*)&As[cur][k][ty*8+4];
            ulonglong2 b0 = *(ulonglong2*)&Bs[cur][k][tx*8];
            ulonglong2 b1 = *(ulonglong2*)&Bs[cur][k][tx*8+4];
            u64 ad[8];
            ad[0]=dup2(a0.x); ad[1]=dup2(a0.y); ad[2]=dup2(a0.z); ad[3]=dup2(a0.w);
            ad[4]=dup2(a1.x); ad[5]=dup2(a1.y); ad[6]=dup2(a1.z); ad[7]=dup2(a1.w);
            #pragma unroll
            for (int r = 0; r < 8; r++) {
                fma2(acc2[r][0], ad[r], b0.x);
                fma2(acc2[r][1], ad[r], b0.y);
                fma2(acc2[r][2], ad[r], b1.x);
                fma2(acc2[r][3], ad[r], b1.y);
            }
        }
        if (c < 7) {
            int nxt = cur ^ 1;
            float av[8]; *(float4*)av = pa0; *(float4*)(av+4) = pa1;
            #pragma unroll
            for (int i = 0; i < 8; i++) As[nxt][ak+i][am] = av[i];
            *(float4*)&Bs[nxt][bk][bc]    = pb0;
            *(float4*)&Bs[nxt][bk][bc+4]  = pb1;
            *(float4*)&Bs[nxt][bk][bc+8]  = pb2;
            *(float4*)&Bs[nxt][bk][bc+12] = pb3;
        }
        __syncthreads();
    }
    #pragma unroll
    for (int r = 0; r < 8; r++) {
        float vv[8];
        #pragma unroll
        for (int cp = 0; cp < 4; cp++) {
            float2 p2 = unpk(acc2[r][cp]);
            vv[cp*2] = p2.x; vv[cp*2+1] = p2.y;
        }
        float* yp = &Yp[(m0+ty*8+r)*NT + n0 + tx*8];
        *(float4*)yp = *(float4*)vv; *(float4*)(yp+4) = *(float4*)(vv+4);
    }
}

// ---------- attention tile: 32 cols, 128 threads ----------
__device__ __forceinline__ void attn_tile(const float* __restrict__ wa1, const float* __restrict__ ba1,
                                          const float* __restrict__ wa2, const float* __restrict__ ba2,
                                          const float* __restrict__ X, int n0) {
    __shared__ float Aa[16][68];     // [k][m 0..63]
    __shared__ float Ba[16][36];     // [k][col 0..31]
    __shared__ float stg[4][32];
    int t = threadIdx.x;
    int c = t & 31, g = t >> 5;      // col c, rows g*16 .. g*16+15
    int am = t >> 1, ak = (t & 1) * 8;
    int bk = t >> 3, bc = (t & 7) * 4;
    float4 pa0 = *(const float4*)&wa1[am*NC + ak];
    float4 pa1 = *(const float4*)&wa1[am*NC + ak + 4];
    float4 pb = *(const float4*)&X[bk*NT + n0 + bc];
    float acc[16] = {};
    for (int kk = 0; kk < NC; kk += 16) {
        {
            float av[8]; *(float4*)av = pa0; *(float4*)(av+4) = pa1;
            #pragma unroll
            for (int i = 0; i < 8; i++) Aa[ak+i][am] = av[i];
            *(float4*)&Ba[bk][bc] = pb;
        }
        __syncthreads();
        if (kk + 16 < NC) {
            pa0 = *(const float4*)&wa1[am*NC + kk+16 + ak];
            pa1 = *(const float4*)&wa1[am*NC + kk+16 + ak + 4];
            pb  = *(const float4*)&X[(kk+16+bk)*NT + n0 + bc];
        }
        #pragma unroll
        for (int k = 0; k < 16; k++) {
            float bv = Ba[k][c];
            #pragma unroll
            for (int r = 0; r < 16; r++)
                acc[r] = fmaf(Aa[k][g*16+r], bv, acc[r]);
        }
        __syncthreads();
    }
    float part = 0.f;
    #pragma unroll
    for (int r = 0; r < 16; r++) {
        int m = g*16 + r;
        part = fmaf(wa2[m], fmaxf(acc[r] + ba1[m], 0.f), part);
    }
    stg[g][c] = part;
    __syncthreads();
    if (t < 32) {
        float sm = stg[0][t] + stg[1][t] + stg[2][t] + stg[3][t];
        float z = sm + ba2[0];
        d_attn[n0 + t] = 1.f / (1.f + expf(-z));
    }
}

// ---------- gemm1 (split-K) + attn ----------
__global__ __launch_bounds__(128) void k_g1a(const float* __restrict__ w1,
                      const float* __restrict__ wa1, const float* __restrict__ ba1,
                      const float* __restrict__ wa2, const float* __restrict__ ba2,
                      const float* __restrict__ X, float* __restrict__ Yp) {
    int x = blockIdx.x, y = blockIdx.y;
    if (y < 8) {
        int split = y >> 2;
        gemm_sk(w1, X, Yp + split*(NC*NT), (y & 3)*64, x*128, split*128);
    } else {
        int a = (y - 8)*32 + x;   // 0..127
        attn_tile(wa1, ba1, wa2, ba2, X, a*32);
    }
}

// ---------- gemm2 (split-K) ----------
__global__ __launch_bounds__(128) void k_gemm2(const float* __restrict__ w2,
                        const float* __restrict__ X, float* __restrict__ Yp) {
    int x = blockIdx.x, y = blockIdx.y;
    int split = y >> 2;
    gemm_sk(w2, X, Yp + split*(NC*NT), (y & 3)*64, x*128, split*128);
}

// ---------- merge gemm1 partials: H = relu(Hp0+Hp1+b1) ----------
__global__ void k_act(const float* __restrict__ b1) {
    int i = blockIdx.x*256 + threadIdx.x;      // float4 index, NC*NT/4 total
    int m = i >> 10;                           // NT/4 = 1024 float4 per row
    float bv = b1[m];
    const float4* p0 = (const float4*)d_Hp;
    const float4* p1 = (const float4*)(d_Hp + NC*NT);
    float4 a = p0[i], b = p1[i];
    float4 o;
    o.x = fmaxf(a.x + b.x + bv, 0.f);
    o.y = fmaxf(a.y + b.y + bv, 0.f);
    o.z = fmaxf(a.z + b.z + bv, 0.f);
    o.w = fmaxf(a.w + b.w + bv, 0.f);
    ((float4*)d_H)[i] = o;
}

// ---------- merge gemm2 partials + column sumsq: P = Pp0+Pp1+b2, ss ----------
__global__ void k_rnorm(const float* __restrict__ b2) {
    int col = blockIdx.x*128 + threadIdx.x;    // 0..4095
    int mseg = blockIdx.y;                     // 0..3 -> m rows mseg*64..+63
    float ss = 0.f;
    #pragma unroll 4
    for (int r = 0; r < 64; r++) {
        int m = mseg*64 + r;
        float v = d_Pp[m*NT + col] + d_Pp[NC*NT + m*NT + col] + b2[m];
        d_P[m*NT + col] = v;
        ss = fmaf(v, v, ss);
    }
    atomicAdd(&d_ss[col], ss);
}

// ---------- fused sim + contrastive reductions, 256 threads, 8x8, double-buffered ----------
__global__ __launch_bounds__(256, 1) void k_sim() {
    int b = blockIdx.z;
    int pid = blockIdx.x;                // 0..35 -> (I<=J)
    int I = 0, rem = pid;
    while (rem >= (8 - I)) { rem -= (8 - I); I++; }
    int J = I + rem;
    int i0 = I*128, j0 = J*128;
    bool diag = (I == J);
    const float* Pb = d_P + b*NS;

    __shared__ float As[2][16][132], Bs[2][16][132];
    __shared__ int   spI[128], spJ[128], seI[128], seJ[128];
    __shared__ float wI[128], wJ[128], rnI[128], rnJ[128];
    __shared__ float stage[3][8][128];

    int t = threadIdx.x;
    int tx = t & 15, ty = t >> 4;        // cols tx*8, rows ty*8
    if (t < 128) {
        int ci = b*NS + i0 + t;
        spI[t] = d_spv[ci]; seI[t] = d_sel[ci]; wI[t] = d_attn[ci];
        rnI[t] = 1.f / fmaxf(sqrtf(d_ss[ci]), 1e-12f);
    } else {
        int u = t - 128;
        int cj = b*NS + j0 + u;
        spJ[u] = d_spv[cj]; seJ[u] = d_sel[cj]; wJ[u] = d_attn[cj];
        rnJ[u] = 1.f / fmaxf(sqrtf(d_ss[cj]), 1e-12f);
    }

    int k_l = t >> 4, c0 = (t & 15) * 8;
    float4 ra0 = *(const float4*)&Pb[k_l*NT + i0 + c0];
    float4 ra1 = *(const float4*)&Pb[k_l*NT + i0 + c0 + 4];
    float4 rb0 = *(const float4*)&Pb[k_l*NT + j0 + c0];
    float4 rb1 = *(const float4*)&Pb[k_l*NT + j0 + c0 + 4];
    *(float4*)&As[0][k_l][c0]   = ra0;
    *(float4*)&As[0][k_l][c0+4] = ra1;
    *(float4*)&Bs[0][k_l][c0]   = rb0;
    *(float4*)&Bs[0][k_l][c0+4] = rb1;
    __syncthreads();

    u64 acc2[8][4] = {};
    for (int c = 0; c < 16; c++) {
        int cur = c & 1;
        if (c < 15) {
            const float* rp = Pb + ((c+1)*16 + k_l)*NT;
            ra0 = *(const float4*)&rp[i0 + c0];
            ra1 = *(const float4*)&rp[i0 + c0 + 4];
            rb0 = *(const float4*)&rp[j0 + c0];
            rb1 = *(const float4*)&rp[j0 + c0 + 4];
        }
        #pragma unroll
        for (int k = 0; k < 16; k++) {
            float4 a0 = *(float4*)&As[cur][k][ty*8];
            float4 a1 = *(float4*)&As[cur][k][ty*8+4];
            ulonglong2 b0 = *(ulonglong2*)&Bs[cur][k][tx*8];
            ulonglong2 b1 = *(ulonglong2*)&Bs[cur][k][tx*8+4];
            u64 ad[8];
            ad[0]=dup2(a0.x); ad[1]=dup2(a0.y); ad[2]=dup2(a0.z); ad[3]=dup2(a0.w);
            ad[4]=dup2(a1.x); ad[5]=dup2(a1.y); ad[6]=dup2(a1.z); ad[7]=dup2(a1.w);
            #pragma unroll
            for (int r = 0; r < 8; r++) {
                fma2(acc2[r][0], ad[r], b0.x);
                fma2(acc2[r][1], ad[r], b0.y);
                fma2(acc2[r][2], ad[r], b1.x);
                fma2(acc2[r][3], ad[r], b1.y);
            }
        }
        if (c < 15) {
            int nxt = cur ^ 1;
            *(float4*)&As[nxt][k_l][c0]   = ra0;
            *(float4*)&As[nxt][k_l][c0+4] = ra1;
            *(float4*)&Bs[nxt][k_l][c0]   = rb0;
            *(float4*)&Bs[nxt][k_l][c0+4] = rb1;
        }
        __syncthreads();
    }

    // epilogue
    float colA[8] = {}, colB[8] = {}, colD[8] = {};
    #pragma unroll
    for (int r = 0; r < 8; r++) {
        int il = ty*8 + r, gi = i0 + il;
        int si = seI[il], spi = spI[il];
        float wi = wI[il], ri = rnI[il];
        float sv[8];
        #pragma unroll
        for (int cp = 0; cp < 4; cp++) {
            float2 p2 = unpk(acc2[r][cp]);
            sv[cp*2] = p2.x; sv[cp*2+1] = p2.y;
        }
        float rA = 0.f, rB = 0.f, rD = 0.f;
        #pragma unroll
        for (int q = 0; q < 8; q++) {
            int jl = tx*8 + q, gj = j0 + jl;
            float s = sv[q] * ri * rnJ[jl];
            float e = __expf(10.0f * s);           // 1/TEMP = 10
            int sj = seJ[jl];
            if (sj) rD += e;
            if (!diag && si) colD[q] += e;
            if (si && sj && (gi != gj) && (spi == spJ[jl]) && (s > 0.7f)) {
                float pw = wi * wJ[jl];
                rB += pw; rA = fmaf(pw, s, rA);
                if (!diag) { colB[q] += pw; colA[q] = fmaf(pw, s, colA[q]); }
            }
        }
        #pragma unroll
        for (int off = 8; off >= 1; off >>= 1) {
            rA += __shfl_down_sync(0xffffffffu, rA, off, 16);
            rB += __shfl_down_sync(0xffffffffu, rB, off, 16);
            rD += __shfl_down_sync(0xffffffffu, rD, off, 16);
        }
        if ((t & 15) == 0) {
            atomicAdd(&d_rowA[b*NS + gi], rA);
            atomicAdd(&d_rowB[b*NS + gi], rB);
            atomicAdd(&d_rowD[b*NS + gi], rD);
        }
    }
    if (!diag) {
        int w = t >> 5;      // 0..7
        #pragma unroll
        for (int q = 0; q < 8; q++) {
            colA[q] += __shfl_xor_sync(0xffffffffu, colA[q], 16);
            colB[q] += __shfl_xor_sync(0xffffffffu, colB[q], 16);
            colD[q] += __shfl_xor_sync(0xffffffffu, colD[q], 16);
        }
        if ((t & 31) < 16) {
            #pragma unroll
            for (int q = 0; q < 8; q++) {
                stage[0][w][tx*8+q] = colA[q];
                stage[1][w][tx*8+q] = colB[q];
                stage[2][w][tx*8+q] = colD[q];
            }
        }
        __syncthreads();
        if (t < 128) {
            float a0=0.f, b0=0.f, d0=0.f;
            #pragma unroll
            for (int ww = 0; ww < 8; ww++) {
                a0 += stage[0][ww][t]; b0 += stage[1][ww][t]; d0 += stage[2][ww][t];
            }
            atomicAdd(&d_rowA[b*NS + j0 + t], a0);
            atomicAdd(&d_rowB[b*NS + j0 + t], b0);
            atomicAdd(&d_rowD[b*NS + j0 + t], d0);
        }
    }
}

// ---------- final reduction ----------
__global__ void k_final(float* __restrict__ out) {
    __shared__ float red[256];
    __shared__ float s_num, s_ps;
    int t = threadIdx.x;
    float totLoss = 0.f;
    int nHas = 0;
    for (int b = 0; b < NB; b++) {
        float num = 0.f, ps = 0.f;
        for (int i = t; i < NS; i += 256) {
            float Ai = d_rowA[b*NS+i], Bi = d_rowB[b*NS+i], Di = d_rowD[b*NS+i];
            float ld = logf(Di > 0.f ? Di : 1.f);
            num += Ai * 10.0f - ld * Bi;
            ps  += Bi;
        }
        red[t] = num; __syncthreads();
        for (int o = 128; o > 0; o >>= 1) { if (t < o) red[t] += red[t+o]; __syncthreads(); }
        if (t == 0) s_num = red[0];
        __syncthreads();
        red[t] = ps; __syncthreads();
        for (int o = 128; o > 0; o >>= 1) { if (t < o) red[t] += red[t+o]; __syncthreads(); }
        if (t == 0) s_ps = red[0];
        __syncthreads();
        if (t == 0) {
            if (s_ps > 0.f) {
                totLoss += -(0.1f/0.07f) * s_num / s_ps;
                nHas++;
            }
        }
        __syncthreads();
    }
    if (t == 0) out[0] = (nHas > 0) ? (totLoss / fmaxf((float)nHas, 1.f)) : 0.f;
}

extern "C" void kernel_launch(void* const* d_in, const int* in_sizes, int n_in,
                              void* d_out, int out_size) {
    const float*     feats  = (const float*)d_in[0];
    const long long* labels = (const long long*)d_in[1];
    const long long* sp     = (const long long*)d_in[2];
    const float*     w1     = (const float*)d_in[3];
    const float*     b1     = (const float*)d_in[4];
    const float*     w2     = (const float*)d_in[5];
    const float*     b2     = (const float*)d_in[6];
    const float*     wa1    = (const float*)d_in[7];
    const float*     ba1    = (const float*)d_in[8];
    const float*     wa2    = (const float*)d_in[9];
    const float*     ba2    = (const float*)d_in[10];
    float* out = (float*)d_out;

    static float* pG = nullptr; static float* pHp = nullptr; static float* pH = nullptr;
    static float* pPp = nullptr;
    if (!pG) {
        cudaGetSymbolAddress((void**)&pG,  d_G);
        cudaGetSymbolAddress((void**)&pHp, d_Hp);
        cudaGetSymbolAddress((void**)&pH,  d_H);
        cudaGetSymbolAddress((void**)&pPp, d_Pp);
    }

    k_prep  <<<NB, 1024>>>(labels, sp);
    k_gather<<<dim3(NS/256, NC/16, NB), 256>>>(feats);
    k_g1a   <<<dim3(32, 12), 128>>>(w1, wa1, ba1, wa2, ba2, pG, pHp);
    k_act   <<<NC*NT/4/256, 256>>>(b1);
    k_gemm2 <<<dim3(32, 8), 128>>>(w2, pH, pPp);
    k_rnorm <<<dim3(32, 4), 128>>>(b2);
    k_sim   <<<dim3(36, 1, NB), 256>>>();
    k_final <<<1, 256>>>(out);
}

// round 7
// speedup vs baseline: 1.0145x; 1.0145x over previous
#include <cuda_runtime.h>
#include <math.h>

#define NB 4
#define NC 256
#define HWP 25600
#define NS 1024
#define NT 4096   // NB*NS

typedef unsigned long long u64;

__device__ __forceinline__ u64 dup2(float v) {
    u64 r; asm("mov.b64 %0, {%1, %1};" : "=l"(r) : "f"(v)); return r;
}
__device__ __forceinline__ void fma2(u64& d, u64 a, u64 b) {
    asm("fma.rn.f32x2 %0, %1, %2, %0;" : "+l"(d) : "l"(a), "l"(b));
}
__device__ __forceinline__ float2 unpk(u64 v) {
    float2 f; asm("mov.b64 {%0, %1}, %2;" : "=f"(f.x), "=f"(f.y) : "l"(v)); return f;
}

// ---------- scratch ----------
__device__ float d_G[NC*NT];
__device__ float d_H[NC*NT];
__device__ float d_P[NC*NT];
__device__ float d_attn[NT];
__device__ float d_ss[NT];
__device__ int   d_idx[NT];
__device__ int   d_sel[NT];
__device__ int   d_spv[NT];
__device__ int   d_vlist[NT];
__device__ int   d_ilist[NT];
__device__ float d_rowA[NT];
__device__ float d_rowB[NT];
__device__ float d_rowD[NT];

// ---------- fused selection ----------
__global__ void k_prep(const long long* __restrict__ labels, const long long* __restrict__ sp) {
    int b = blockIdx.x, t = threadIdx.x;          // 1024 threads
    const long long* lb = labels + (long long)b*HWP;
    int base = t*25;
    unsigned flags = 0; int cnt = 0;
    #pragma unroll
    for (int j = 0; j < 25; j++) {
        int f = (lb[base+j] == 1);
        flags |= (unsigned)f << j; cnt += f;
    }
    __shared__ int wsum[32];
    __shared__ int s_nv;
    int lane = t & 31, w = t >> 5;
    int incl = cnt;
    #pragma unroll
    for (int o = 1; o < 32; o <<= 1) {
        int n = __shfl_up_sync(0xffffffffu, incl, o);
        if (lane >= o) incl += n;
    }
    if (lane == 31) wsum[w] = incl;
    __syncthreads();
    if (t < 32) {
        int v = wsum[t]; int inc2 = v;
        #pragma unroll
        for (int o = 1; o < 32; o <<= 1) {
            int n = __shfl_up_sync(0xffffffffu, inc2, o);
            if (t >= o) inc2 += n;
        }
        wsum[t] = inc2 - v;
        if (t == 31) s_nv = inc2;
    }
    __syncthreads();
    int v_run = (incl - cnt) + wsum[w];
    #pragma unroll
    for (int j = 0; j < 25; j++) {
        int p = base + j;
        if ((flags >> j) & 1u) {
            if (v_run < NS) d_vlist[b*NS + v_run] = p;
            v_run++;
        } else {
            int ir = p - v_run;
            if (ir < NS) d_ilist[b*NS + ir] = p;
        }
    }
    __syncthreads();
    int nv = s_nv; if (nv > NS) nv = NS;
    int s = t;
    int p, se;
    if (s < nv) { p = d_vlist[b*NS + s];        se = 1; }
    else        { p = d_ilist[b*NS + (s - nv)]; se = 0; }
    int col = b*NS + s;
    d_idx[col] = p;
    d_sel[col] = se;
    d_spv[col] = (int)sp[(long long)b*HWP + p];
    d_rowA[col] = 0.f; d_rowB[col] = 0.f; d_rowD[col] = 0.f; d_ss[col] = 0.f;
}

// ---------- gather feats -> G[c][col] ----------
__global__ void k_gather(const float* __restrict__ feats) {
    int t = threadIdx.x;
    int s = blockIdx.x*256 + t;
    int b = blockIdx.z;
    int c0 = blockIdx.y*16;
    int col = b*NS + s;
    int p = d_idx[col];
    const float* fb = feats + ((long long)b*NC + c0)*HWP + p;
    float* g = d_G + (long long)c0*NT + col;
    #pragma unroll
    for (int cc = 0; cc < 16; cc++) {
        g[(long long)cc*NT] = __ldg(&fb[(long long)cc*HWP]);
    }
}

// ---------- 64x128 tile, 256 threads, 4x8/thread, double-buffered ----------
template<bool RELU, bool NORM>
__device__ __forceinline__ void gemm_tile(const float* __restrict__ W, const float* __restrict__ bias,
                                          const float* __restrict__ X, float* __restrict__ Y,
                                          int m0, int n0) {
    __shared__ float As[2][16][68];      // [stage][k][m 0..63]
    __shared__ float Bs[2][16][132];     // [stage][k][col 0..127]
    __shared__ float s_ss[128];
    int t = threadIdx.x;
    int tx = t & 15, ty = t >> 4;        // cols tx*8, rows ty*4
    int am = t >> 2, ak = (t & 3) * 4;   // A fill: row am (0..63), k ak..ak+3
    int bk = t >> 4, bc = (t & 15) * 8;  // B fill: k row bk, cols bc..bc+7
    if (NORM && t < 128) s_ss[t] = 0.f;

    float4 pa  = *(const float4*)&W[(m0+am)*NC + ak];
    float4 pb0 = *(const float4*)&X[bk*NT + n0 + bc];
    float4 pb1 = *(const float4*)&X[bk*NT + n0 + bc + 4];
    As[0][ak+0][am]=pa.x; As[0][ak+1][am]=pa.y; As[0][ak+2][am]=pa.z; As[0][ak+3][am]=pa.w;
    *(float4*)&Bs[0][bk][bc]   = pb0;
    *(float4*)&Bs[0][bk][bc+4] = pb1;
    __syncthreads();

    u64 acc2[4][4] = {};
    for (int c = 0; c < 16; c++) {
        int cur = c & 1;
        if (c < 15) {
            int kk = (c+1)*16;
            pa  = *(const float4*)&W[(m0+am)*NC + kk + ak];
            pb0 = *(const float4*)&X[(kk+bk)*NT + n0 + bc];
            pb1 = *(const float4*)&X[(kk+bk)*NT + n0 + bc + 4];
        }
        #pragma unroll
        for (int k = 0; k < 16; k++) {
            float4 a4 = *(float4*)&As[cur][k][ty*4];
            ulonglong2 b0 = *(ulonglong2*)&Bs[cur][k][tx*8];
            ulonglong2 b1 = *(ulonglong2*)&Bs[cur][k][tx*8+4];
            u64 ad[4];
            ad[0]=dup2(a4.x); ad[1]=dup2(a4.y); ad[2]=dup2(a4.z); ad[3]=dup2(a4.w);
            #pragma unroll
            for (int r = 0; r < 4; r++) {
                fma2(acc2[r][0], ad[r], b0.x);
                fma2(acc2[r][1], ad[r], b0.y);
                fma2(acc2[r][2], ad[r], b1.x);
                fma2(acc2[r][3], ad[r], b1.y);
            }
        }
        if (c < 15) {
            int nxt = cur ^ 1;
            As[nxt][ak+0][am]=pa.x; As[nxt][ak+1][am]=pa.y; As[nxt][ak+2][am]=pa.z; As[nxt][ak+3][am]=pa.w;
            *(float4*)&Bs[nxt][bk][bc]   = pb0;
            *(float4*)&Bs[nxt][bk][bc+4] = pb1;
        }
        __syncthreads();
    }

    float ssq[8] = {};
    #pragma unroll
    for (int r = 0; r < 4; r++) {
        float bv = bias[m0 + ty*4 + r];
        float vv[8];
        #pragma unroll
        for (int cp = 0; cp < 4; cp++) {
            float2 p2 = unpk(acc2[r][cp]);
            vv[cp*2] = p2.x + bv; vv[cp*2+1] = p2.y + bv;
        }
        #pragma unroll
        for (int q = 0; q < 8; q++) {
            if (RELU) vv[q] = fmaxf(vv[q], 0.f);
            if (NORM) ssq[q] = fmaf(vv[q], vv[q], ssq[q]);
        }
        float* yp = &Y[(m0+ty*4+r)*NT + n0 + tx*8];
        *(float4*)yp = *(float4*)vv; *(float4*)(yp+4) = *(float4*)(vv+4);
    }
    if (NORM) {
        #pragma unroll
        for (int q = 0; q < 8; q++) atomicAdd(&s_ss[tx*8+q], ssq[q]);
        __syncthreads();
        if (t < 128) atomicAdd(&d_ss[n0 + t], s_ss[t]);
    }
}

// ---------- attention tile: 64 cols, 256 threads ----------
__device__ __forceinline__ void attn_tile(const float* __restrict__ wa1, const float* __restrict__ ba1,
                                          const float* __restrict__ wa2, const float* __restrict__ ba2,
                                          const float* __restrict__ X, int n0) {
    __shared__ float Aa[16][68];     // [k][m 0..63]
    __shared__ float Ba[16][68];     // [k][col 0..63]
    __shared__ float stg[4][64];
    int t = threadIdx.x;
    int c = t & 63, g = t >> 6;      // col c, rows g*16 .. g*16+15
    int am = t >> 2, ak = (t & 3) * 4;
    int bk = t >> 4, bc = (t & 15) * 4;
    float4 pa = *(const float4*)&wa1[am*NC + ak];
    float4 pb = *(const float4*)&X[bk*NT + n0 + bc];
    float acc[16] = {};
    for (int kk = 0; kk < NC; kk += 16) {
        Aa[ak+0][am]=pa.x; Aa[ak+1][am]=pa.y; Aa[ak+2][am]=pa.z; Aa[ak+3][am]=pa.w;
        *(float4*)&Ba[bk][bc] = pb;
        __syncthreads();
        if (kk + 16 < NC) {
            pa = *(const float4*)&wa1[am*NC + kk+16 + ak];
            pb = *(const float4*)&X[(kk+16+bk)*NT + n0 + bc];
        }
        #pragma unroll
        for (int k = 0; k < 16; k++) {
            float bv = Ba[k][c];
            #pragma unroll
            for (int r = 0; r < 16; r++)
                acc[r] = fmaf(Aa[k][g*16+r], bv, acc[r]);
        }
        __syncthreads();
    }
    float part = 0.f;
    #pragma unroll
    for (int r = 0; r < 16; r++) {
        int m = g*16 + r;
        part = fmaf(wa2[m], fmaxf(acc[r] + ba1[m], 0.f), part);
    }
    stg[g][c] = part;
    __syncthreads();
    if (t < 64) {
        float sm = stg[0][t] + stg[1][t] + stg[2][t] + stg[3][t];
        float z = sm + ba2[0];
        d_attn[n0 + t] = 1.f / (1.f + expf(-z));
    }
}

// ---------- gemm1 + attn ----------
__global__ __launch_bounds__(256) void k_g1a(const float* __restrict__ w1, const float* __restrict__ b1,
                      const float* __restrict__ wa1, const float* __restrict__ ba1,
                      const float* __restrict__ wa2, const float* __restrict__ ba2,
                      const float* __restrict__ X, float* __restrict__ Y) {
    int x = blockIdx.x, y = blockIdx.y;
    if (y < 4) {
        gemm_tile<true, false>(w1, b1, X, Y, y*64, x*128);
    } else {
        int a = (y - 4)*32 + x;   // 0..63
        attn_tile(wa1, ba1, wa2, ba2, X, a*64);
    }
}

__global__ __launch_bounds__(256) void k_gemm2(const float* __restrict__ w2, const float* __restrict__ b2,
                        const float* __restrict__ X, float* __restrict__ Y) {
    gemm_tile<false, true>(w2, b2, X, Y, blockIdx.y*64, blockIdx.x*128);
}

// ---------- fused sim + contrastive reductions, 256 threads, 8x8, double-buffered ----------
__global__ __launch_bounds__(256, 1) void k_sim() {
    int b = blockIdx.z;
    int pid = blockIdx.x;                // 0..35 -> (I<=J)
    int I = 0, rem = pid;
    while (rem >= (8 - I)) { rem -= (8 - I); I++; }
    int J = I + rem;
    int i0 = I*128, j0 = J*128;
    bool diag = (I == J);
    const float* Pb = d_P + b*NS;

    __shared__ float As[2][16][132], Bs[2][16][132];
    __shared__ int   spI[128], spJ[128], seI[128], seJ[128];
    __shared__ float wI[128], wJ[128], rnI[128], rnJ[128];
    __shared__ float stage[3][8][128];

    int t = threadIdx.x;
    int tx = t & 15, ty = t >> 4;        // cols tx*8, rows ty*8
    if (t < 128) {
        int ci = b*NS + i0 + t;
        spI[t] = d_spv[ci]; seI[t] = d_sel[ci]; wI[t] = d_attn[ci];
        rnI[t] = 1.f / fmaxf(sqrtf(d_ss[ci]), 1e-12f);
    } else {
        int u = t - 128;
        int cj = b*NS + j0 + u;
        spJ[u] = d_spv[cj]; seJ[u] = d_sel[cj]; wJ[u] = d_attn[cj];
        rnJ[u] = 1.f / fmaxf(sqrtf(d_ss[cj]), 1e-12f);
    }

    int k_l = t >> 4, c0 = (t & 15) * 8;
    float4 ra0 = *(const float4*)&Pb[k_l*NT + i0 + c0];
    float4 ra1 = *(const float4*)&Pb[k_l*NT + i0 + c0 + 4];
    float4 rb0 = *(const float4*)&Pb[k_l*NT + j0 + c0];
    float4 rb1 = *(const float4*)&Pb[k_l*NT + j0 + c0 + 4];
    *(float4*)&As[0][k_l][c0]   = ra0;
    *(float4*)&As[0][k_l][c0+4] = ra1;
    *(float4*)&Bs[0][k_l][c0]   = rb0;
    *(float4*)&Bs[0][k_l][c0+4] = rb1;
    __syncthreads();

    u64 acc2[8][4] = {};
    for (int c = 0; c < 16; c++) {
        int cur = c & 1;
        if (c < 15) {
            const float* rp = Pb + ((c+1)*16 + k_l)*NT;
            ra0 = *(const float4*)&rp[i0 + c0];
            ra1 = *(const float4*)&rp[i0 + c0 + 4];
            rb0 = *(const float4*)&rp[j0 + c0];
            rb1 = *(const float4*)&rp[j0 + c0 + 4];
        }
        #pragma unroll
        for (int k = 0; k < 16; k++) {
            float4 a0 = *(float4*)&As[cur][k][ty*8];
            float4 a1 = *(float4*)&As[cur][k][ty*8+4];
            ulonglong2 b0 = *(ulonglong2*)&Bs[cur][k][tx*8];
            ulonglong2 b1 = *(ulonglong2*)&Bs[cur][k][tx*8+4];
            u64 ad[8];
            ad[0]=dup2(a0.x); ad[1]=dup2(a0.y); ad[2]=dup2(a0.z); ad[3]=dup2(a0.w);
            ad[4]=dup2(a1.x); ad[5]=dup2(a1.y); ad[6]=dup2(a1.z); ad[7]=dup2(a1.w);
            #pragma unroll
            for (int r = 0; r < 8; r++) {
                fma2(acc2[r][0], ad[r], b0.x);
                fma2(acc2[r][1], ad[r], b0.y);
                fma2(acc2[r][2], ad[r], b1.x);
                fma2(acc2[r][3], ad[r], b1.y);
            }
        }
        if (c < 15) {
            int nxt = cur ^ 1;
            *(float4*)&As[nxt][k_l][c0]   = ra0;
            *(float4*)&As[nxt][k_l][c0+4] = ra1;
            *(float4*)&Bs[nxt][k_l][c0]   = rb0;
            *(float4*)&Bs[nxt][k_l][c0+4] = rb1;
        }
        __syncthreads();
    }

    // epilogue
    float colA[8] = {}, colB[8] = {}, colD[8] = {};
    #pragma unroll
    for (int r = 0; r < 8; r++) {
        int il = ty*8 + r, gi = i0 + il;
        int si = seI[il], spi = spI[il];
        float wi = wI[il], ri = rnI[il];
        float sv[8];
        #pragma unroll
        for (int cp = 0; cp < 4; cp++) {
            float2 p2 = unpk(acc2[r][cp]);
            sv[cp*2] = p2.x; sv[cp*2+1] = p2.y;
        }
        float rA = 0.f, rB = 0.f, rD = 0.f;
        #pragma unroll
        for (int q = 0; q < 8; q++) {
            int jl = tx*8 + q, gj = j0 + jl;
            float s = sv[q] * ri * rnJ[jl];
            float e = __expf(10.0f * s);           // 1/TEMP = 10
            int sj = seJ[jl];
            if (sj) rD += e;
            if (!diag && si) colD[q] += e;
            if (si && sj && (gi != gj) && (spi == spJ[jl]) && (s > 0.7f)) {
                float pw = wi * wJ[jl];
                rB += pw; rA = fmaf(pw, s, rA);
                if (!diag) { colB[q] += pw; colA[q] = fmaf(pw, s, colA[q]); }
            }
        }
        #pragma unroll
        for (int off = 8; off >= 1; off >>= 1) {
            rA += __shfl_down_sync(0xffffffffu, rA, off, 16);
            rB += __shfl_down_sync(0xffffffffu, rB, off, 16);
            rD += __shfl_down_sync(0xffffffffu, rD, off, 16);
        }
        if ((t & 15) == 0) {
            atomicAdd(&d_rowA[b*NS + gi], rA);
            atomicAdd(&d_rowB[b*NS + gi], rB);
            atomicAdd(&d_rowD[b*NS + gi], rD);
        }
    }
    if (!diag) {
        int w = t >> 5;      // 0..7
        #pragma unroll
        for (int q = 0; q < 8; q++) {
            colA[q] += __shfl_xor_sync(0xffffffffu, colA[q], 16);
            colB[q] += __shfl_xor_sync(0xffffffffu, colB[q], 16);
            colD[q] += __shfl_xor_sync(0xffffffffu, colD[q], 16);
        }
        if ((t & 31) < 16) {
            #pragma unroll
            for (int q = 0; q < 8; q++) {
                stage[0][w][tx*8+q] = colA[q];
                stage[1][w][tx*8+q] = colB[q];
                stage[2][w][tx*8+q] = colD[q];
            }
        }
        __syncthreads();
        if (t < 128) {
            float a0=0.f, b0=0.f, d0=0.f;
            #pragma unroll
            for (int ww = 0; ww < 8; ww++) {
                a0 += stage[0][ww][t]; b0 += stage[1][ww][t]; d0 += stage[2][ww][t];
            }
            atomicAdd(&d_rowA[b*NS + j0 + t], a0);
            atomicAdd(&d_rowB[b*NS + j0 + t], b0);
            atomicAdd(&d_rowD[b*NS + j0 + t], d0);
        }
    }
}

// ---------- final reduction ----------
__global__ void k_final(float* __restrict__ out) {
    __shared__ float red[256];
    __shared__ float s_num, s_ps;
    int t = threadIdx.x;
    float totLoss = 0.f;
    int nHas = 0;
    for (int b = 0; b < NB; b++) {
        float num = 0.f, ps = 0.f;
        for (int i = t; i < NS; i += 256) {
            float Ai = d_rowA[b*NS+i], Bi = d_rowB[b*NS+i], Di = d_rowD[b*NS+i];
            float ld = logf(Di > 0.f ? Di : 1.f);
            num += Ai * 10.0f - ld * Bi;
            ps  += Bi;
        }
        red[t] = num; __syncthreads();
        for (int o = 128; o > 0; o >>= 1) { if (t < o) red[t] += red[t+o]; __syncthreads(); }
        if (t == 0) s_num = red[0];
        __syncthreads();
        red[t] = ps; __syncthreads();
        for (int o = 128; o > 0; o >>= 1) { if (t < o) red[t] += red[t+o]; __syncthreads(); }
        if (t == 0) s_ps = red[0];
        __syncthreads();
        if (t == 0) {
            if (s_ps > 0.f) {
                totLoss += -(0.1f/0.07f) * s_num / s_ps;
                nHas++;
            }
        }
        __syncthreads();
    }
    if (t == 0) out[0] = (nHas > 0) ? (totLoss / fmaxf((float)nHas, 1.f)) : 0.f;
}

extern "C" void kernel_launch(void* const* d_in, const int* in_sizes, int n_in,
                              void* d_out, int out_size) {
    const float*     feats  = (const float*)d_in[0];
    const long long* labels = (const long long*)d_in[1];
    const long long* sp     = (const long long*)d_in[2];
    const float*     w1     = (const float*)d_in[3];
    const float*     b1     = (const float*)d_in[4];
    const float*     w2     = (const float*)d_in[5];
    const float*     b2     = (const float*)d_in[6];
    const float*     wa1    = (const float*)d_in[7];
    const float*     ba1    = (const float*)d_in[8];
    const float*     wa2    = (const float*)d_in[9];
    const float*     ba2    = (const float*)d_in[10];
    float* out = (float*)d_out;

    static float* pG = nullptr; static float* pH = nullptr;
    if (!pG) {
        cudaGetSymbolAddress((void**)&pG, d_G);
        cudaGetSymbolAddress((void**)&pH, d_H);
    }
    static float* pP = nullptr;
    if (!pP) cudaGetSymbolAddress((void**)&pP, d_P);

    k_prep  <<<NB, 1024>>>(labels, sp);
    k_gather<<<dim3(NS/256, NC/16, NB), 256>>>(feats);
    k_g1a   <<<dim3(32, 6), 256>>>(w1, b1, wa1, ba1, wa2, ba2, pG, pH);
    k_gemm2 <<<dim3(32, 4), 256>>>(w2, b2, pH, pP);
    k_sim   <<<dim3(36, 1, NB), 256>>>();
    k_final <<<1, 256>>>(out);
}

// round 8
// speedup vs baseline: 1.2143x; 1.1969x over previous
#include <cuda_runtime.h>
#include <math.h>

#define NB 4
#define NC 256
#define HWP 25600
#define NS 1024
#define NT 4096   // NB*NS

typedef unsigned long long u64;

__device__ __forceinline__ u64 dup2(float v) {
    u64 r; asm("mov.b64 %0, {%1, %1};" : "=l"(r) : "f"(v)); return r;
}
__device__ __forceinline__ void fma2(u64& d, u64 a, u64 b) {
    asm("fma.rn.f32x2 %0, %1, %2, %0;" : "+l"(d) : "l"(a), "l"(b));
}
__device__ __forceinline__ float2 unpk(u64 v) {
    float2 f; asm("mov.b64 {%0, %1}, %2;" : "=f"(f.x), "=f"(f.y) : "l"(v)); return f;
}

// ---------- scratch ----------
__device__ float d_G[NC*NT];
__device__ float d_H[NC*NT];
__device__ float d_P[NC*NT];
__device__ float d_attn[NT];
__device__ float d_ss[NT];
__device__ int   d_idx[NT];
__device__ int   d_sel[NT];
__device__ int   d_spv[NT];
__device__ int   d_vlist[NT];
__device__ int   d_ilist[NT];
__device__ float d_rowA[NT];
__device__ float d_rowB[NT];
__device__ float d_rowD[NT];

// ---------- fused selection ----------
__global__ void k_prep(const long long* __restrict__ labels, const long long* __restrict__ sp) {
    int b = blockIdx.x, t = threadIdx.x;          // 1024 threads
    const long long* lb = labels + (long long)b*HWP;
    int base = t*25;
    unsigned flags = 0; int cnt = 0;
    #pragma unroll
    for (int j = 0; j < 25; j++) {
        int f = (lb[base+j] == 1);
        flags |= (unsigned)f << j; cnt += f;
    }
    __shared__ int wsum[32];
    __shared__ int s_nv;
    int lane = t & 31, w = t >> 5;
    int incl = cnt;
    #pragma unroll
    for (int o = 1; o < 32; o <<= 1) {
        int n = __shfl_up_sync(0xffffffffu, incl, o);
        if (lane >= o) incl += n;
    }
    if (lane == 31) wsum[w] = incl;
    __syncthreads();
    if (t < 32) {
        int v = wsum[t]; int inc2 = v;
        #pragma unroll
        for (int o = 1; o < 32; o <<= 1) {
            int n = __shfl_up_sync(0xffffffffu, inc2, o);
            if (t >= o) inc2 += n;
        }
        wsum[t] = inc2 - v;
        if (t == 31) s_nv = inc2;
    }
    __syncthreads();
    int v_run = (incl - cnt) + wsum[w];
    #pragma unroll
    for (int j = 0; j < 25; j++) {
        int p = base + j;
        if ((flags >> j) & 1u) {
            if (v_run < NS) d_vlist[b*NS + v_run] = p;
            v_run++;
        } else {
            int ir = p - v_run;
            if (ir < NS) d_ilist[b*NS + ir] = p;
        }
    }
    __syncthreads();
    int nv = s_nv; if (nv > NS) nv = NS;
    int s = t;
    int p, se;
    if (s < nv) { p = d_vlist[b*NS + s];        se = 1; }
    else        { p = d_ilist[b*NS + (s - nv)]; se = 0; }
    int col = b*NS + s;
    d_idx[col] = p;
    d_sel[col] = se;
    d_spv[col] = (int)sp[(long long)b*HWP + p];
    d_rowA[col] = 0.f; d_rowB[col] = 0.f; d_rowD[col] = 0.f; d_ss[col] = 0.f;
}

// ---------- gather feats -> G[c][col] ----------
__global__ void k_gather(const float* __restrict__ feats) {
    int t = threadIdx.x;
    int s = blockIdx.x*256 + t;
    int b = blockIdx.z;
    int c0 = blockIdx.y*16;
    int col = b*NS + s;
    int p = d_idx[col];
    const float* fb = feats + ((long long)b*NC + c0)*HWP + p;
    float* g = d_G + (long long)c0*NT + col;
    #pragma unroll
    for (int cc = 0; cc < 16; cc++) {
        g[(long long)cc*NT] = __ldg(&fb[(long long)cc*HWP]);
    }
}

// ---------- 64x64 tile, 256 threads, 4x4/thread FFMA2, double-buffered ----------
template<bool RELU, bool NORM>
__device__ __forceinline__ void gemm_tile(const float* __restrict__ W, const float* __restrict__ bias,
                                          const float* __restrict__ X, float* __restrict__ Y,
                                          int m0, int n0) {
    __shared__ float As[2][16][68];   // [stage][k][m 0..63]
    __shared__ float Bs[2][16][68];   // [stage][k][col 0..63]
    __shared__ float s_ss[64];
    int t = threadIdx.x;
    int tx = t & 15, ty = t >> 4;     // cols tx*4, rows ty*4
    int am = t >> 2, ak = (t & 3) * 4;
    int bk = t >> 4, bc = (t & 15) * 4;
    if (NORM && t < 64) s_ss[t] = 0.f;

    float4 pa = *(const float4*)&W[(m0+am)*NC + ak];
    float4 pb = *(const float4*)&X[bk*NT + n0 + bc];
    As[0][ak+0][am]=pa.x; As[0][ak+1][am]=pa.y; As[0][ak+2][am]=pa.z; As[0][ak+3][am]=pa.w;
    *(float4*)&Bs[0][bk][bc] = pb;
    __syncthreads();

    u64 acc2[4][2] = {};
    for (int c = 0; c < 16; c++) {
        int cur = c & 1;
        if (c < 15) {
            int kk = (c+1)*16;
            pa = *(const float4*)&W[(m0+am)*NC + kk + ak];
            pb = *(const float4*)&X[(kk+bk)*NT + n0 + bc];
        }
        #pragma unroll
        for (int k = 0; k < 16; k++) {
            float4 a4 = *(float4*)&As[cur][k][ty*4];
            ulonglong2 bp = *(ulonglong2*)&Bs[cur][k][tx*4];
            u64 ad[4];
            ad[0] = dup2(a4.x); ad[1] = dup2(a4.y); ad[2] = dup2(a4.z); ad[3] = dup2(a4.w);
            #pragma unroll
            for (int r = 0; r < 4; r++) {
                fma2(acc2[r][0], ad[r], bp.x);
                fma2(acc2[r][1], ad[r], bp.y);
            }
        }
        if (c < 15) {
            int nxt = cur ^ 1;
            As[nxt][ak+0][am]=pa.x; As[nxt][ak+1][am]=pa.y; As[nxt][ak+2][am]=pa.z; As[nxt][ak+3][am]=pa.w;
            *(float4*)&Bs[nxt][bk][bc] = pb;
        }
        __syncthreads();
    }
    float ssq[4] = {};
    #pragma unroll
    for (int r = 0; r < 4; r++) {
        float bv = bias[m0 + ty*4 + r];
        float2 c01 = unpk(acc2[r][0]);
        float2 c23 = unpk(acc2[r][1]);
        float vv[4] = {c01.x + bv, c01.y + bv, c23.x + bv, c23.y + bv};
        #pragma unroll
        for (int q = 0; q < 4; q++) {
            if (RELU) vv[q] = fmaxf(vv[q], 0.f);
            if (NORM) ssq[q] = fmaf(vv[q], vv[q], ssq[q]);
        }
        *(float4*)&Y[(m0+ty*4+r)*NT + n0 + tx*4] = *(float4*)vv;
    }
    if (NORM) {
        #pragma unroll
        for (int q = 0; q < 4; q++) atomicAdd(&s_ss[tx*4+q], ssq[q]);
        __syncthreads();
        if (t < 64) atomicAdd(&d_ss[n0 + t], s_ss[t]);
    }
}

// ---------- attention tile: 32 cols, 256 threads ----------
__device__ __forceinline__ void attn_tile(const float* __restrict__ wa1, const float* __restrict__ ba1,
                                          const float* __restrict__ wa2, const float* __restrict__ ba2,
                                          const float* __restrict__ X, int n0) {
    __shared__ float Aa[16][68];     // [k][m], m 0..63
    __shared__ float Ba[16][36];     // [k][col], col 0..31
    __shared__ float stg[8][32];
    int t = threadIdx.x;
    int c = t & 31, g = t >> 5;      // col c, rows g*8..g*8+7
    int am = t >> 2, ak = (t & 3) * 4;
    int bk = t >> 4, bc = (t & 15) * 2;
    float4 pa = *(const float4*)&wa1[am*NC + ak];
    float2 pb = *(const float2*)&X[bk*NT + n0 + bc];
    float acc[8] = {};
    for (int kk = 0; kk < NC; kk += 16) {
        Aa[ak+0][am]=pa.x; Aa[ak+1][am]=pa.y; Aa[ak+2][am]=pa.z; Aa[ak+3][am]=pa.w;
        *(float2*)&Ba[bk][bc] = pb;
        __syncthreads();
        if (kk + 16 < NC) {
            pa = *(const float4*)&wa1[am*NC + kk+16 + ak];
            pb = *(const float2*)&X[(kk+16+bk)*NT + n0 + bc];
        }
        #pragma unroll
        for (int k = 0; k < 16; k++) {
            float bv = Ba[k][c];
            #pragma unroll
            for (int r = 0; r < 8; r++)
                acc[r] = fmaf(Aa[k][g*8+r], bv, acc[r]);
        }
        __syncthreads();
    }
    float part = 0.f;
    #pragma unroll
    for (int r = 0; r < 8; r++) {
        int m = g*8 + r;
        part = fmaf(wa2[m], fmaxf(acc[r] + ba1[m], 0.f), part);
    }
    stg[g][c] = part;
    __syncthreads();
    if (t < 32) {
        float sm = 0.f;
        #pragma unroll
        for (int gg = 0; gg < 8; gg++) sm += stg[gg][t];
        float z = sm + ba2[0];
        d_attn[n0 + t] = 1.f / (1.f + expf(-z));
    }
}

// ---------- gemm1 + attn ----------
__global__ __launch_bounds__(256) void k_g1a(const float* __restrict__ w1, const float* __restrict__ b1,
                      const float* __restrict__ wa1, const float* __restrict__ ba1,
                      const float* __restrict__ wa2, const float* __restrict__ ba2,
                      const float* __restrict__ X, float* __restrict__ Y) {
    int x = blockIdx.x, y = blockIdx.y;
    if (y < 4) {
        gemm_tile<true, false>(w1, b1, X, Y, y*64, x*64);
    } else {
        int a = (y - 4)*64 + x;   // 0..127
        attn_tile(wa1, ba1, wa2, ba2, X, a*32);
    }
}

__global__ __launch_bounds__(256) void k_gemm2(const float* __restrict__ w2, const float* __restrict__ b2,
                        const float* __restrict__ X, float* __restrict__ Y) {
    gemm_tile<false, true>(w2, b2, X, Y, blockIdx.y*64, blockIdx.x*64);
}

// ---------- fused sim + contrastive reductions, 256 threads, 8x8, double-buffered ----------
__global__ __launch_bounds__(256, 1) void k_sim() {
    int b = blockIdx.z;
    int pid = blockIdx.x;                // 0..35 -> (I<=J)
    int I = 0, rem = pid;
    while (rem >= (8 - I)) { rem -= (8 - I); I++; }
    int J = I + rem;
    int i0 = I*128, j0 = J*128;
    bool diag = (I == J);
    const float* Pb = d_P + b*NS;

    __shared__ float As[2][16][132], Bs[2][16][132];
    __shared__ int   spI[128], spJ[128], seI[128], seJ[128];
    __shared__ float wI[128], wJ[128], rnI[128], rnJ[128];
    __shared__ float stage[3][8][128];

    int t = threadIdx.x;
    int tx = t & 15, ty = t >> 4;        // cols tx*8, rows ty*8
    if (t < 128) {
        int ci = b*NS + i0 + t;
        spI[t] = d_spv[ci]; seI[t] = d_sel[ci]; wI[t] = d_attn[ci];
        rnI[t] = 1.f / fmaxf(sqrtf(d_ss[ci]), 1e-12f);
    } else {
        int u = t - 128;
        int cj = b*NS + j0 + u;
        spJ[u] = d_spv[cj]; seJ[u] = d_sel[cj]; wJ[u] = d_attn[cj];
        rnJ[u] = 1.f / fmaxf(sqrtf(d_ss[cj]), 1e-12f);
    }

    int k_l = t >> 4, c0 = (t & 15) * 8;
    float4 ra0 = *(const float4*)&Pb[k_l*NT + i0 + c0];
    float4 ra1 = *(const float4*)&Pb[k_l*NT + i0 + c0 + 4];
    float4 rb0 = *(const float4*)&Pb[k_l*NT + j0 + c0];
    float4 rb1 = *(const float4*)&Pb[k_l*NT + j0 + c0 + 4];
    *(float4*)&As[0][k_l][c0]   = ra0;
    *(float4*)&As[0][k_l][c0+4] = ra1;
    *(float4*)&Bs[0][k_l][c0]   = rb0;
    *(float4*)&Bs[0][k_l][c0+4] = rb1;
    __syncthreads();

    u64 acc2[8][4] = {};
    for (int c = 0; c < 16; c++) {
        int cur = c & 1;
        if (c < 15) {
            const float* rp = Pb + ((c+1)*16 + k_l)*NT;
            ra0 = *(const float4*)&rp[i0 + c0];
            ra1 = *(const float4*)&rp[i0 + c0 + 4];
            rb0 = *(const float4*)&rp[j0 + c0];
            rb1 = *(const float4*)&rp[j0 + c0 + 4];
        }
        #pragma unroll
        for (int k = 0; k < 16; k++) {
            float4 a0 = *(float4*)&As[cur][k][ty*8];
            float4 a1 = *(float4*)&As[cur][k][ty*8+4];
            ulonglong2 b0 = *(ulonglong2*)&Bs[cur][k][tx*8];
            ulonglong2 b1 = *(ulonglong2*)&Bs[cur][k][tx*8+4];
            u64 ad[8];
            ad[0]=dup2(a0.x); ad[1]=dup2(a0.y); ad[2]=dup2(a0.z); ad[3]=dup2(a0.w);
            ad[4]=dup2(a1.x); ad[5]=dup2(a1.y); ad[6]=dup2(a1.z); ad[7]=dup2(a1.w);
            #pragma unroll
            for (int r = 0; r < 8; r++) {
                fma2(acc2[r][0], ad[r], b0.x);
                fma2(acc2[r][1], ad[r], b0.y);
                fma2(acc2[r][2], ad[r], b1.x);
                fma2(acc2[r][3], ad[r], b1.y);
            }
        }
        if (c < 15) {
            int nxt = cur ^ 1;
            *(float4*)&As[nxt][k_l][c0]   = ra0;
            *(float4*)&As[nxt][k_l][c0+4] = ra1;
            *(float4*)&Bs[nxt][k_l][c0]   = rb0;
            *(float4*)&Bs[nxt][k_l][c0+4] = rb1;
        }
        __syncthreads();
    }

    // epilogue
    float colA[8] = {}, colB[8] = {}, colD[8] = {};
    #pragma unroll
    for (int r = 0; r < 8; r++) {
        int il = ty*8 + r, gi = i0 + il;
        int si = seI[il], spi = spI[il];
        float wi = wI[il], ri = rnI[il];
        float sv[8];
        #pragma unroll
        for (int cp = 0; cp < 4; cp++) {
            float2 p2 = unpk(acc2[r][cp]);
            sv[cp*2] = p2.x; sv[cp*2+1] = p2.y;
        }
        float rA = 0.f, rB = 0.f, rD = 0.f;
        #pragma unroll
        for (int q = 0; q < 8; q++) {
            int jl = tx*8 + q, gj = j0 + jl;
            float s = sv[q] * ri * rnJ[jl];
            float e = __expf(10.0f * s);           // 1/TEMP = 10
            int sj = seJ[jl];
            if (sj) rD += e;
            if (!diag && si) colD[q] += e;
            if (si && sj && (gi != gj) && (spi == spJ[jl]) && (s > 0.7f)) {
                float pw = wi * wJ[jl];
                rB += pw; rA = fmaf(pw, s, rA);
                if (!diag) { colB[q] += pw; colA[q] = fmaf(pw, s, colA[q]); }
            }
        }
        #pragma unroll
        for (int off = 8; off >= 1; off >>= 1) {
            rA += __shfl_down_sync(0xffffffffu, rA, off, 16);
            rB += __shfl_down_sync(0xffffffffu, rB, off, 16);
            rD += __shfl_down_sync(0xffffffffu, rD, off, 16);
        }
        if ((t & 15) == 0) {
            atomicAdd(&d_rowA[b*NS + gi], rA);
            atomicAdd(&d_rowB[b*NS + gi], rB);
            atomicAdd(&d_rowD[b*NS + gi], rD);
        }
    }
    if (!diag) {
        int w = t >> 5;      // 0..7
        #pragma unroll
        for (int q = 0; q < 8; q++) {
            colA[q] += __shfl_xor_sync(0xffffffffu, colA[q], 16);
            colB[q] += __shfl_xor_sync(0xffffffffu, colB[q], 16);
            colD[q] += __shfl_xor_sync(0xffffffffu, colD[q], 16);
        }
        if ((t & 31) < 16) {
            #pragma unroll
            for (int q = 0; q < 8; q++) {
                stage[0][w][tx*8+q] = colA[q];
                stage[1][w][tx*8+q] = colB[q];
                stage[2][w][tx*8+q] = colD[q];
            }
        }
        __syncthreads();
        if (t < 128) {
            float a0=0.f, b0=0.f, d0=0.f;
            #pragma unroll
            for (int ww = 0; ww < 8; ww++) {
                a0 += stage[0][ww][t]; b0 += stage[1][ww][t]; d0 += stage[2][ww][t];
            }
            atomicAdd(&d_rowA[b*NS + j0 + t], a0);
            atomicAdd(&d_rowB[b*NS + j0 + t], b0);
            atomicAdd(&d_rowD[b*NS + j0 + t], d0);
        }
    }
}

// ---------- final reduction ----------
__global__ void k_final(float* __restrict__ out) {
    __shared__ float red[256];
    __shared__ float s_num, s_ps;
    int t = threadIdx.x;
    float totLoss = 0.f;
    int nHas = 0;
    for (int b = 0; b < NB; b++) {
        float num = 0.f, ps = 0.f;
        for (int i = t; i < NS; i += 256) {
            float Ai = d_rowA[b*NS+i], Bi = d_rowB[b*NS+i], Di = d_rowD[b*NS+i];
            float ld = logf(Di > 0.f ? Di : 1.f);
            num += Ai * 10.0f - ld * Bi;
            ps  += Bi;
        }
        red[t] = num; __syncthreads();
        for (int o = 128; o > 0; o >>= 1) { if (t < o) red[t] += red[t+o]; __syncthreads(); }
        if (t == 0) s_num = red[0];
        __syncthreads();
        red[t] = ps; __syncthreads();
        for (int o = 128; o > 0; o >>= 1) { if (t < o) red[t] += red[t+o]; __syncthreads(); }
        if (t == 0) s_ps = red[0];
        __syncthreads();
        if (t == 0) {
            if (s_ps > 0.f) {
                totLoss += -(0.1f/0.07f) * s_num / s_ps;
                nHas++;
            }
        }
        __syncthreads();
    }
    if (t == 0) out[0] = (nHas > 0) ? (totLoss / fmaxf((float)nHas, 1.f)) : 0.f;
}

extern "C" void kernel_launch(void* const* d_in, const int* in_sizes, int n_in,
                              void* d_out, int out_size) {
    const float*     feats  = (const float*)d_in[0];
    const long long* labels = (const long long*)d_in[1];
    const long long* sp     = (const long long*)d_in[2];
    const float*     w1     = (const float*)d_in[3];
    const float*     b1     = (const float*)d_in[4];
    const float*     w2     = (const float*)d_in[5];
    const float*     b2     = (const float*)d_in[6];
    const float*     wa1    = (const float*)d_in[7];
    const float*     ba1    = (const float*)d_in[8];
    const float*     wa2    = (const float*)d_in[9];
    const float*     ba2    = (const float*)d_in[10];
    float* out = (float*)d_out;

    static float* pG = nullptr; static float* pH = nullptr; static float* pP = nullptr;
    if (!pG) {
        cudaGetSymbolAddress((void**)&pG, d_G);
        cudaGetSymbolAddress((void**)&pH, d_H);
        cudaGetSymbolAddress((void**)&pP, d_P);
    }

    k_prep  <<<NB, 1024>>>(labels, sp);
    k_gather<<<dim3(NS/256, NC/16, NB), 256>>>(feats);
    k_g1a   <<<dim3(64, 6), 256>>>(w1, b1, wa1, ba1, wa2, ba2, pG, pH);
    k_gemm2 <<<dim3(64, 4), 256>>>(w2, b2, pH, pP);
    k_sim   <<<dim3(36, 1, NB), 256>>>();
    k_final <<<1, 256>>>(out);
}

// round 10
// speedup vs baseline: 1.3428x; 1.1058x over previous
#include <cuda_runtime.h>
#include <cuda_bf16.h>
#include <math.h>
#include <stdint.h>

#define NB 4
#define NC 256
#define HWP 25600
#define NS 1024
#define NT 4096   // NB*NS

typedef unsigned long long u64;

__device__ __forceinline__ u64 dup2(float v) {
    u64 r; asm("mov.b64 %0, {%1, %1};" : "=l"(r) : "f"(v)); return r;
}
__device__ __forceinline__ void fma2(u64& d, u64 a, u64 b) {
    asm("fma.rn.f32x2 %0, %1, %2, %0;" : "+l"(d) : "l"(a), "l"(b));
}
__device__ __forceinline__ float2 unpk(u64 v) {
    float2 f; asm("mov.b64 {%0, %1}, %2;" : "=f"(f.x), "=f"(f.y) : "l"(v)); return f;
}

// ---------- scratch ----------
__device__ float d_G[NC*NT];
__device__ float d_H[NC*NT];
__device__ float d_P[NC*NT];
__device__ __nv_bfloat16 d_Tbf[(size_t)NT*NC];   // normalized proj, [col][c], bf16
__device__ float d_attn[NT];
__device__ float d_ss[NT];
__device__ int   d_idx[NT];
__device__ int   d_sel[NT];
__device__ int   d_spv[NT];
__device__ int   d_vlist[NT];
__device__ int   d_ilist[NT];
__device__ float d_rowA[NT];
__device__ float d_rowB[NT];
__device__ float d_rowD[NT];

// ---------- fused selection ----------
__global__ void k_prep(const long long* __restrict__ labels, const long long* __restrict__ sp) {
    int b = blockIdx.x, t = threadIdx.x;          // 1024 threads
    const long long* lb = labels + (long long)b*HWP;
    int base = t*25;
    unsigned flags = 0; int cnt = 0;
    #pragma unroll
    for (int j = 0; j < 25; j++) {
        int f = (lb[base+j] == 1);
        flags |= (unsigned)f << j; cnt += f;
    }
    __shared__ int wsum[32];
    __shared__ int s_nv;
    int lane = t & 31, w = t >> 5;
    int incl = cnt;
    #pragma unroll
    for (int o = 1; o < 32; o <<= 1) {
        int n = __shfl_up_sync(0xffffffffu, incl, o);
        if (lane >= o) incl += n;
    }
    if (lane == 31) wsum[w] = incl;
    __syncthreads();
    if (t < 32) {
        int v = wsum[t]; int inc2 = v;
        #pragma unroll
        for (int o = 1; o < 32; o <<= 1) {
            int n = __shfl_up_sync(0xffffffffu, inc2, o);
            if (t >= o) inc2 += n;
        }
        wsum[t] = inc2 - v;
        if (t == 31) s_nv = inc2;
    }
    __syncthreads();
    int v_run = (incl - cnt) + wsum[w];
    #pragma unroll
    for (int j = 0; j < 25; j++) {
        int p = base + j;
        if ((flags >> j) & 1u) {
            if (v_run < NS) d_vlist[b*NS + v_run] = p;
            v_run++;
        } else {
            int ir = p - v_run;
            if (ir < NS) d_ilist[b*NS + ir] = p;
        }
    }
    __syncthreads();
    int nv = s_nv; if (nv > NS) nv = NS;
    int s = t;
    int p, se;
    if (s < nv) { p = d_vlist[b*NS + s];        se = 1; }
    else        { p = d_ilist[b*NS + (s - nv)]; se = 0; }
    int col = b*NS + s;
    d_idx[col] = p;
    d_sel[col] = se;
    d_spv[col] = (int)sp[(long long)b*HWP + p];
    d_rowA[col] = 0.f; d_rowB[col] = 0.f; d_rowD[col] = 0.f; d_ss[col] = 0.f;
}

// ---------- gather feats -> G[c][col] ----------
__global__ void k_gather(const float* __restrict__ feats) {
    int t = threadIdx.x;
    int s = blockIdx.x*256 + t;
    int b = blockIdx.z;
    int c0 = blockIdx.y*16;
    int col = b*NS + s;
    int p = d_idx[col];
    const float* fb = feats + ((long long)b*NC + c0)*HWP + p;
    float* g = d_G + (long long)c0*NT + col;
    #pragma unroll
    for (int cc = 0; cc < 16; cc++) {
        g[(long long)cc*NT] = __ldg(&fb[(long long)cc*HWP]);
    }
}

// ---------- 64x64 tile, 256 threads, 4x4/thread FFMA2, double-buffered ----------
template<bool RELU, bool NORM>
__device__ __forceinline__ void gemm_tile(const float* __restrict__ W, const float* __restrict__ bias,
                                          const float* __restrict__ X, float* __restrict__ Y,
                                          int m0, int n0) {
    __shared__ float As[2][16][68];   // [stage][k][m 0..63]
    __shared__ float Bs[2][16][68];   // [stage][k][col 0..63]
    __shared__ float s_ss[64];
    int t = threadIdx.x;
    int tx = t & 15, ty = t >> 4;     // cols tx*4, rows ty*4
    int am = t >> 2, ak = (t & 3) * 4;
    int bk = t >> 4, bc = (t & 15) * 4;
    if (NORM && t < 64) s_ss[t] = 0.f;

    float4 pa = *(const float4*)&W[(m0+am)*NC + ak];
    float4 pb = *(const float4*)&X[bk*NT + n0 + bc];
    As[0][ak+0][am]=pa.x; As[0][ak+1][am]=pa.y; As[0][ak+2][am]=pa.z; As[0][ak+3][am]=pa.w;
    *(float4*)&Bs[0][bk][bc] = pb;
    __syncthreads();

    u64 acc2[4][2] = {};
    for (int c = 0; c < 16; c++) {
        int cur = c & 1;
        if (c < 15) {
            int kk = (c+1)*16;
            pa = *(const float4*)&W[(m0+am)*NC + kk + ak];
            pb = *(const float4*)&X[(kk+bk)*NT + n0 + bc];
        }
        #pragma unroll
        for (int k = 0; k < 16; k++) {
            float4 a4 = *(float4*)&As[cur][k][ty*4];
            ulonglong2 bp = *(ulonglong2*)&Bs[cur][k][tx*4];
            u64 ad[4];
            ad[0] = dup2(a4.x); ad[1] = dup2(a4.y); ad[2] = dup2(a4.z); ad[3] = dup2(a4.w);
            #pragma unroll
            for (int r = 0; r < 4; r++) {
                fma2(acc2[r][0], ad[r], bp.x);
                fma2(acc2[r][1], ad[r], bp.y);
            }
        }
        if (c < 15) {
            int nxt = cur ^ 1;
            As[nxt][ak+0][am]=pa.x; As[nxt][ak+1][am]=pa.y; As[nxt][ak+2][am]=pa.z; As[nxt][ak+3][am]=pa.w;
            *(float4*)&Bs[nxt][bk][bc] = pb;
        }
        __syncthreads();
    }
    float ssq[4] = {};
    #pragma unroll
    for (int r = 0; r < 4; r++) {
        float bv = bias[m0 + ty*4 + r];
        float2 c01 = unpk(acc2[r][0]);
        float2 c23 = unpk(acc2[r][1]);
        float vv[4] = {c01.x + bv, c01.y + bv, c23.x + bv, c23.y + bv};
        #pragma unroll
        for (int q = 0; q < 4; q++) {
            if (RELU) vv[q] = fmaxf(vv[q], 0.f);
            if (NORM) ssq[q] = fmaf(vv[q], vv[q], ssq[q]);
        }
        *(float4*)&Y[(m0+ty*4+r)*NT + n0 + tx*4] = *(float4*)vv;
    }
    if (NORM) {
        #pragma unroll
        for (int q = 0; q < 4; q++) atomicAdd(&s_ss[tx*4+q], ssq[q]);
        __syncthreads();
        if (t < 64) atomicAdd(&d_ss[n0 + t], s_ss[t]);
    }
}

// ---------- attention tile: 32 cols, 256 threads ----------
__device__ __forceinline__ void attn_tile(const float* __restrict__ wa1, const float* __restrict__ ba1,
                                          const float* __restrict__ wa2, const float* __restrict__ ba2,
                                          const float* __restrict__ X, int n0) {
    __shared__ float Aa[16][68];     // [k][m], m 0..63
    __shared__ float Ba[16][36];     // [k][col], col 0..31
    __shared__ float stg[8][32];
    int t = threadIdx.x;
    int c = t & 31, g = t >> 5;      // col c, rows g*8..g*8+7
    int am = t >> 2, ak = (t & 3) * 4;
    int bk = t >> 4, bc = (t & 15) * 2;
    float4 pa = *(const float4*)&wa1[am*NC + ak];
    float2 pb = *(const float2*)&X[bk*NT + n0 + bc];
    float acc[8] = {};
    for (int kk = 0; kk < NC; kk += 16) {
        Aa[ak+0][am]=pa.x; Aa[ak+1][am]=pa.y; Aa[ak+2][am]=pa.z; Aa[ak+3][am]=pa.w;
        *(float2*)&Ba[bk][bc] = pb;
        __syncthreads();
        if (kk + 16 < NC) {
            pa = *(const float4*)&wa1[am*NC + kk+16 + ak];
            pb = *(const float2*)&X[(kk+16+bk)*NT + n0 + bc];
        }
        #pragma unroll
        for (int k = 0; k < 16; k++) {
            float bv = Ba[k][c];
            #pragma unroll
            for (int r = 0; r < 8; r++)
                acc[r] = fmaf(Aa[k][g*8+r], bv, acc[r]);
        }
        __syncthreads();
    }
    float part = 0.f;
    #pragma unroll
    for (int r = 0; r < 8; r++) {
        int m = g*8 + r;
        part = fmaf(wa2[m], fmaxf(acc[r] + ba1[m], 0.f), part);
    }
    stg[g][c] = part;
    __syncthreads();
    if (t < 32) {
        float sm = 0.f;
        #pragma unroll
        for (int gg = 0; gg < 8; gg++) sm += stg[gg][t];
        float z = sm + ba2[0];
        d_attn[n0 + t] = 1.f / (1.f + expf(-z));
    }
}

// ---------- gemm1 + attn ----------
__global__ __launch_bounds__(256) void k_g1a(const float* __restrict__ w1, const float* __restrict__ b1,
                      const float* __restrict__ wa1, const float* __restrict__ ba1,
                      const float* __restrict__ wa2, const float* __restrict__ ba2,
                      const float* __restrict__ X, float* __restrict__ Y) {
    int x = blockIdx.x, y = blockIdx.y;
    if (y < 4) {
        gemm_tile<true, false>(w1, b1, X, Y, y*64, x*64);
    } else {
        int a = (y - 4)*64 + x;   // 0..127
        attn_tile(wa1, ba1, wa2, ba2, X, a*32);
    }
}

__global__ __launch_bounds__(256) void k_gemm2(const float* __restrict__ w2, const float* __restrict__ b2,
                        const float* __restrict__ X, float* __restrict__ Y) {
    gemm_tile<false, true>(w2, b2, X, Y, blockIdx.y*64, blockIdx.x*64);
}

// ---------- transpose + normalize + bf16: Tbf[col][c] = bf16(P[c][col] * rnorm[col]) ----------
__global__ __launch_bounds__(256) void k_cvt() {
    __shared__ float tile[32][33];
    __shared__ float s_rn[32];
    int colT = blockIdx.x*32, cT = blockIdx.y*32;
    int t = threadIdx.x;
    if (t < 32) s_rn[t] = 1.f / fmaxf(sqrtf(d_ss[colT + t]), 1e-12f);
    int j = t & 31, ig = t >> 5;
    #pragma unroll
    for (int g = 0; g < 4; g++) {
        int i = ig*4 + g;
        tile[i][j] = d_P[(cT + i)*NT + colT + j];
    }
    __syncthreads();
    int i2 = t & 31, jg = t >> 5;
    #pragma unroll
    for (int g = 0; g < 4; g++) {
        int j3 = jg*4 + g;
        d_Tbf[(size_t)(colT + j3)*NC + cT + i2] = __float2bfloat16(tile[i2][j3] * s_rn[j3]);
    }
}

// ---------- tensor-core sim via bf16 mma.sync: 128x128x256 per (J,I,b) block ----------
// smem layout: rows of 32 halves padded to 40 (stride 80B -> conflict-free fragment LDS)
__global__ __launch_bounds__(256) void k_simt() {
    __shared__ __align__(16) __nv_bfloat16 sA[128*40];
    __shared__ __align__(16) __nv_bfloat16 sB[128*40];
    __shared__ int   spJ[128];
    __shared__ int   seJ[128];
    __shared__ float wJ[128];
    int t = threadIdx.x;
    int Jt = blockIdx.x, It = blockIdx.y, b = blockIdx.z;
    int i0 = It*128, j0 = Jt*128;
    if (t < 128) {
        int cj = b*NS + j0 + t;
        spJ[t] = d_spv[cj]; seJ[t] = d_sel[cj]; wJ[t] = d_attn[cj];
    }
    int w = t >> 5, lane = t & 31;
    int g = lane >> 2, tig = lane & 3;
    int wm = w >> 1, wn = w & 1;          // warp-tile: rows wm*32..+31, cols wn*64..+63
    const __nv_bfloat16* TA = d_Tbf + (size_t)(b*NS + i0)*NC;
    const __nv_bfloat16* TB = d_Tbf + (size_t)(b*NS + j0)*NC;
    int lrow = t >> 1, lpart = (t & 1)*16;

    float acc[2][8][4] = {};              // [mt][nt][c0..c3]
    for (int kc = 0; kc < 8; kc++) {
        int kk = kc*32;
        uint4 va0 = *(const uint4*)&TA[lrow*NC + kk + lpart];
        uint4 va1 = *(const uint4*)&TA[lrow*NC + kk + lpart + 8];
        uint4 vb0 = *(const uint4*)&TB[lrow*NC + kk + lpart];
        uint4 vb1 = *(const uint4*)&TB[lrow*NC + kk + lpart + 8];
        __syncthreads();
        *(uint4*)&sA[lrow*40 + lpart]     = va0;
        *(uint4*)&sA[lrow*40 + lpart + 8] = va1;
        *(uint4*)&sB[lrow*40 + lpart]     = vb0;
        *(uint4*)&sB[lrow*40 + lpart + 8] = vb1;
        __syncthreads();
        #pragma unroll
        for (int ks = 0; ks < 2; ks++) {
            int kb = ks*16;
            uint32_t a[2][4];
            #pragma unroll
            for (int mt = 0; mt < 2; mt++) {
                int rb = wm*32 + mt*16;
                a[mt][0] = *(const uint32_t*)&sA[(rb + g    )*40 + kb + tig*2];
                a[mt][1] = *(const uint32_t*)&sA[(rb + g + 8)*40 + kb + tig*2];
                a[mt][2] = *(const uint32_t*)&sA[(rb + g    )*40 + kb + tig*2 + 8];
                a[mt][3] = *(const uint32_t*)&sA[(rb + g + 8)*40 + kb + tig*2 + 8];
            }
            #pragma unroll
            for (int nt = 0; nt < 8; nt++) {
                int nb = wn*64 + nt*8;
                uint32_t b0 = *(const uint32_t*)&sB[(nb + g)*40 + kb + tig*2];
                uint32_t b1 = *(const uint32_t*)&sB[(nb + g)*40 + kb + tig*2 + 8];
                #pragma unroll
                for (int mt = 0; mt < 2; mt++) {
                    asm volatile(
                        "mma.sync.aligned.m16n8k16.row.col.f32.bf16.bf16.f32 "
                        "{%0,%1,%2,%3}, {%4,%5,%6,%7}, {%8,%9}, {%0,%1,%2,%3};"
                        : "+f"(acc[mt][nt][0]), "+f"(acc[mt][nt][1]),
                          "+f"(acc[mt][nt][2]), "+f"(acc[mt][nt][3])
                        : "r"(a[mt][0]), "r"(a[mt][1]), "r"(a[mt][2]), "r"(a[mt][3]),
                          "r"(b0), "r"(b1));
                }
            }
        }
    }

    // epilogue: row stats.  c0,c1 -> row g; c2,c3 -> row g+8; col = nt*8 + tig*2 + c
    #pragma unroll
    for (int mt = 0; mt < 2; mt++) {
        #pragma unroll
        for (int half = 0; half < 2; half++) {
            int il = wm*32 + mt*16 + half*8 + g;
            int ci = b*NS + i0 + il;
            int gi = i0 + il;
            int si = d_sel[ci], spi = d_spv[ci];
            float wi = d_attn[ci];
            float rA = 0.f, rB = 0.f, rD = 0.f;
            #pragma unroll
            for (int nt = 0; nt < 8; nt++) {
                #pragma unroll
                for (int c = 0; c < 2; c++) {
                    int jl = wn*64 + nt*8 + tig*2 + c;
                    float s = acc[mt][nt][half*2 + c];
                    if (seJ[jl]) {
                        rD += __expf(10.0f * s);      // 1/TEMP = 10
                        if (si && (gi != j0 + jl) && (spi == spJ[jl]) && (s > 0.7f)) {
                            float pw = wi * wJ[jl];
                            rB += pw; rA = fmaf(pw, s, rA);
                        }
                    }
                }
            }
            rA += __shfl_down_sync(0xffffffffu, rA, 2, 4);
            rA += __shfl_down_sync(0xffffffffu, rA, 1, 4);
            rB += __shfl_down_sync(0xffffffffu, rB, 2, 4);
            rB += __shfl_down_sync(0xffffffffu, rB, 1, 4);
            rD += __shfl_down_sync(0xffffffffu, rD, 2, 4);
            rD += __shfl_down_sync(0xffffffffu, rD, 1, 4);
            if (tig == 0) {
                atomicAdd(&d_rowA[ci], rA);
                atomicAdd(&d_rowB[ci], rB);
                atomicAdd(&d_rowD[ci], rD);
            }
        }
    }
}

// ---------- final reduction ----------
__global__ void k_final(float* __restrict__ out) {
    __shared__ float red[256];
    __shared__ float s_num, s_ps;
    int t = threadIdx.x;
    float totLoss = 0.f;
    int nHas = 0;
    for (int b = 0; b < NB; b++) {
        float num = 0.f, ps = 0.f;
        for (int i = t; i < NS; i += 256) {
            float Ai = d_rowA[b*NS+i], Bi = d_rowB[b*NS+i], Di = d_rowD[b*NS+i];
            float ld = logf(Di > 0.f ? Di : 1.f);
            num += Ai * 10.0f - ld * Bi;
            ps  += Bi;
        }
        red[t] = num; __syncthreads();
        for (int o = 128; o > 0; o >>= 1) { if (t < o) red[t] += red[t+o]; __syncthreads(); }
        if (t == 0) s_num = red[0];
        __syncthreads();
        red[t] = ps; __syncthreads();
        for (int o = 128; o > 0; o >>= 1) { if (t < o) red[t] += red[t+o]; __syncthreads(); }
        if (t == 0) s_ps = red[0];
        __syncthreads();
        if (t == 0) {
            if (s_ps > 0.f) {
                totLoss += -(0.1f/0.07f) * s_num / s_ps;
                nHas++;
            }
        }
        __syncthreads();
    }
    if (t == 0) out[0] = (nHas > 0) ? (totLoss / fmaxf((float)nHas, 1.f)) : 0.f;
}

extern "C" void kernel_launch(void* const* d_in, const int* in_sizes, int n_in,
                              void* d_out, int out_size) {
    const float*     feats  = (const float*)d_in[0];
    const long long* labels = (const long long*)d_in[1];
    const long long* sp     = (const long long*)d_in[2];
    const float*     w1     = (const float*)d_in[3];
    const float*     b1     = (const float*)d_in[4];
    const float*     w2     = (const float*)d_in[5];
    const float*     b2     = (const float*)d_in[6];
    const float*     wa1    = (const float*)d_in[7];
    const float*     ba1    = (const float*)d_in[8];
    const float*     wa2    = (const float*)d_in[9];
    const float*     ba2    = (const float*)d_in[10];
    float* out = (float*)d_out;

    static float* pG = nullptr; static float* pH = nullptr; static float* pP = nullptr;
    if (!pG) {
        cudaGetSymbolAddress((void**)&pG, d_G);
        cudaGetSymbolAddress((void**)&pH, d_H);
        cudaGetSymbolAddress((void**)&pP, d_P);
    }

    k_prep  <<<NB, 1024>>>(labels, sp);
    k_gather<<<dim3(NS/256, NC/16, NB), 256>>>(feats);
    k_g1a   <<<dim3(64, 6), 256>>>(w1, b1, wa1, ba1, wa2, ba2, pG, pH);
    k_gemm2 <<<dim3(64, 4), 256>>>(w2, b2, pH, pP);
    k_cvt   <<<dim3(NT/32, NC/32), 256>>>();
    k_simt  <<<dim3(8, 8, NB), 256>>>();
    k_final <<<1, 256>>>(out);
}

// round 11
// speedup vs baseline: 1.9302x; 1.4375x over previous
#include <cuda_runtime.h>
#include <cuda_bf16.h>
#include <math.h>
#include <stdint.h>

#define NB 4
#define NC 256
#define HWP 25600
#define NS 1024
#define NT 4096   // NB*NS

typedef unsigned long long u64;
typedef __nv_bfloat16 bf16;

// ---------- scratch ----------
__device__ bf16  d_Gbf[(size_t)NT*NC];   // gathered feats, [col][c] bf16
__device__ bf16  d_Hbf[(size_t)NT*NC];   // hidden,         [col][m] bf16
__device__ bf16  d_Ptbf[(size_t)NT*NC];  // proj (unnorm),  [col][m] bf16
__device__ bf16  d_Tbf[(size_t)NT*NC];   // proj normalized [col][c] bf16
__device__ bf16  d_w1bf[NC*NC];
__device__ bf16  d_w2bf[NC*NC];
__device__ bf16  d_wa1bf[64*NC];
__device__ float d_attn[NT];
__device__ int   d_idx[NT];
__device__ int   d_sel[NT];
__device__ int   d_spv[NT];
__device__ int   d_vlist[NT];
__device__ int   d_ilist[NT];
__device__ float d_rowA[NT];
__device__ float d_rowB[NT];
__device__ float d_rowD[NT];

// ---------- fused selection ----------
__global__ void k_prep(const long long* __restrict__ labels, const long long* __restrict__ sp) {
    int b = blockIdx.x, t = threadIdx.x;          // 1024 threads
    const long long* lb = labels + (long long)b*HWP;
    int base = t*25;
    unsigned flags = 0; int cnt = 0;
    #pragma unroll
    for (int j = 0; j < 25; j++) {
        int f = (lb[base+j] == 1);
        flags |= (unsigned)f << j; cnt += f;
    }
    __shared__ int wsum[32];
    __shared__ int s_nv;
    int lane = t & 31, w = t >> 5;
    int incl = cnt;
    #pragma unroll
    for (int o = 1; o < 32; o <<= 1) {
        int n = __shfl_up_sync(0xffffffffu, incl, o);
        if (lane >= o) incl += n;
    }
    if (lane == 31) wsum[w] = incl;
    __syncthreads();
    if (t < 32) {
        int v = wsum[t]; int inc2 = v;
        #pragma unroll
        for (int o = 1; o < 32; o <<= 1) {
            int n = __shfl_up_sync(0xffffffffu, inc2, o);
            if (t >= o) inc2 += n;
        }
        wsum[t] = inc2 - v;
        if (t == 31) s_nv = inc2;
    }
    __syncthreads();
    int v_run = (incl - cnt) + wsum[w];
    #pragma unroll
    for (int j = 0; j < 25; j++) {
        int p = base + j;
        if ((flags >> j) & 1u) {
            if (v_run < NS) d_vlist[b*NS + v_run] = p;
            v_run++;
        } else {
            int ir = p - v_run;
            if (ir < NS) d_ilist[b*NS + ir] = p;
        }
    }
    __syncthreads();
    int nv = s_nv; if (nv > NS) nv = NS;
    int s = t;
    int p, se;
    if (s < nv) { p = d_vlist[b*NS + s];        se = 1; }
    else        { p = d_ilist[b*NS + (s - nv)]; se = 0; }
    int col = b*NS + s;
    d_idx[col] = p;
    d_sel[col] = se;
    d_spv[col] = (int)sp[(long long)b*HWP + p];
    d_rowA[col] = 0.f; d_rowB[col] = 0.f; d_rowD[col] = 0.f;
}

// ---------- gather feats -> Gbf[col][c] bf16 ----------
__global__ void k_gather(const float* __restrict__ feats) {
    int t = threadIdx.x;
    int s = blockIdx.x*256 + t;
    int b = blockIdx.z;
    int c0 = blockIdx.y*16;
    int col = b*NS + s;
    int p = d_idx[col];
    const float* fb = feats + ((long long)b*NC + c0)*HWP + p;
    uint32_t pk[8];
    #pragma unroll
    for (int cc = 0; cc < 8; cc++) {
        float v0 = __ldg(&fb[(long long)(2*cc  )*HWP]);
        float v1 = __ldg(&fb[(long long)(2*cc+1)*HWP]);
        __nv_bfloat162 pr = __floats2bfloat162_rn(v0, v1);
        pk[cc] = *(uint32_t*)&pr;
    }
    uint4* dst = (uint4*)&d_Gbf[(size_t)col*NC + c0];
    dst[0] = make_uint4(pk[0], pk[1], pk[2], pk[3]);
    dst[1] = make_uint4(pk[4], pk[5], pk[6], pk[7]);
}

// ---------- convert weights to bf16 ----------
__global__ void k_wcvt(const float* __restrict__ w1, const float* __restrict__ w2,
                       const float* __restrict__ wa1) {
    int i = (blockIdx.x*256 + threadIdx.x)*4;
    const float* src; bf16* dst; int off;
    if (i < 65536)        { src = w1;  dst = d_w1bf;  off = i; }
    else if (i < 131072)  { src = w2;  dst = d_w2bf;  off = i - 65536; }
    else                  { src = wa1; dst = d_wa1bf; off = i - 131072; }
    float4 v = *(const float4*)&src[off];
    __nv_bfloat162 lo = __floats2bfloat162_rn(v.x, v.y);
    __nv_bfloat162 hi = __floats2bfloat162_rn(v.z, v.w);
    *(uint2*)&dst[off] = make_uint2(*(uint32_t*)&lo, *(uint32_t*)&hi);
}

// ---------- shared mma mainloop: 64x64 tile, K=256, warp grid 2x4 ----------
// A [m][k] bf16 row-major; X [col][k] bf16 (B operand, k-contiguous). acc[mt][nt][4].
__device__ __forceinline__ void mma_mainloop(const bf16* __restrict__ A,
                                             const bf16* __restrict__ X,
                                             bf16* sA, bf16* sB,
                                             int m0, int n0, float acc[2][2][4]) {
    int t = threadIdx.x;
    int w = t >> 5, lane = t & 31;
    int g = lane >> 2, tig = lane & 3;
    int wm = w >> 2, wn = w & 3;
    int frow = t >> 2, fchk = (t & 3)*8;
    for (int kc = 0; kc < 8; kc++) {
        int kk = kc*32;
        uint4 va = *(const uint4*)&A[(size_t)(m0+frow)*NC + kk + fchk];
        uint4 vb = *(const uint4*)&X[(size_t)(n0+frow)*NC + kk + fchk];
        __syncthreads();
        *(uint4*)&sA[frow*40 + fchk] = va;
        *(uint4*)&sB[frow*40 + fchk] = vb;
        __syncthreads();
        #pragma unroll
        for (int ks = 0; ks < 2; ks++) {
            int kb = ks*16;
            uint32_t a[2][4], bb[2][2];
            #pragma unroll
            for (int mt = 0; mt < 2; mt++) {
                int rb = wm*32 + mt*16;
                a[mt][0] = *(const uint32_t*)&sA[(rb + g    )*40 + kb + tig*2];
                a[mt][1] = *(const uint32_t*)&sA[(rb + g + 8)*40 + kb + tig*2];
                a[mt][2] = *(const uint32_t*)&sA[(rb + g    )*40 + kb + tig*2 + 8];
                a[mt][3] = *(const uint32_t*)&sA[(rb + g + 8)*40 + kb + tig*2 + 8];
            }
            #pragma unroll
            for (int nt = 0; nt < 2; nt++) {
                int nb = wn*16 + nt*8;
                bb[nt][0] = *(const uint32_t*)&sB[(nb + g)*40 + kb + tig*2];
                bb[nt][1] = *(const uint32_t*)&sB[(nb + g)*40 + kb + tig*2 + 8];
            }
            #pragma unroll
            for (int mt = 0; mt < 2; mt++)
                #pragma unroll
                for (int nt = 0; nt < 2; nt++)
                    asm volatile(
                        "mma.sync.aligned.m16n8k16.row.col.f32.bf16.bf16.f32 "
                        "{%0,%1,%2,%3}, {%4,%5,%6,%7}, {%8,%9}, {%0,%1,%2,%3};"
                        : "+f"(acc[mt][nt][0]), "+f"(acc[mt][nt][1]),
                          "+f"(acc[mt][nt][2]), "+f"(acc[mt][nt][3])
                        : "r"(a[mt][0]), "r"(a[mt][1]), "r"(a[mt][2]), "r"(a[mt][3]),
                          "r"(bb[nt][0]), "r"(bb[nt][1]));
        }
    }
}

// ---------- transposed bf16 store epilogue: Y[col][m] = act(acc + bias[m]) ----------
template<bool RELU>
__device__ __forceinline__ void store_T(float acc[2][2][4], const float* __restrict__ bias,
                                        bf16* sT /*64 cols x 72*/, bf16* __restrict__ Y,
                                        int m0, int n0) {
    int t = threadIdx.x;
    int w = t >> 5, lane = t & 31;
    int g = lane >> 2, tig = lane & 3;
    int wm = w >> 2, wn = w & 3;
    __syncthreads();   // done with sA/sB (aliased)
    #pragma unroll
    for (int mt = 0; mt < 2; mt++) {
        #pragma unroll
        for (int half = 0; half < 2; half++) {
            int r = wm*32 + mt*16 + half*8 + g;
            float bv = bias[m0 + r];
            #pragma unroll
            for (int nt = 0; nt < 2; nt++) {
                #pragma unroll
                for (int c = 0; c < 2; c++) {
                    int cl = wn*16 + nt*8 + tig*2 + c;
                    float v = acc[mt][nt][half*2 + c] + bv;
                    if (RELU) v = fmaxf(v, 0.f);
                    sT[cl*72 + r] = __float2bfloat16(v);
                }
            }
        }
    }
    __syncthreads();
    #pragma unroll
    for (int i = 0; i < 2; i++) {
        int e = t*2 + i;
        int row = e >> 3, chk = (e & 7)*8;
        *(uint4*)&Y[(size_t)(n0+row)*NC + m0 + chk] = *(uint4*)&sT[row*72 + chk];
    }
}

// ---------- gemm1 (tensor) + attn (tensor) in one launch ----------
__global__ __launch_bounds__(256) void k_mma1(const float* __restrict__ b1,
                      const float* __restrict__ ba1, const float* __restrict__ wa2,
                      const float* __restrict__ ba2) {
    __shared__ __align__(16) char buf[10240];   // sA 5120 | sB 5120 ; sT aliases (9216)
    __shared__ float sRed[2][64];
    bf16* sA = (bf16*)buf;
    bf16* sB = (bf16*)(buf + 5120);
    bf16* sT = (bf16*)buf;
    int x = blockIdx.x, y = blockIdx.y;
    int n0 = x*64;
    float acc[2][2][4] = {};
    if (y < 4) {
        int m0 = y*64;
        mma_mainloop(d_w1bf, d_Gbf, sA, sB, m0, n0, acc);
        store_T<true>(acc, b1, sT, d_Hbf, m0, n0);
    } else {
        mma_mainloop(d_wa1bf, d_Gbf, sA, sB, 0, n0, acc);
        int t = threadIdx.x;
        int w = t >> 5, lane = t & 31;
        int g = lane >> 2, tig = lane & 3;
        int wm = w >> 2, wn = w & 3;
        float part[2][2] = {};
        #pragma unroll
        for (int mt = 0; mt < 2; mt++) {
            #pragma unroll
            for (int half = 0; half < 2; half++) {
                int r = wm*32 + mt*16 + half*8 + g;
                float bm = ba1[r], wmv = wa2[r];
                #pragma unroll
                for (int nt = 0; nt < 2; nt++)
                    #pragma unroll
                    for (int c = 0; c < 2; c++)
                        part[nt][c] = fmaf(wmv, fmaxf(acc[mt][nt][half*2+c] + bm, 0.f), part[nt][c]);
            }
        }
        #pragma unroll
        for (int nt = 0; nt < 2; nt++)
            #pragma unroll
            for (int c = 0; c < 2; c++) {
                part[nt][c] += __shfl_down_sync(0xffffffffu, part[nt][c], 16);
                part[nt][c] += __shfl_down_sync(0xffffffffu, part[nt][c], 8);
                part[nt][c] += __shfl_down_sync(0xffffffffu, part[nt][c], 4);
            }
        if (g == 0) {
            #pragma unroll
            for (int nt = 0; nt < 2; nt++)
                #pragma unroll
                for (int c = 0; c < 2; c++)
                    sRed[wm][wn*16 + nt*8 + tig*2 + c] = part[nt][c];
        }
        __syncthreads();
        if (t < 64) {
            float z = sRed[0][t] + sRed[1][t] + ba2[0];
            d_attn[n0 + t] = 1.f / (1.f + expf(-z));
        }
    }
}

// ---------- gemm2 (tensor): Ptbf[col][m] = W2 . Hbf + b2 ----------
__global__ __launch_bounds__(256) void k_mma2(const float* __restrict__ b2) {
    __shared__ __align__(16) char buf[10240];
    bf16* sA = (bf16*)buf;
    bf16* sB = (bf16*)(buf + 5120);
    bf16* sT = (bf16*)buf;
    int m0 = blockIdx.y*64, n0 = blockIdx.x*64;
    float acc[2][2][4] = {};
    mma_mainloop(d_w2bf, d_Hbf, sA, sB, m0, n0, acc);
    store_T<false>(acc, b2, sT, d_Ptbf, m0, n0);
}

// ---------- normalize: Tbf[col][c] = bf16(Pt[col][c] / max(||Pt[col]||,1e-12)), warp per col ----------
__global__ __launch_bounds__(256) void k_scale() {
    int w = threadIdx.x >> 5, lane = threadIdx.x & 31;
    int col = blockIdx.x*8 + w;
    const uint4* src = (const uint4*)&d_Ptbf[(size_t)col*NC];
    uint4 v = src[lane];
    bf16* h = (bf16*)&v;
    float f[8]; float ss = 0.f;
    #pragma unroll
    for (int i = 0; i < 8; i++) { f[i] = __bfloat162float(h[i]); ss = fmaf(f[i], f[i], ss); }
    #pragma unroll
    for (int o = 16; o >= 1; o >>= 1) ss += __shfl_xor_sync(0xffffffffu, ss, o);
    float rn = 1.f / fmaxf(sqrtf(ss), 1e-12f);
    uint4 ov;
    bf16* oh = (bf16*)&ov;
    #pragma unroll
    for (int i = 0; i < 8; i++) oh[i] = __float2bfloat16(f[i] * rn);
    ((uint4*)&d_Tbf[(size_t)col*NC])[lane] = ov;
}

// ---------- tensor-core sim (validated round-10 kernel) ----------
__global__ __launch_bounds__(256) void k_simt() {
    __shared__ __align__(16) bf16 sA[128*40];
    __shared__ __align__(16) bf16 sB[128*40];
    __shared__ int   spJ[128];
    __shared__ int   seJ[128];
    __shared__ float wJ[128];
    int t = threadIdx.x;
    int Jt = blockIdx.x, It = blockIdx.y, b = blockIdx.z;
    int i0 = It*128, j0 = Jt*128;
    if (t < 128) {
        int cj = b*NS + j0 + t;
        spJ[t] = d_spv[cj]; seJ[t] = d_sel[cj]; wJ[t] = d_attn[cj];
    }
    int w = t >> 5, lane = t & 31;
    int g = lane >> 2, tig = lane & 3;
    int wm = w >> 1, wn = w & 1;
    const bf16* TA = d_Tbf + (size_t)(b*NS + i0)*NC;
    const bf16* TB = d_Tbf + (size_t)(b*NS + j0)*NC;
    int lrow = t >> 1, lpart = (t & 1)*16;

    float acc[2][8][4] = {};
    for (int kc = 0; kc < 8; kc++) {
        int kk = kc*32;
        uint4 va0 = *(const uint4*)&TA[lrow*NC + kk + lpart];
        uint4 va1 = *(const uint4*)&TA[lrow*NC + kk + lpart + 8];
        uint4 vb0 = *(const uint4*)&TB[lrow*NC + kk + lpart];
        uint4 vb1 = *(const uint4*)&TB[lrow*NC + kk + lpart + 8];
        __syncthreads();
        *(uint4*)&sA[lrow*40 + lpart]     = va0;
        *(uint4*)&sA[lrow*40 + lpart + 8] = va1;
        *(uint4*)&sB[lrow*40 + lpart]     = vb0;
        *(uint4*)&sB[lrow*40 + lpart + 8] = vb1;
        __syncthreads();
        #pragma unroll
        for (int ks = 0; ks < 2; ks++) {
            int kb = ks*16;
            uint32_t a[2][4];
            #pragma unroll
            for (int mt = 0; mt < 2; mt++) {
                int rb = wm*32 + mt*16;
                a[mt][0] = *(const uint32_t*)&sA[(rb + g    )*40 + kb + tig*2];
                a[mt][1] = *(const uint32_t*)&sA[(rb + g + 8)*40 + kb + tig*2];
                a[mt][2] = *(const uint32_t*)&sA[(rb + g    )*40 + kb + tig*2 + 8];
                a[mt][3] = *(const uint32_t*)&sA[(rb + g + 8)*40 + kb + tig*2 + 8];
            }
            #pragma unroll
            for (int nt = 0; nt < 8; nt++) {
                int nb = wn*64 + nt*8;
                uint32_t b0 = *(const uint32_t*)&sB[(nb + g)*40 + kb + tig*2];
                uint32_t b1 = *(const uint32_t*)&sB[(nb + g)*40 + kb + tig*2 + 8];
                #pragma unroll
                for (int mt = 0; mt < 2; mt++) {
                    asm volatile(
                        "mma.sync.aligned.m16n8k16.row.col.f32.bf16.bf16.f32 "
                        "{%0,%1,%2,%3}, {%4,%5,%6,%7}, {%8,%9}, {%0,%1,%2,%3};"
                        : "+f"(acc[mt][nt][0]), "+f"(acc[mt][nt][1]),
                          "+f"(acc[mt][nt][2]), "+f"(acc[mt][nt][3])
                        : "r"(a[mt][0]), "r"(a[mt][1]), "r"(a[mt][2]), "r"(a[mt][3]),
                          "r"(b0), "r"(b1));
                }
            }
        }
    }
    #pragma unroll
    for (int mt = 0; mt < 2; mt++) {
        #pragma unroll
        for (int half = 0; half < 2; half++) {
            int il = wm*32 + mt*16 + half*8 + g;
            int ci = b*NS + i0 + il;
            int gi = i0 + il;
            int si = d_sel[ci], spi = d_spv[ci];
            float wi = d_attn[ci];
            float rA = 0.f, rB = 0.f, rD = 0.f;
            #pragma unroll
            for (int nt = 0; nt < 8; nt++) {
                #pragma unroll
                for (int c = 0; c < 2; c++) {
                    int jl = wn*64 + nt*8 + tig*2 + c;
                    float s = acc[mt][nt][half*2 + c];
                    if (seJ[jl]) {
                        rD += __expf(10.0f * s);      // 1/TEMP = 10
                        if (si && (gi != j0 + jl) && (spi == spJ[jl]) && (s > 0.7f)) {
                            float pw = wi * wJ[jl];
                            rB += pw; rA = fmaf(pw, s, rA);
                        }
                    }
                }
            }
            rA += __shfl_down_sync(0xffffffffu, rA, 2, 4);
            rA += __shfl_down_sync(0xffffffffu, rA, 1, 4);
            rB += __shfl_down_sync(0xffffffffu, rB, 2, 4);
            rB += __shfl_down_sync(0xffffffffu, rB, 1, 4);
            rD += __shfl_down_sync(0xffffffffu, rD, 2, 4);
            rD += __shfl_down_sync(0xffffffffu, rD, 1, 4);
            if (tig == 0) {
                atomicAdd(&d_rowA[ci], rA);
                atomicAdd(&d_rowB[ci], rB);
                atomicAdd(&d_rowD[ci], rD);
            }
        }
    }
}

// ---------- final reduction ----------
__global__ void k_final(float* __restrict__ out) {
    __shared__ float red[256];
    __shared__ float s_num, s_ps;
    int t = threadIdx.x;
    float totLoss = 0.f;
    int nHas = 0;
    for (int b = 0; b < NB; b++) {
        float num = 0.f, ps = 0.f;
        for (int i = t; i < NS; i += 256) {
            float Ai = d_rowA[b*NS+i], Bi = d_rowB[b*NS+i], Di = d_rowD[b*NS+i];
            float ld = logf(Di > 0.f ? Di : 1.f);
            num += Ai * 10.0f - ld * Bi;
            ps  += Bi;
        }
        red[t] = num; __syncthreads();
        for (int o = 128; o > 0; o >>= 1) { if (t < o) red[t] += red[t+o]; __syncthreads(); }
        if (t == 0) s_num = red[0];
        __syncthreads();
        red[t] = ps; __syncthreads();
        for (int o = 128; o > 0; o >>= 1) { if (t < o) red[t] += red[t+o]; __syncthreads(); }
        if (t == 0) s_ps = red[0];
        __syncthreads();
        if (t == 0) {
            if (s_ps > 0.f) {
                totLoss += -(0.1f/0.07f) * s_num / s_ps;
                nHas++;
            }
        }
        __syncthreads();
    }
    if (t == 0) out[0] = (nHas > 0) ? (totLoss / fmaxf((float)nHas, 1.f)) : 0.f;
}

extern "C" void kernel_launch(void* const* d_in, const int* in_sizes, int n_in,
                              void* d_out, int out_size) {
    const float*     feats  = (const float*)d_in[0];
    const long long* labels = (const long long*)d_in[1];
    const long long* sp     = (const long long*)d_in[2];
    const float*     w1     = (const float*)d_in[3];
    const float*     b1     = (const float*)d_in[4];
    const float*     w2     = (const float*)d_in[5];
    const float*     b2     = (const float*)d_in[6];
    const float*     wa1    = (const float*)d_in[7];
    const float*     ba1    = (const float*)d_in[8];
    const float*     wa2    = (const float*)d_in[9];
    const float*     ba2    = (const float*)d_in[10];
    float* out = (float*)d_out;

    k_prep  <<<NB, 1024>>>(labels, sp);
    k_gather<<<dim3(NS/256, NC/16, NB), 256>>>(feats);
    k_wcvt  <<<144, 256>>>(w1, w2, wa1);
    k_mma1  <<<dim3(64, 5), 256>>>(b1, ba1, wa2, ba2);
    k_mma2  <<<dim3(64, 4), 256>>>(b2);
    k_scale <<<NT/8, 256>>>();
    k_simt  <<<dim3(8, 8, NB), 256>>>();
    k_final <<<1, 256>>>(out);
}

// round 12
// speedup vs baseline: 2.1282x; 1.1026x over previous
#include <cuda_runtime.h>
#include <cuda_bf16.h>
#include <math.h>
#include <stdint.h>

#define NB 4
#define NC 256
#define HWP 25600
#define NS 1024
#define NT 4096   // NB*NS

typedef __nv_bfloat16 bf16;

__device__ __forceinline__ void cp16(void* sdst, const void* gsrc) {
    uint32_t s = (uint32_t)__cvta_generic_to_shared(sdst);
    asm volatile("cp.async.cg.shared.global [%0], [%1], 16;" :: "r"(s), "l"(gsrc));
}
#define CP_COMMIT() asm volatile("cp.async.commit_group;")
#define CP_WAIT0()  asm volatile("cp.async.wait_group 0;")

// ---------- scratch ----------
__device__ __align__(16) bf16  d_Gbf[(size_t)NT*NC];   // gathered feats, [col][c]
__device__ __align__(16) bf16  d_Hbf[(size_t)NT*NC];   // hidden,         [col][m]
__device__ __align__(16) bf16  d_Ptbf[(size_t)NT*NC];  // proj (unnorm),  [col][m]
__device__ __align__(16) bf16  d_w1bf[NC*NC];
__device__ __align__(16) bf16  d_w2bf[NC*NC];
__device__ __align__(16) bf16  d_wa1bf[64*NC];
__device__ float d_attn[NT];
__device__ float d_ss[NT];
__device__ int   d_idx[NT];
__device__ int   d_sel[NT];
__device__ int   d_spv[NT];
__device__ int   d_vlist[NT];
__device__ int   d_ilist[NT];
__device__ float d_rowA[NT];
__device__ float d_rowB[NT];
__device__ float d_rowD[NT];

// ---------- fused selection (blocks 0-3) + weight bf16 convert (blocks 4-39) ----------
__global__ void k_prep(const long long* __restrict__ labels, const long long* __restrict__ sp,
                       const float* __restrict__ w1, const float* __restrict__ w2,
                       const float* __restrict__ wa1) {
    int blk = blockIdx.x, t = threadIdx.x;   // 1024 threads
    if (blk >= NB) {
        // weight convert: 36 blocks x 1024 threads x 4 floats = 147456 = 64K+64K+16K
        int i = ((blk - NB)*1024 + t)*4;
        const float* src; bf16* dst; int off;
        if (i < 65536)        { src = w1;  dst = d_w1bf;  off = i; }
        else if (i < 131072)  { src = w2;  dst = d_w2bf;  off = i - 65536; }
        else                  { src = wa1; dst = d_wa1bf; off = i - 131072; }
        float4 v = *(const float4*)&src[off];
        __nv_bfloat162 lo = __floats2bfloat162_rn(v.x, v.y);
        __nv_bfloat162 hi = __floats2bfloat162_rn(v.z, v.w);
        *(uint2*)&dst[off] = make_uint2(*(uint32_t*)&lo, *(uint32_t*)&hi);
        return;
    }
    int b = blk;
    const long long* lb = labels + (long long)b*HWP;
    int base = t*25;
    unsigned flags = 0; int cnt = 0;
    #pragma unroll
    for (int j = 0; j < 25; j++) {
        int f = (lb[base+j] == 1);
        flags |= (unsigned)f << j; cnt += f;
    }
    __shared__ int wsum[32];
    __shared__ int s_nv;
    int lane = t & 31, w = t >> 5;
    int incl = cnt;
    #pragma unroll
    for (int o = 1; o < 32; o <<= 1) {
        int n = __shfl_up_sync(0xffffffffu, incl, o);
        if (lane >= o) incl += n;
    }
    if (lane == 31) wsum[w] = incl;
    __syncthreads();
    if (t < 32) {
        int v = wsum[t]; int inc2 = v;
        #pragma unroll
        for (int o = 1; o < 32; o <<= 1) {
            int n = __shfl_up_sync(0xffffffffu, inc2, o);
            if (t >= o) inc2 += n;
        }
        wsum[t] = inc2 - v;
        if (t == 31) s_nv = inc2;
    }
    __syncthreads();
    int v_run = (incl - cnt) + wsum[w];
    #pragma unroll
    for (int j = 0; j < 25; j++) {
        int p = base + j;
        if ((flags >> j) & 1u) {
            if (v_run < NS) d_vlist[b*NS + v_run] = p;
            v_run++;
        } else {
            int ir = p - v_run;
            if (ir < NS) d_ilist[b*NS + ir] = p;
        }
    }
    __syncthreads();
    int nv = s_nv; if (nv > NS) nv = NS;
    int s = t;
    int p, se;
    if (s < nv) { p = d_vlist[b*NS + s];        se = 1; }
    else        { p = d_ilist[b*NS + (s - nv)]; se = 0; }
    int col = b*NS + s;
    d_idx[col] = p;
    d_sel[col] = se;
    d_spv[col] = (int)sp[(long long)b*HWP + p];
    d_rowA[col] = 0.f; d_rowB[col] = 0.f; d_rowD[col] = 0.f; d_ss[col] = 0.f;
}

// ---------- gather feats -> Gbf[col][c] bf16 ----------
__global__ void k_gather(const float* __restrict__ feats) {
    int t = threadIdx.x;
    int s = blockIdx.x*256 + t;
    int b = blockIdx.z;
    int c0 = blockIdx.y*16;
    int col = b*NS + s;
    int p = d_idx[col];
    const float* fb = feats + ((long long)b*NC + c0)*HWP + p;
    uint32_t pk[8];
    #pragma unroll
    for (int cc = 0; cc < 8; cc++) {
        float v0 = __ldg(&fb[(long long)(2*cc  )*HWP]);
        float v1 = __ldg(&fb[(long long)(2*cc+1)*HWP]);
        __nv_bfloat162 pr = __floats2bfloat162_rn(v0, v1);
        pk[cc] = *(uint32_t*)&pr;
    }
    uint4* dst = (uint4*)&d_Gbf[(size_t)col*NC + c0];
    dst[0] = make_uint4(pk[0], pk[1], pk[2], pk[3]);
    dst[1] = make_uint4(pk[4], pk[5], pk[6], pk[7]);
}

// ---------- mma mainloop: 64x64 tile, K=256, warp grid 2x4, cp.async double-buffered ----------
// A [m][k] bf16 row-major; X [col][k] bf16. sA/sB each hold 2 stages of 64x40 halves.
__device__ __forceinline__ void mma_mainloop(const bf16* __restrict__ A,
                                             const bf16* __restrict__ X,
                                             bf16* sA, bf16* sB,
                                             int m0, int n0, float acc[2][2][4]) {
    int t = threadIdx.x;
    int w = t >> 5, lane = t & 31;
    int g = lane >> 2, tig = lane & 3;
    int wm = w >> 2, wn = w & 3;
    int frow = t >> 2, fchk = (t & 3)*8;
    const bf16* gA = &A[(size_t)(m0+frow)*NC + fchk];
    const bf16* gB = &X[(size_t)(n0+frow)*NC + fchk];
    cp16(&sA[frow*40 + fchk], gA);
    cp16(&sB[frow*40 + fchk], gB);
    CP_COMMIT();
    CP_WAIT0();
    __syncthreads();
    for (int kc = 0; kc < 8; kc++) {
        int cur = kc & 1;
        bf16* cA = sA + cur*2560;
        bf16* cB = sB + cur*2560;
        if (kc < 7) {
            int nxt = cur ^ 1;
            cp16(&sA[nxt*2560 + frow*40 + fchk], gA + (kc+1)*32);
            cp16(&sB[nxt*2560 + frow*40 + fchk], gB + (kc+1)*32);
            CP_COMMIT();
        }
        #pragma unroll
        for (int ks = 0; ks < 2; ks++) {
            int kb = ks*16;
            uint32_t a[2][4], bb[2][2];
            #pragma unroll
            for (int mt = 0; mt < 2; mt++) {
                int rb = wm*32 + mt*16;
                a[mt][0] = *(const uint32_t*)&cA[(rb + g    )*40 + kb + tig*2];
                a[mt][1] = *(const uint32_t*)&cA[(rb + g + 8)*40 + kb + tig*2];
                a[mt][2] = *(const uint32_t*)&cA[(rb + g    )*40 + kb + tig*2 + 8];
                a[mt][3] = *(const uint32_t*)&cA[(rb + g + 8)*40 + kb + tig*2 + 8];
            }
            #pragma unroll
            for (int nt = 0; nt < 2; nt++) {
                int nb = wn*16 + nt*8;
                bb[nt][0] = *(const uint32_t*)&cB[(nb + g)*40 + kb + tig*2];
                bb[nt][1] = *(const uint32_t*)&cB[(nb + g)*40 + kb + tig*2 + 8];
            }
            #pragma unroll
            for (int mt = 0; mt < 2; mt++)
                #pragma unroll
                for (int nt = 0; nt < 2; nt++)
                    asm volatile(
                        "mma.sync.aligned.m16n8k16.row.col.f32.bf16.bf16.f32 "
                        "{%0,%1,%2,%3}, {%4,%5,%6,%7}, {%8,%9}, {%0,%1,%2,%3};"
                        : "+f"(acc[mt][nt][0]), "+f"(acc[mt][nt][1]),
                          "+f"(acc[mt][nt][2]), "+f"(acc[mt][nt][3])
                        : "r"(a[mt][0]), "r"(a[mt][1]), "r"(a[mt][2]), "r"(a[mt][3]),
                          "r"(bb[nt][0]), "r"(bb[nt][1]));
        }
        if (kc < 7) { CP_WAIT0(); __syncthreads(); }
    }
}

// ---------- transposed bf16 store epilogue: Y[col][m] = act(acc + bias[m]); optional col-sumsq ----------
template<bool RELU, bool SS>
__device__ __forceinline__ void store_T(float acc[2][2][4], const float* __restrict__ bias,
                                        bf16* sT /*64 x 72*/, float* s_ss,
                                        bf16* __restrict__ Y, int m0, int n0) {
    int t = threadIdx.x;
    int w = t >> 5, lane = t & 31;
    int g = lane >> 2, tig = lane & 3;
    int wm = w >> 2, wn = w & 3;
    if (SS && t < 64) s_ss[t] = 0.f;
    __syncthreads();   // done with sA/sB (aliased)
    #pragma unroll
    for (int mt = 0; mt < 2; mt++) {
        #pragma unroll
        for (int half = 0; half < 2; half++) {
            int r = wm*32 + mt*16 + half*8 + g;
            float bv = bias[m0 + r];
            #pragma unroll
            for (int nt = 0; nt < 2; nt++) {
                #pragma unroll
                for (int c = 0; c < 2; c++) {
                    int cl = wn*16 + nt*8 + tig*2 + c;
                    float v = acc[mt][nt][half*2 + c] + bv;
                    if (RELU) v = fmaxf(v, 0.f);
                    sT[cl*72 + r] = __float2bfloat16(v);
                }
            }
        }
    }
    __syncthreads();
    #pragma unroll
    for (int i = 0; i < 2; i++) {
        int e = t*2 + i;
        int row = e >> 3, chk = (e & 7)*8;
        uint4 v = *(uint4*)&sT[row*72 + chk];
        *(uint4*)&Y[(size_t)(n0+row)*NC + m0 + chk] = v;
        if (SS) {
            bf16* h = (bf16*)&v;
            float p = 0.f;
            #pragma unroll
            for (int q = 0; q < 8; q++) {
                float f = __bfloat162float(h[q]);
                p = fmaf(f, f, p);
            }
            atomicAdd(&s_ss[row], p);
        }
    }
    if (SS) {
        __syncthreads();
        if (t < 64) atomicAdd(&d_ss[n0 + t], s_ss[t]);
    }
}

// ---------- gemm1 (tensor) + attn (tensor) in one launch ----------
__global__ __launch_bounds__(256) void k_mma1(const float* __restrict__ b1,
                      const float* __restrict__ ba1, const float* __restrict__ wa2,
                      const float* __restrict__ ba2) {
    __shared__ __align__(16) char buf[20480];   // sA 2x5120 | sB 2x5120 ; sT aliases
    __shared__ float sRed[2][64];
    bf16* sA = (bf16*)buf;
    bf16* sB = (bf16*)(buf + 10240);
    bf16* sT = (bf16*)buf;
    int x = blockIdx.x, y = blockIdx.y;
    int n0 = x*64;
    float acc[2][2][4] = {};
    if (y < 4) {
        int m0 = y*64;
        mma_mainloop(d_w1bf, d_Gbf, sA, sB, m0, n0, acc);
        store_T<true, false>(acc, b1, sT, nullptr, d_Hbf, m0, n0);
    } else {
        mma_mainloop(d_wa1bf, d_Gbf, sA, sB, 0, n0, acc);
        int t = threadIdx.x;
        int w = t >> 5, lane = t & 31;
        int g = lane >> 2, tig = lane & 3;
        int wm = w >> 2, wn = w & 3;
        float part[2][2] = {};
        #pragma unroll
        for (int mt = 0; mt < 2; mt++) {
            #pragma unroll
            for (int half = 0; half < 2; half++) {
                int r = wm*32 + mt*16 + half*8 + g;
                float bm = ba1[r], wmv = wa2[r];
                #pragma unroll
                for (int nt = 0; nt < 2; nt++)
                    #pragma unroll
                    for (int c = 0; c < 2; c++)
                        part[nt][c] = fmaf(wmv, fmaxf(acc[mt][nt][half*2+c] + bm, 0.f), part[nt][c]);
            }
        }
        #pragma unroll
        for (int nt = 0; nt < 2; nt++)
            #pragma unroll
            for (int c = 0; c < 2; c++) {
                part[nt][c] += __shfl_down_sync(0xffffffffu, part[nt][c], 16);
                part[nt][c] += __shfl_down_sync(0xffffffffu, part[nt][c], 8);
                part[nt][c] += __shfl_down_sync(0xffffffffu, part[nt][c], 4);
            }
        if (g == 0) {
            #pragma unroll
            for (int nt = 0; nt < 2; nt++)
                #pragma unroll
                for (int c = 0; c < 2; c++)
                    sRed[wm][wn*16 + nt*8 + tig*2 + c] = part[nt][c];
        }
        __syncthreads();
        if (t < 64) {
            float z = sRed[0][t] + sRed[1][t] + ba2[0];
            d_attn[n0 + t] = 1.f / (1.f + expf(-z));
        }
    }
}

// ---------- gemm2 (tensor): Ptbf[col][m] = W2 . Hbf + b2, + column sumsq ----------
__global__ __launch_bounds__(256) void k_mma2(const float* __restrict__ b2) {
    __shared__ __align__(16) char buf[20480];
    __shared__ float s_ss[64];
    bf16* sA = (bf16*)buf;
    bf16* sB = (bf16*)(buf + 10240);
    bf16* sT = (bf16*)buf;
    int m0 = blockIdx.y*64, n0 = blockIdx.x*64;
    float acc[2][2][4] = {};
    mma_mainloop(d_w2bf, d_Hbf, sA, sB, m0, n0, acc);
    store_T<false, true>(acc, b2, sT, s_ss, d_Ptbf, m0, n0);
}

// ---------- tensor-core sim, cp.async double-buffered, post-MMA normalization ----------
__global__ __launch_bounds__(256) void k_simt() {
    __shared__ __align__(16) bf16 sA[2*128*40];
    __shared__ __align__(16) bf16 sB[2*128*40];
    __shared__ int   spJ[128];
    __shared__ int   seJ[128];
    __shared__ float wJ[128];
    __shared__ float rnJ[128];
    int t = threadIdx.x;
    int Jt = blockIdx.x, It = blockIdx.y, b = blockIdx.z;
    int i0 = It*128, j0 = Jt*128;
    if (t < 128) {
        int cj = b*NS + j0 + t;
        spJ[t] = d_spv[cj]; seJ[t] = d_sel[cj]; wJ[t] = d_attn[cj];
        rnJ[t] = 1.f / fmaxf(sqrtf(d_ss[cj]), 1e-12f);
    }
    int w = t >> 5, lane = t & 31;
    int g = lane >> 2, tig = lane & 3;
    int wm = w >> 1, wn = w & 1;
    const bf16* TA = d_Ptbf + (size_t)(b*NS + i0)*NC;
    const bf16* TB = d_Ptbf + (size_t)(b*NS + j0)*NC;
    int lrow = t >> 1, lpart = (t & 1)*16;

    cp16(&sA[lrow*40 + lpart],     &TA[lrow*NC + lpart]);
    cp16(&sA[lrow*40 + lpart + 8], &TA[lrow*NC + lpart + 8]);
    cp16(&sB[lrow*40 + lpart],     &TB[lrow*NC + lpart]);
    cp16(&sB[lrow*40 + lpart + 8], &TB[lrow*NC + lpart + 8]);
    CP_COMMIT();
    CP_WAIT0();
    __syncthreads();

    float acc[2][8][4] = {};
    for (int kc = 0; kc < 8; kc++) {
        int cur = kc & 1;
        bf16* cA = sA + cur*5120;
        bf16* cB = sB + cur*5120;
        if (kc < 7) {
            int nxt = cur ^ 1;
            int kk = (kc+1)*32;
            cp16(&sA[nxt*5120 + lrow*40 + lpart],     &TA[lrow*NC + kk + lpart]);
            cp16(&sA[nxt*5120 + lrow*40 + lpart + 8], &TA[lrow*NC + kk + lpart + 8]);
            cp16(&sB[nxt*5120 + lrow*40 + lpart],     &TB[lrow*NC + kk + lpart]);
            cp16(&sB[nxt*5120 + lrow*40 + lpart + 8], &TB[lrow*NC + kk + lpart + 8]);
            CP_COMMIT();
        }
        #pragma unroll
        for (int ks = 0; ks < 2; ks++) {
            int kb = ks*16;
            uint32_t a[2][4];
            #pragma unroll
            for (int mt = 0; mt < 2; mt++) {
                int rb = wm*32 + mt*16;
                a[mt][0] = *(const uint32_t*)&cA[(rb + g    )*40 + kb + tig*2];
                a[mt][1] = *(const uint32_t*)&cA[(rb + g + 8)*40 + kb + tig*2];
                a[mt][2] = *(const uint32_t*)&cA[(rb + g    )*40 + kb + tig*2 + 8];
                a[mt][3] = *(const uint32_t*)&cA[(rb + g + 8)*40 + kb + tig*2 + 8];
            }
            #pragma unroll
            for (int nt = 0; nt < 8; nt++) {
                int nb = wn*64 + nt*8;
                uint32_t b0 = *(const uint32_t*)&cB[(nb + g)*40 + kb + tig*2];
                uint32_t b1 = *(const uint32_t*)&cB[(nb + g)*40 + kb + tig*2 + 8];
                #pragma unroll
                for (int mt = 0; mt < 2; mt++) {
                    asm volatile(
                        "mma.sync.aligned.m16n8k16.row.col.f32.bf16.bf16.f32 "
                        "{%0,%1,%2,%3}, {%4,%5,%6,%7}, {%8,%9}, {%0,%1,%2,%3};"
                        : "+f"(acc[mt][nt][0]), "+f"(acc[mt][nt][1]),
                          "+f"(acc[mt][nt][2]), "+f"(acc[mt][nt][3])
                        : "r"(a[mt][0]), "r"(a[mt][1]), "r"(a[mt][2]), "r"(a[mt][3]),
                          "r"(b0), "r"(b1));
                }
            }
        }
        if (kc < 7) { CP_WAIT0(); __syncthreads(); }
    }
    #pragma unroll
    for (int mt = 0; mt < 2; mt++) {
        #pragma unroll
        for (int half = 0; half < 2; half++) {
            int il = wm*32 + mt*16 + half*8 + g;
            int ci = b*NS + i0 + il;
            int gi = i0 + il;
            int si = d_sel[ci], spi = d_spv[ci];
            float wi = d_attn[ci];
            float ri = 1.f / fmaxf(sqrtf(d_ss[ci]), 1e-12f);
            float rA = 0.f, rB = 0.f, rD = 0.f;
            #pragma unroll
            for (int nt = 0; nt < 8; nt++) {
                #pragma unroll
                for (int c = 0; c < 2; c++) {
                    int jl = wn*64 + nt*8 + tig*2 + c;
                    float s = acc[mt][nt][half*2 + c] * ri * rnJ[jl];
                    if (seJ[jl]) {
                        rD += __expf(10.0f * s);      // 1/TEMP = 10
                        if (si && (gi != j0 + jl) && (spi == spJ[jl]) && (s > 0.7f)) {
                            float pw = wi * wJ[jl];
                            rB += pw; rA = fmaf(pw, s, rA);
                        }
                    }
                }
            }
            rA += __shfl_down_sync(0xffffffffu, rA, 2, 4);
            rA += __shfl_down_sync(0xffffffffu, rA, 1, 4);
            rB += __shfl_down_sync(0xffffffffu, rB, 2, 4);
            rB += __shfl_down_sync(0xffffffffu, rB, 1, 4);
            rD += __shfl_down_sync(0xffffffffu, rD, 2, 4);
            rD += __shfl_down_sync(0xffffffffu, rD, 1, 4);
            if (tig == 0) {
                atomicAdd(&d_rowA[ci], rA);
                atomicAdd(&d_rowB[ci], rB);
                atomicAdd(&d_rowD[ci], rD);
            }
        }
    }
}

// ---------- final reduction ----------
__global__ void k_final(float* __restrict__ out) {
    __shared__ float red[256];
    __shared__ float s_num, s_ps;
    int t = threadIdx.x;
    float totLoss = 0.f;
    int nHas = 0;
    for (int b = 0; b < NB; b++) {
        float num = 0.f, ps = 0.f;
        for (int i = t; i < NS; i += 256) {
            float Ai = d_rowA[b*NS+i], Bi = d_rowB[b*NS+i], Di = d_rowD[b*NS+i];
            float ld = logf(Di > 0.f ? Di : 1.f);
            num += Ai * 10.0f - ld * Bi;
            ps  += Bi;
        }
        red[t] = num; __syncthreads();
        for (int o = 128; o > 0; o >>= 1) { if (t < o) red[t] += red[t+o]; __syncthreads(); }
        if (t == 0) s_num = red[0];
        __syncthreads();
        red[t] = ps; __syncthreads();
        for (int o = 128; o > 0; o >>= 1) { if (t < o) red[t] += red[t+o]; __syncthreads(); }
        if (t == 0) s_ps = red[0];
        __syncthreads();
        if (t == 0) {
            if (s_ps > 0.f) {
                totLoss += -(0.1f/0.07f) * s_num / s_ps;
                nHas++;
            }
        }
        __syncthreads();
    }
    if (t == 0) out[0] = (nHas > 0) ? (totLoss / fmaxf((float)nHas, 1.f)) : 0.f;
}

extern "C" void kernel_launch(void* const* d_in, const int* in_sizes, int n_in,
                              void* d_out, int out_size) {
    const float*     feats  = (const float*)d_in[0];
    const long long* labels = (const long long*)d_in[1];
    const long long* sp     = (const long long*)d_in[2];
    const float*     w1     = (const float*)d_in[3];
    const float*     b1     = (const float*)d_in[4];
    const float*     w2     = (const float*)d_in[5];
    const float*     b2     = (const float*)d_in[6];
    const float*     wa1    = (const float*)d_in[7];
    const float*     ba1    = (const float*)d_in[8];
    const float*     wa2    = (const float*)d_in[9];
    const float*     ba2    = (const float*)d_in[10];
    float* out = (float*)d_out;

    k_prep  <<<NB + 36, 1024>>>(labels, sp, w1, w2, wa1);
    k_gather<<<dim3(NS/256, NC/16, NB), 256>>>(feats);
    k_mma1  <<<dim3(64, 5), 256>>>(b1, ba1, wa2, ba2);
    k_mma2  <<<dim3(64, 4), 256>>>(b2);
    k_simt  <<<dim3(8, 8, NB), 256>>>();
    k_final <<<1, 256>>>(out);
}

// round 13
// speedup vs baseline: 2.2146x; 1.0406x over previous
#include <cuda_runtime.h>
#include <cuda_bf16.h>
#include <math.h>
#include <stdint.h>

#define NB 4
#define NC 256
#define HWP 25600
#define NS 1024
#define NT 4096   // NB*NS

typedef __nv_bfloat16 bf16;

__device__ __forceinline__ void cp16(void* sdst, const void* gsrc) {
    uint32_t s = (uint32_t)__cvta_generic_to_shared(sdst);
    asm volatile("cp.async.cg.shared.global [%0], [%1], 16;" :: "r"(s), "l"(gsrc));
}
#define CP_COMMIT() asm volatile("cp.async.commit_group;")
#define CP_WAIT2()  asm volatile("cp.async.wait_group 2;")

// ---------- scratch ----------
__device__ __align__(16) bf16  d_Gbf[(size_t)NT*NC];   // gathered feats, [col][c]
__device__ __align__(16) bf16  d_Hbf[(size_t)NT*NC];   // hidden,         [col][m]
__device__ __align__(16) bf16  d_Ptbf[(size_t)NT*NC];  // proj (unnorm),  [col][m]
__device__ __align__(16) bf16  d_w1bf[NC*NC];
__device__ __align__(16) bf16  d_w2bf[NC*NC];
__device__ __align__(16) bf16  d_wa1bf[64*NC];
__device__ float d_attn[NT];
__device__ float d_ss[NT];
__device__ int   d_idx[NT];
__device__ int   d_sel[NT];
__device__ int   d_spv[NT];
__device__ int   d_vlist[NT];
__device__ int   d_ilist[NT];
__device__ float d_rowA[NT];
__device__ float d_rowB[NT];
__device__ float d_rowD[NT];
__device__ int   d_cnt;

// ---------- fused selection (blocks 0-3) + weight bf16 convert (blocks 4-39) ----------
__global__ void k_prep(const long long* __restrict__ labels, const long long* __restrict__ sp,
                       const float* __restrict__ w1, const float* __restrict__ w2,
                       const float* __restrict__ wa1) {
    int blk = blockIdx.x, t = threadIdx.x;   // 1024 threads
    if (blk >= NB) {
        int i = ((blk - NB)*1024 + t)*4;
        const float* src; bf16* dst; int off;
        if (i < 65536)        { src = w1;  dst = d_w1bf;  off = i; }
        else if (i < 131072)  { src = w2;  dst = d_w2bf;  off = i - 65536; }
        else                  { src = wa1; dst = d_wa1bf; off = i - 131072; }
        float4 v = *(const float4*)&src[off];
        __nv_bfloat162 lo = __floats2bfloat162_rn(v.x, v.y);
        __nv_bfloat162 hi = __floats2bfloat162_rn(v.z, v.w);
        *(uint2*)&dst[off] = make_uint2(*(uint32_t*)&lo, *(uint32_t*)&hi);
        return;
    }
    int b = blk;
    if (b == 0 && t == 0) d_cnt = 0;
    const long long* lb = labels + (long long)b*HWP;
    int base = t*25;
    unsigned flags = 0; int cnt = 0;
    #pragma unroll
    for (int j = 0; j < 25; j++) {
        int f = (lb[base+j] == 1);
        flags |= (unsigned)f << j; cnt += f;
    }
    __shared__ int wsum[32];
    __shared__ int s_nv;
    int lane = t & 31, w = t >> 5;
    int incl = cnt;
    #pragma unroll
    for (int o = 1; o < 32; o <<= 1) {
        int n = __shfl_up_sync(0xffffffffu, incl, o);
        if (lane >= o) incl += n;
    }
    if (lane == 31) wsum[w] = incl;
    __syncthreads();
    if (t < 32) {
        int v = wsum[t]; int inc2 = v;
        #pragma unroll
        for (int o = 1; o < 32; o <<= 1) {
            int n = __shfl_up_sync(0xffffffffu, inc2, o);
            if (t >= o) inc2 += n;
        }
        wsum[t] = inc2 - v;
        if (t == 31) s_nv = inc2;
    }
    __syncthreads();
    int v_run = (incl - cnt) + wsum[w];
    #pragma unroll
    for (int j = 0; j < 25; j++) {
        int p = base + j;
        if ((flags >> j) & 1u) {
            if (v_run < NS) d_vlist[b*NS + v_run] = p;
            v_run++;
        } else {
            int ir = p - v_run;
            if (ir < NS) d_ilist[b*NS + ir] = p;
        }
    }
    __syncthreads();
    int nv = s_nv; if (nv > NS) nv = NS;
    int s = t;
    int p, se;
    if (s < nv) { p = d_vlist[b*NS + s];        se = 1; }
    else        { p = d_ilist[b*NS + (s - nv)]; se = 0; }
    int col = b*NS + s;
    d_idx[col] = p;
    d_sel[col] = se;
    d_spv[col] = (int)sp[(long long)b*HWP + p];
    d_rowA[col] = 0.f; d_rowB[col] = 0.f; d_rowD[col] = 0.f; d_ss[col] = 0.f;
}

// ---------- gather feats -> Gbf[col][c] bf16 ----------
__global__ void k_gather(const float* __restrict__ feats) {
    int t = threadIdx.x;
    int s = blockIdx.x*256 + t;
    int b = blockIdx.z;
    int c0 = blockIdx.y*16;
    int col = b*NS + s;
    int p = d_idx[col];
    const float* fb = feats + ((long long)b*NC + c0)*HWP + p;
    uint32_t pk[8];
    #pragma unroll
    for (int cc = 0; cc < 8; cc++) {
        float v0 = __ldg(&fb[(long long)(2*cc  )*HWP]);
        float v1 = __ldg(&fb[(long long)(2*cc+1)*HWP]);
        __nv_bfloat162 pr = __floats2bfloat162_rn(v0, v1);
        pk[cc] = *(uint32_t*)&pr;
    }
    uint4* dst = (uint4*)&d_Gbf[(size_t)col*NC + c0];
    dst[0] = make_uint4(pk[0], pk[1], pk[2], pk[3]);
    dst[1] = make_uint4(pk[4], pk[5], pk[6], pk[7]);
}

// ---------- mma mainloop: 64x64 tile, K=256, 4-stage cp.async pipeline ----------
// A [m][k] bf16 row-major; X [col][k] bf16. sA/sB: 4 stages of 64x40 halves each.
__device__ __forceinline__ void mma_mainloop(const bf16* __restrict__ A,
                                             const bf16* __restrict__ X,
                                             bf16* sA, bf16* sB,
                                             int m0, int n0, float acc[2][2][4]) {
    int t = threadIdx.x;
    int w = t >> 5, lane = t & 31;
    int g = lane >> 2, tig = lane & 3;
    int wm = w >> 2, wn = w & 3;
    int frow = t >> 2, fchk = (t & 3)*8;
    const bf16* gA = &A[(size_t)(m0+frow)*NC + fchk];
    const bf16* gB = &X[(size_t)(n0+frow)*NC + fchk];
    #pragma unroll
    for (int pc = 0; pc < 3; pc++) {
        cp16(&sA[pc*2560 + frow*40 + fchk], gA + pc*32);
        cp16(&sB[pc*2560 + frow*40 + fchk], gB + pc*32);
        CP_COMMIT();
    }
    for (int kc = 0; kc < 8; kc++) {
        int cur = kc & 3;
        CP_WAIT2();
        __syncthreads();
        if (kc + 3 < 8) {
            int nxt = (kc + 3) & 3;
            cp16(&sA[nxt*2560 + frow*40 + fchk], gA + (kc+3)*32);
            cp16(&sB[nxt*2560 + frow*40 + fchk], gB + (kc+3)*32);
        }
        CP_COMMIT();
        bf16* cA = sA + cur*2560;
        bf16* cB = sB + cur*2560;
        #pragma unroll
        for (int ks = 0; ks < 2; ks++) {
            int kb = ks*16;
            uint32_t a[2][4], bb[2][2];
            #pragma unroll
            for (int mt = 0; mt < 2; mt++) {
                int rb = wm*32 + mt*16;
                a[mt][0] = *(const uint32_t*)&cA[(rb + g    )*40 + kb + tig*2];
                a[mt][1] = *(const uint32_t*)&cA[(rb + g + 8)*40 + kb + tig*2];
                a[mt][2] = *(const uint32_t*)&cA[(rb + g    )*40 + kb + tig*2 + 8];
                a[mt][3] = *(const uint32_t*)&cA[(rb + g + 8)*40 + kb + tig*2 + 8];
            }
            #pragma unroll
            for (int nt = 0; nt < 2; nt++) {
                int nb = wn*16 + nt*8;
                bb[nt][0] = *(const uint32_t*)&cB[(nb + g)*40 + kb + tig*2];
                bb[nt][1] = *(const uint32_t*)&cB[(nb + g)*40 + kb + tig*2 + 8];
            }
            #pragma unroll
            for (int mt = 0; mt < 2; mt++)
                #pragma unroll
                for (int nt = 0; nt < 2; nt++)
                    asm volatile(
                        "mma.sync.aligned.m16n8k16.row.col.f32.bf16.bf16.f32 "
                        "{%0,%1,%2,%3}, {%4,%5,%6,%7}, {%8,%9}, {%0,%1,%2,%3};"
                        : "+f"(acc[mt][nt][0]), "+f"(acc[mt][nt][1]),
                          "+f"(acc[mt][nt][2]), "+f"(acc[mt][nt][3])
                        : "r"(a[mt][0]), "r"(a[mt][1]), "r"(a[mt][2]), "r"(a[mt][3]),
                          "r"(bb[nt][0]), "r"(bb[nt][1]));
        }
    }
}

// ---------- transposed bf16 store epilogue: Y[col][m] = act(acc + bias[m]); optional col-sumsq ----------
template<bool RELU, bool SS>
__device__ __forceinline__ void store_T(float acc[2][2][4], const float* __restrict__ bias,
                                        bf16* sT /*64 x 72*/, float* s_ss,
                                        bf16* __restrict__ Y, int m0, int n0) {
    int t = threadIdx.x;
    int w = t >> 5, lane = t & 31;
    int g = lane >> 2, tig = lane & 3;
    int wm = w >> 2, wn = w & 3;
    if (SS && t < 64) s_ss[t] = 0.f;
    __syncthreads();   // done with sA/sB (aliased)
    #pragma unroll
    for (int mt = 0; mt < 2; mt++) {
        #pragma unroll
        for (int half = 0; half < 2; half++) {
            int r = wm*32 + mt*16 + half*8 + g;
            float bv = bias[m0 + r];
            #pragma unroll
            for (int nt = 0; nt < 2; nt++) {
                #pragma unroll
                for (int c = 0; c < 2; c++) {
                    int cl = wn*16 + nt*8 + tig*2 + c;
                    float v = acc[mt][nt][half*2 + c] + bv;
                    if (RELU) v = fmaxf(v, 0.f);
                    sT[cl*72 + r] = __float2bfloat16(v);
                }
            }
        }
    }
    __syncthreads();
    #pragma unroll
    for (int i = 0; i < 2; i++) {
        int e = t*2 + i;
        int row = e >> 3, chk = (e & 7)*8;
        uint4 v = *(uint4*)&sT[row*72 + chk];
        *(uint4*)&Y[(size_t)(n0+row)*NC + m0 + chk] = v;
        if (SS) {
            bf16* h = (bf16*)&v;
            float p = 0.f;
            #pragma unroll
            for (int q = 0; q < 8; q++) {
                float f = __bfloat162float(h[q]);
                p = fmaf(f, f, p);
            }
            atomicAdd(&s_ss[row], p);
        }
    }
    if (SS) {
        __syncthreads();
        if (t < 64) atomicAdd(&d_ss[n0 + t], s_ss[t]);
    }
}

// ---------- gemm1 (tensor) + attn (tensor) in one launch ----------
__global__ __launch_bounds__(256) void k_mma1(const float* __restrict__ b1,
                      const float* __restrict__ ba1, const float* __restrict__ wa2,
                      const float* __restrict__ ba2) {
    __shared__ __align__(16) char buf[40960];   // sA 4x5120 | sB 4x5120 ; sT aliases
    __shared__ float sRed[2][64];
    bf16* sA = (bf16*)buf;
    bf16* sB = (bf16*)(buf + 20480);
    bf16* sT = (bf16*)buf;
    int x = blockIdx.x, y = blockIdx.y;
    int n0 = x*64;
    float acc[2][2][4] = {};
    if (y < 4) {
        int m0 = y*64;
        mma_mainloop(d_w1bf, d_Gbf, sA, sB, m0, n0, acc);
        store_T<true, false>(acc, b1, sT, nullptr, d_Hbf, m0, n0);
    } else {
        mma_mainloop(d_wa1bf, d_Gbf, sA, sB, 0, n0, acc);
        int t = threadIdx.x;
        int w = t >> 5, lane = t & 31;
        int g = lane >> 2, tig = lane & 3;
        int wm = w >> 2, wn = w & 3;
        float part[2][2] = {};
        #pragma unroll
        for (int mt = 0; mt < 2; mt++) {
            #pragma unroll
            for (int half = 0; half < 2; half++) {
                int r = wm*32 + mt*16 + half*8 + g;
                float bm = ba1[r], wmv = wa2[r];
                #pragma unroll
                for (int nt = 0; nt < 2; nt++)
                    #pragma unroll
                    for (int c = 0; c < 2; c++)
                        part[nt][c] = fmaf(wmv, fmaxf(acc[mt][nt][half*2+c] + bm, 0.f), part[nt][c]);
            }
        }
        #pragma unroll
        for (int nt = 0; nt < 2; nt++)
            #pragma unroll
            for (int c = 0; c < 2; c++) {
                part[nt][c] += __shfl_down_sync(0xffffffffu, part[nt][c], 16);
                part[nt][c] += __shfl_down_sync(0xffffffffu, part[nt][c], 8);
                part[nt][c] += __shfl_down_sync(0xffffffffu, part[nt][c], 4);
            }
        if (g == 0) {
            #pragma unroll
            for (int nt = 0; nt < 2; nt++)
                #pragma unroll
                for (int c = 0; c < 2; c++)
                    sRed[wm][wn*16 + nt*8 + tig*2 + c] = part[nt][c];
        }
        __syncthreads();
        if (t < 64) {
            float z = sRed[0][t] + sRed[1][t] + ba2[0];
            d_attn[n0 + t] = 1.f / (1.f + expf(-z));
        }
    }
}

// ---------- gemm2 (tensor): Ptbf[col][m] = W2 . Hbf + b2, + column sumsq ----------
__global__ __launch_bounds__(256) void k_mma2(const float* __restrict__ b2) {
    __shared__ __align__(16) char buf[40960];
    __shared__ float s_ss[64];
    bf16* sA = (bf16*)buf;
    bf16* sB = (bf16*)(buf + 20480);
    bf16* sT = (bf16*)buf;
    int m0 = blockIdx.y*64, n0 = blockIdx.x*64;
    float acc[2][2][4] = {};
    mma_mainloop(d_w2bf, d_Hbf, sA, sB, m0, n0, acc);
    store_T<false, true>(acc, b2, sT, s_ss, d_Ptbf, m0, n0);
}

// ---------- tensor-core sim, 4-stage cp.async, post-MMA normalization, fused final ----------
#define SIMT_SMEM (4*10240*2)

__global__ __launch_bounds__(256) void k_simt(float* __restrict__ out) {
    extern __shared__ __align__(16) char dbuf[];
    bf16* sA = (bf16*)dbuf;                      // 4 stages x 5120 halves
    bf16* sB = (bf16*)(dbuf + 4*10240);
    __shared__ int   spJ[128];
    __shared__ int   seJ[128];
    __shared__ float wJ[128];
    __shared__ float rnJ[128];
    __shared__ int   s_last;
    int t = threadIdx.x;
    int Jt = blockIdx.x, It = blockIdx.y, b = blockIdx.z;
    int i0 = It*128, j0 = Jt*128;
    if (t < 128) {
        int cj = b*NS + j0 + t;
        spJ[t] = d_spv[cj]; seJ[t] = d_sel[cj]; wJ[t] = d_attn[cj];
        rnJ[t] = 1.f / fmaxf(sqrtf(d_ss[cj]), 1e-12f);
    }
    int w = t >> 5, lane = t & 31;
    int g = lane >> 2, tig = lane & 3;
    int wm = w >> 1, wn = w & 1;
    const bf16* TA = d_Ptbf + (size_t)(b*NS + i0)*NC;
    const bf16* TB = d_Ptbf + (size_t)(b*NS + j0)*NC;
    int lrow = t >> 1, lpart = (t & 1)*16;

    #pragma unroll
    for (int pc = 0; pc < 3; pc++) {
        int kk = pc*32;
        cp16(&sA[pc*5120 + lrow*40 + lpart],     &TA[lrow*NC + kk + lpart]);
        cp16(&sA[pc*5120 + lrow*40 + lpart + 8], &TA[lrow*NC + kk + lpart + 8]);
        cp16(&sB[pc*5120 + lrow*40 + lpart],     &TB[lrow*NC + kk + lpart]);
        cp16(&sB[pc*5120 + lrow*40 + lpart + 8], &TB[lrow*NC + kk + lpart + 8]);
        CP_COMMIT();
    }

    float acc[2][8][4] = {};
    for (int kc = 0; kc < 8; kc++) {
        int cur = kc & 3;
        CP_WAIT2();
        __syncthreads();
        if (kc + 3 < 8) {
            int nxt = (kc + 3) & 3;
            int kk = (kc+3)*32;
            cp16(&sA[nxt*5120 + lrow*40 + lpart],     &TA[lrow*NC + kk + lpart]);
            cp16(&sA[nxt*5120 + lrow*40 + lpart + 8], &TA[lrow*NC + kk + lpart + 8]);
            cp16(&sB[nxt*5120 + lrow*40 + lpart],     &TB[lrow*NC + kk + lpart]);
            cp16(&sB[nxt*5120 + lrow*40 + lpart + 8], &TB[lrow*NC + kk + lpart + 8]);
        }
        CP_COMMIT();
        bf16* cA = sA + cur*5120;
        bf16* cB = sB + cur*5120;
        #pragma unroll
        for (int ks = 0; ks < 2; ks++) {
            int kb = ks*16;
            uint32_t a[2][4];
            #pragma unroll
            for (int mt = 0; mt < 2; mt++) {
                int rb = wm*32 + mt*16;
                a[mt][0] = *(const uint32_t*)&cA[(rb + g    )*40 + kb + tig*2];
                a[mt][1] = *(const uint32_t*)&cA[(rb + g + 8)*40 + kb + tig*2];
                a[mt][2] = *(const uint32_t*)&cA[(rb + g    )*40 + kb + tig*2 + 8];
                a[mt][3] = *(const uint32_t*)&cA[(rb + g + 8)*40 + kb + tig*2 + 8];
            }
            #pragma unroll
            for (int nt = 0; nt < 8; nt++) {
                int nb = wn*64 + nt*8;
                uint32_t b0 = *(const uint32_t*)&cB[(nb + g)*40 + kb + tig*2];
                uint32_t b1 = *(const uint32_t*)&cB[(nb + g)*40 + kb + tig*2 + 8];
                #pragma unroll
                for (int mt = 0; mt < 2; mt++) {
                    asm volatile(
                        "mma.sync.aligned.m16n8k16.row.col.f32.bf16.bf16.f32 "
                        "{%0,%1,%2,%3}, {%4,%5,%6,%7}, {%8,%9}, {%0,%1,%2,%3};"
                        : "+f"(acc[mt][nt][0]), "+f"(acc[mt][nt][1]),
                          "+f"(acc[mt][nt][2]), "+f"(acc[mt][nt][3])
                        : "r"(a[mt][0]), "r"(a[mt][1]), "r"(a[mt][2]), "r"(a[mt][3]),
                          "r"(b0), "r"(b1));
                }
            }
        }
    }
    #pragma unroll
    for (int mt = 0; mt < 2; mt++) {
        #pragma unroll
        for (int half = 0; half < 2; half++) {
            int il = wm*32 + mt*16 + half*8 + g;
            int ci = b*NS + i0 + il;
            int gi = i0 + il;
            int si = d_sel[ci], spi = d_spv[ci];
            float wi = d_attn[ci];
            float ri = 1.f / fmaxf(sqrtf(d_ss[ci]), 1e-12f);
            float rA = 0.f, rB = 0.f, rD = 0.f;
            #pragma unroll
            for (int nt = 0; nt < 8; nt++) {
                #pragma unroll
                for (int c = 0; c < 2; c++) {
                    int jl = wn*64 + nt*8 + tig*2 + c;
                    float s = acc[mt][nt][half*2 + c] * ri * rnJ[jl];
                    if (seJ[jl]) {
                        rD += __expf(10.0f * s);      // 1/TEMP = 10
                        if (si && (gi != j0 + jl) && (spi == spJ[jl]) && (s > 0.7f)) {
                            float pw = wi * wJ[jl];
                            rB += pw; rA = fmaf(pw, s, rA);
                        }
                    }
                }
            }
            rA += __shfl_down_sync(0xffffffffu, rA, 2, 4);
            rA += __shfl_down_sync(0xffffffffu, rA, 1, 4);
            rB += __shfl_down_sync(0xffffffffu, rB, 2, 4);
            rB += __shfl_down_sync(0xffffffffu, rB, 1, 4);
            rD += __shfl_down_sync(0xffffffffu, rD, 2, 4);
            rD += __shfl_down_sync(0xffffffffu, rD, 1, 4);
            if (tig == 0) {
                atomicAdd(&d_rowA[ci], rA);
                atomicAdd(&d_rowB[ci], rB);
                atomicAdd(&d_rowD[ci], rD);
            }
        }
    }

    // ---- last-block fused final reduction ----
    __syncthreads();
    if (t == 0) {
        __threadfence();
        int prev = atomicAdd(&d_cnt, 1);
        s_last = (prev == 8*8*NB - 1);
    }
    __syncthreads();
    if (!s_last) return;
    __threadfence();

    __shared__ float red[256];
    __shared__ float s_num, s_ps;
    float totLoss = 0.f;
    int nHas = 0;
    for (int b2i = 0; b2i < NB; b2i++) {
        float num = 0.f, ps = 0.f;
        for (int i = t; i < NS; i += 256) {
            float Ai = d_rowA[b2i*NS+i], Bi = d_rowB[b2i*NS+i], Di = d_rowD[b2i*NS+i];
            float ld = logf(Di > 0.f ? Di : 1.f);
            num += Ai * 10.0f - ld * Bi;
            ps  += Bi;
        }
        red[t] = num; __syncthreads();
        for (int o = 128; o > 0; o >>= 1) { if (t < o) red[t] += red[t+o]; __syncthreads(); }
        if (t == 0) s_num = red[0];
        __syncthreads();
        red[t] = ps; __syncthreads();
        for (int o = 128; o > 0; o >>= 1) { if (t < o) red[t] += red[t+o]; __syncthreads(); }
        if (t == 0) s_ps = red[0];
        __syncthreads();
        if (t == 0) {
            if (s_ps > 0.f) {
                totLoss += -(0.1f/0.07f) * s_num / s_ps;
                nHas++;
            }
        }
        __syncthreads();
    }
    if (t == 0) out[0] = (nHas > 0) ? (totLoss / fmaxf((float)nHas, 1.f)) : 0.f;
}

extern "C" void kernel_launch(void* const* d_in, const int* in_sizes, int n_in,
                              void* d_out, int out_size) {
    const float*     feats  = (const float*)d_in[0];
    const long long* labels = (const long long*)d_in[1];
    const long long* sp     = (const long long*)d_in[2];
    const float*     w1     = (const float*)d_in[3];
    const float*     b1     = (const float*)d_in[4];
    const float*     w2     = (const float*)d_in[5];
    const float*     b2     = (const float*)d_in[6];
    const float*     wa1    = (const float*)d_in[7];
    const float*     ba1    = (const float*)d_in[8];
    const float*     wa2    = (const float*)d_in[9];
    const float*     ba2    = (const float*)d_in[10];
    float* out = (float*)d_out;

    static bool inited = false;
    if (!inited) {
        cudaFuncSetAttribute(k_simt, cudaFuncAttributeMaxDynamicSharedMemorySize, SIMT_SMEM);
        inited = true;
    }

    k_prep  <<<NB + 36, 1024>>>(labels, sp, w1, w2, wa1);
    k_gather<<<dim3(NS/256, NC/16, NB), 256>>>(feats);
    k_mma1  <<<dim3(64, 5), 256>>>(b1, ba1, wa2, ba2);
    k_mma2  <<<dim3(64, 4), 256>>>(b2);
    k_simt  <<<dim3(8, 8, NB), 256, SIMT_SMEM>>>(out);
}

// round 14
// speedup vs baseline: 2.2857x; 1.0321x over previous
#include <cuda_runtime.h>
#include <cuda_bf16.h>
#include <math.h>
#include <stdint.h>

#define NB 4
#define NC 256
#define HWP 25600
#define NS 1024
#define NT 4096   // NB*NS

typedef __nv_bfloat16 bf16;

__device__ __forceinline__ void cp16(void* sdst, const void* gsrc) {
    uint32_t s = (uint32_t)__cvta_generic_to_shared(sdst);
    asm volatile("cp.async.cg.shared.global [%0], [%1], 16;" :: "r"(s), "l"(gsrc));
}
#define CP_COMMIT() asm volatile("cp.async.commit_group;")
#define CP_WAIT2()  asm volatile("cp.async.wait_group 2;")

__device__ __forceinline__ void ldsm_x4(uint32_t& r0, uint32_t& r1, uint32_t& r2, uint32_t& r3,
                                        uint32_t addr) {
    asm volatile("ldmatrix.sync.aligned.m8n8.x4.shared.b16 {%0,%1,%2,%3}, [%4];"
                 : "=r"(r0), "=r"(r1), "=r"(r2), "=r"(r3) : "r"(addr));
}

// ---------- scratch ----------
__device__ __align__(16) bf16  d_Gbf[(size_t)NT*NC];   // gathered feats, [col][c]
__device__ __align__(16) bf16  d_Hbf[(size_t)NT*NC];   // hidden,         [col][m]
__device__ __align__(16) bf16  d_Ptbf[(size_t)NT*NC];  // proj (unnorm),  [col][m]
__device__ __align__(16) bf16  d_w1bf[NC*NC];
__device__ __align__(16) bf16  d_w2bf[NC*NC];
__device__ __align__(16) bf16  d_wa1bf[64*NC];
__device__ float d_attn[NT];
__device__ float d_ss[NT];
__device__ int   d_idx[NT];
__device__ int   d_sel[NT];
__device__ int   d_spv[NT];
__device__ int   d_vlist[NT];
__device__ int   d_ilist[NT];
__device__ float d_rowA[NT];
__device__ float d_rowB[NT];
__device__ float d_rowD[NT];
__device__ int   d_cnt;

// ---------- fused selection (blocks 0-3) + weight bf16 convert (blocks 4-39) ----------
__global__ void k_prep(const long long* __restrict__ labels, const long long* __restrict__ sp,
                       const float* __restrict__ w1, const float* __restrict__ w2,
                       const float* __restrict__ wa1) {
    int blk = blockIdx.x, t = threadIdx.x;   // 1024 threads
    if (blk >= NB) {
        int i = ((blk - NB)*1024 + t)*4;
        const float* src; bf16* dst; int off;
        if (i < 65536)        { src = w1;  dst = d_w1bf;  off = i; }
        else if (i < 131072)  { src = w2;  dst = d_w2bf;  off = i - 65536; }
        else                  { src = wa1; dst = d_wa1bf; off = i - 131072; }
        float4 v = *(const float4*)&src[off];
        __nv_bfloat162 lo = __floats2bfloat162_rn(v.x, v.y);
        __nv_bfloat162 hi = __floats2bfloat162_rn(v.z, v.w);
        *(uint2*)&dst[off] = make_uint2(*(uint32_t*)&lo, *(uint32_t*)&hi);
        return;
    }
    int b = blk;
    if (b == 0 && t == 0) d_cnt = 0;
    const long long* lb = labels + (long long)b*HWP;
    int base = t*25;
    unsigned flags = 0; int cnt = 0;
    #pragma unroll
    for (int j = 0; j < 25; j++) {
        int f = (lb[base+j] == 1);
        flags |= (unsigned)f << j; cnt += f;
    }
    __shared__ int wsum[32];
    __shared__ int s_nv;
    int lane = t & 31, w = t >> 5;
    int incl = cnt;
    #pragma unroll
    for (int o = 1; o < 32; o <<= 1) {
        int n = __shfl_up_sync(0xffffffffu, incl, o);
        if (lane >= o) incl += n;
    }
    if (lane == 31) wsum[w] = incl;
    __syncthreads();
    if (t < 32) {
        int v = wsum[t]; int inc2 = v;
        #pragma unroll
        for (int o = 1; o < 32; o <<= 1) {
            int n = __shfl_up_sync(0xffffffffu, inc2, o);
            if (t >= o) inc2 += n;
        }
        wsum[t] = inc2 - v;
        if (t == 31) s_nv = inc2;
    }
    __syncthreads();
    int v_run = (incl - cnt) + wsum[w];
    #pragma unroll
    for (int j = 0; j < 25; j++) {
        int p = base + j;
        if ((flags >> j) & 1u) {
            if (v_run < NS) d_vlist[b*NS + v_run] = p;
            v_run++;
        } else {
            int ir = p - v_run;
            if (ir < NS) d_ilist[b*NS + ir] = p;
        }
    }
    __syncthreads();
    int nv = s_nv; if (nv > NS) nv = NS;
    int s = t;
    int p, se;
    if (s < nv) { p = d_vlist[b*NS + s];        se = 1; }
    else        { p = d_ilist[b*NS + (s - nv)]; se = 0; }
    int col = b*NS + s;
    d_idx[col] = p;
    d_sel[col] = se;
    d_spv[col] = (int)sp[(long long)b*HWP + p];
    d_rowA[col] = 0.f; d_rowB[col] = 0.f; d_rowD[col] = 0.f; d_ss[col] = 0.f;
}

// ---------- gather feats -> Gbf[col][c] bf16 ----------
__global__ void k_gather(const float* __restrict__ feats) {
    int t = threadIdx.x;
    int s = blockIdx.x*256 + t;
    int b = blockIdx.z;
    int c0 = blockIdx.y*16;
    int col = b*NS + s;
    int p = d_idx[col];
    const float* fb = feats + ((long long)b*NC + c0)*HWP + p;
    uint32_t pk[8];
    #pragma unroll
    for (int cc = 0; cc < 8; cc++) {
        float v0 = __ldg(&fb[(long long)(2*cc  )*HWP]);
        float v1 = __ldg(&fb[(long long)(2*cc+1)*HWP]);
        __nv_bfloat162 pr = __floats2bfloat162_rn(v0, v1);
        pk[cc] = *(uint32_t*)&pr;
    }
    uint4* dst = (uint4*)&d_Gbf[(size_t)col*NC + c0];
    dst[0] = make_uint4(pk[0], pk[1], pk[2], pk[3]);
    dst[1] = make_uint4(pk[4], pk[5], pk[6], pk[7]);
}

// ---------- mma mainloop: 64x64 tile, K=256, 4-stage cp.async, ldmatrix fragments ----------
// A [m][k] bf16 row-major; X [col][k] bf16. sA/sB: 4 stages of 64x40 halves each.
__device__ __forceinline__ void mma_mainloop(const bf16* __restrict__ A,
                                             const bf16* __restrict__ X,
                                             bf16* sA, bf16* sB,
                                             int m0, int n0, float acc[2][2][4]) {
    int t = threadIdx.x;
    int w = t >> 5, lane = t & 31;
    int wm = w >> 2, wn = w & 3;
    int frow = t >> 2, fchk = (t & 3)*8;
    const bf16* gA = &A[(size_t)(m0+frow)*NC + fchk];
    const bf16* gB = &X[(size_t)(n0+frow)*NC + fchk];
    #pragma unroll
    for (int pc = 0; pc < 3; pc++) {
        cp16(&sA[pc*2560 + frow*40 + fchk], gA + pc*32);
        cp16(&sB[pc*2560 + frow*40 + fchk], gB + pc*32);
        CP_COMMIT();
    }
    // ldmatrix per-lane address offsets (bytes)
    uint32_t sAb = (uint32_t)__cvta_generic_to_shared(sA);
    uint32_t sBb = (uint32_t)__cvta_generic_to_shared(sB);
    int lane7 = lane & 7;
    uint32_t aoff[2];
    #pragma unroll
    for (int mt = 0; mt < 2; mt++) {
        int rb = wm*32 + mt*16;
        aoff[mt] = ((rb + ((lane>>3)&1)*8 + lane7)*40 + (lane>>4)*8)*2;
    }
    uint32_t boff = ((wn*16 + ((lane>>4)&1)*8 + lane7)*40 + ((lane>>3)&1)*8)*2;

    for (int kc = 0; kc < 8; kc++) {
        int cur = kc & 3;
        CP_WAIT2();
        __syncthreads();
        if (kc + 3 < 8) {
            int nxt = (kc + 3) & 3;
            cp16(&sA[nxt*2560 + frow*40 + fchk], gA + (kc+3)*32);
            cp16(&sB[nxt*2560 + frow*40 + fchk], gB + (kc+3)*32);
        }
        CP_COMMIT();
        uint32_t cAa = sAb + cur*5120;
        uint32_t cBa = sBb + cur*5120;
        #pragma unroll
        for (int ks = 0; ks < 2; ks++) {
            uint32_t kbB = ks*32;   // 16 halves
            uint32_t a[2][4], bb[2][2];
            #pragma unroll
            for (int mt = 0; mt < 2; mt++)
                ldsm_x4(a[mt][0], a[mt][1], a[mt][2], a[mt][3], cAa + aoff[mt] + kbB);
            ldsm_x4(bb[0][0], bb[0][1], bb[1][0], bb[1][1], cBa + boff + kbB);
            #pragma unroll
            for (int mt = 0; mt < 2; mt++)
                #pragma unroll
                for (int nt = 0; nt < 2; nt++)
                    asm volatile(
                        "mma.sync.aligned.m16n8k16.row.col.f32.bf16.bf16.f32 "
                        "{%0,%1,%2,%3}, {%4,%5,%6,%7}, {%8,%9}, {%0,%1,%2,%3};"
                        : "+f"(acc[mt][nt][0]), "+f"(acc[mt][nt][1]),
                          "+f"(acc[mt][nt][2]), "+f"(acc[mt][nt][3])
                        : "r"(a[mt][0]), "r"(a[mt][1]), "r"(a[mt][2]), "r"(a[mt][3]),
                          "r"(bb[nt][0]), "r"(bb[nt][1]));
        }
    }
}

// ---------- transposed bf16 store epilogue: Y[col][m] = act(acc + bias[m]); optional col-sumsq ----------
template<bool RELU, bool SS>
__device__ __forceinline__ void store_T(float acc[2][2][4], const float* __restrict__ bias,
                                        bf16* sT /*64 x 72*/, float* s_ss,
                                        bf16* __restrict__ Y, int m0, int n0) {
    int t = threadIdx.x;
    int w = t >> 5, lane = t & 31;
    int g = lane >> 2, tig = lane & 3;
    int wm = w >> 2, wn = w & 3;
    if (SS && t < 64) s_ss[t] = 0.f;
    __syncthreads();   // done with sA/sB (aliased)
    #pragma unroll
    for (int mt = 0; mt < 2; mt++) {
        #pragma unroll
        for (int half = 0; half < 2; half++) {
            int r = wm*32 + mt*16 + half*8 + g;
            float bv = bias[m0 + r];
            #pragma unroll
            for (int nt = 0; nt < 2; nt++) {
                #pragma unroll
                for (int c = 0; c < 2; c++) {
                    int cl = wn*16 + nt*8 + tig*2 + c;
                    float v = acc[mt][nt][half*2 + c] + bv;
                    if (RELU) v = fmaxf(v, 0.f);
                    sT[cl*72 + r] = __float2bfloat16(v);
                }
            }
        }
    }
    __syncthreads();
    #pragma unroll
    for (int i = 0; i < 2; i++) {
        int e = t*2 + i;
        int row = e >> 3, chk = (e & 7)*8;
        uint4 v = *(uint4*)&sT[row*72 + chk];
        *(uint4*)&Y[(size_t)(n0+row)*NC + m0 + chk] = v;
        if (SS) {
            bf16* h = (bf16*)&v;
            float p = 0.f;
            #pragma unroll
            for (int q = 0; q < 8; q++) {
                float f = __bfloat162float(h[q]);
                p = fmaf(f, f, p);
            }
            atomicAdd(&s_ss[row], p);
        }
    }
    if (SS) {
        __syncthreads();
        if (t < 64) atomicAdd(&d_ss[n0 + t], s_ss[t]);
    }
}

// ---------- gemm1 (tensor) + attn (tensor) in one launch ----------
__global__ __launch_bounds__(256) void k_mma1(const float* __restrict__ b1,
                      const float* __restrict__ ba1, const float* __restrict__ wa2,
                      const float* __restrict__ ba2) {
    __shared__ __align__(16) char buf[40960];   // sA 4x5120 | sB 4x5120 ; sT aliases
    __shared__ float sRed[2][64];
    bf16* sA = (bf16*)buf;
    bf16* sB = (bf16*)(buf + 20480);
    bf16* sT = (bf16*)buf;
    int x = blockIdx.x, y = blockIdx.y;
    int n0 = x*64;
    float acc[2][2][4] = {};
    if (y < 4) {
        int m0 = y*64;
        mma_mainloop(d_w1bf, d_Gbf, sA, sB, m0, n0, acc);
        store_T<true, false>(acc, b1, sT, nullptr, d_Hbf, m0, n0);
    } else {
        mma_mainloop(d_wa1bf, d_Gbf, sA, sB, 0, n0, acc);
        int t = threadIdx.x;
        int w = t >> 5, lane = t & 31;
        int g = lane >> 2, tig = lane & 3;
        int wm = w >> 2, wn = w & 3;
        float part[2][2] = {};
        #pragma unroll
        for (int mt = 0; mt < 2; mt++) {
            #pragma unroll
            for (int half = 0; half < 2; half++) {
                int r = wm*32 + mt*16 + half*8 + g;
                float bm = ba1[r], wmv = wa2[r];
                #pragma unroll
                for (int nt = 0; nt < 2; nt++)
                    #pragma unroll
                    for (int c = 0; c < 2; c++)
                        part[nt][c] = fmaf(wmv, fmaxf(acc[mt][nt][half*2+c] + bm, 0.f), part[nt][c]);
            }
        }
        #pragma unroll
        for (int nt = 0; nt < 2; nt++)
            #pragma unroll
            for (int c = 0; c < 2; c++) {
                part[nt][c] += __shfl_down_sync(0xffffffffu, part[nt][c], 16);
                part[nt][c] += __shfl_down_sync(0xffffffffu, part[nt][c], 8);
                part[nt][c] += __shfl_down_sync(0xffffffffu, part[nt][c], 4);
            }
        if (g == 0) {
            #pragma unroll
            for (int nt = 0; nt < 2; nt++)
                #pragma unroll
                for (int c = 0; c < 2; c++)
                    sRed[wm][wn*16 + nt*8 + tig*2 + c] = part[nt][c];
        }
        __syncthreads();
        if (t < 64) {
            float z = sRed[0][t] + sRed[1][t] + ba2[0];
            d_attn[n0 + t] = 1.f / (1.f + expf(-z));
        }
    }
}

// ---------- gemm2 (tensor): Ptbf[col][m] = W2 . Hbf + b2, + column sumsq ----------
__global__ __launch_bounds__(256) void k_mma2(const float* __restrict__ b2) {
    __shared__ __align__(16) char buf[40960];
    __shared__ float s_ss[64];
    bf16* sA = (bf16*)buf;
    bf16* sB = (bf16*)(buf + 20480);
    bf16* sT = (bf16*)buf;
    int m0 = blockIdx.y*64, n0 = blockIdx.x*64;
    float acc[2][2][4] = {};
    mma_mainloop(d_w2bf, d_Hbf, sA, sB, m0, n0, acc);
    store_T<false, true>(acc, b2, sT, s_ss, d_Ptbf, m0, n0);
}

// ---------- tensor-core sim, 4-stage cp.async, ldmatrix, post-MMA normalization, fused final ----------
#define SIMT_SMEM (4*10240*2)

__global__ __launch_bounds__(256) void k_simt(float* __restrict__ out) {
    extern __shared__ __align__(16) char dbuf[];
    bf16* sA = (bf16*)dbuf;                      // 4 stages x 5120 halves
    bf16* sB = (bf16*)(dbuf + 4*10240);
    __shared__ int   spJ[128];
    __shared__ int   seJ[128];
    __shared__ float wJ[128];
    __shared__ float rnJ[128];
    __shared__ int   s_last;
    int t = threadIdx.x;
    int Jt = blockIdx.x, It = blockIdx.y, b = blockIdx.z;
    int i0 = It*128, j0 = Jt*128;
    if (t < 128) {
        int cj = b*NS + j0 + t;
        spJ[t] = d_spv[cj]; seJ[t] = d_sel[cj]; wJ[t] = d_attn[cj];
        rnJ[t] = 1.f / fmaxf(sqrtf(d_ss[cj]), 1e-12f);
    }
    int w = t >> 5, lane = t & 31;
    int g = lane >> 2, tig = lane & 3;
    int wm = w >> 1, wn = w & 1;
    const bf16* TA = d_Ptbf + (size_t)(b*NS + i0)*NC;
    const bf16* TB = d_Ptbf + (size_t)(b*NS + j0)*NC;
    int lrow = t >> 1, lpart = (t & 1)*16;

    #pragma unroll
    for (int pc = 0; pc < 3; pc++) {
        int kk = pc*32;
        cp16(&sA[pc*5120 + lrow*40 + lpart],     &TA[lrow*NC + kk + lpart]);
        cp16(&sA[pc*5120 + lrow*40 + lpart + 8], &TA[lrow*NC + kk + lpart + 8]);
        cp16(&sB[pc*5120 + lrow*40 + lpart],     &TB[lrow*NC + kk + lpart]);
        cp16(&sB[pc*5120 + lrow*40 + lpart + 8], &TB[lrow*NC + kk + lpart + 8]);
        CP_COMMIT();
    }

    uint32_t sAb = (uint32_t)__cvta_generic_to_shared(sA);
    uint32_t sBb = (uint32_t)__cvta_generic_to_shared(sB);
    int lane7 = lane & 7;
    uint32_t aoff[2];
    #pragma unroll
    for (int mt = 0; mt < 2; mt++) {
        int rb = wm*32 + mt*16;
        aoff[mt] = ((rb + ((lane>>3)&1)*8 + lane7)*40 + (lane>>4)*8)*2;
    }
    uint32_t boff[4];
    #pragma unroll
    for (int pr = 0; pr < 4; pr++) {
        int nb = wn*64 + pr*16;
        boff[pr] = ((nb + ((lane>>4)&1)*8 + lane7)*40 + ((lane>>3)&1)*8)*2;
    }

    float acc[2][8][4] = {};
    for (int kc = 0; kc < 8; kc++) {
        int cur = kc & 3;
        CP_WAIT2();
        __syncthreads();
        if (kc + 3 < 8) {
            int nxt = (kc + 3) & 3;
            int kk = (kc+3)*32;
            cp16(&sA[nxt*5120 + lrow*40 + lpart],     &TA[lrow*NC + kk + lpart]);
            cp16(&sA[nxt*5120 + lrow*40 + lpart + 8], &TA[lrow*NC + kk + lpart + 8]);
            cp16(&sB[nxt*5120 + lrow*40 + lpart],     &TB[lrow*NC + kk + lpart]);
            cp16(&sB[nxt*5120 + lrow*40 + lpart + 8], &TB[lrow*NC + kk + lpart + 8]);
        }
        CP_COMMIT();
        uint32_t cAa = sAb + cur*10240;
        uint32_t cBa = sBb + cur*10240;
        #pragma unroll
        for (int ks = 0; ks < 2; ks++) {
            uint32_t kbB = ks*32;
            uint32_t a[2][4];
            #pragma unroll
            for (int mt = 0; mt < 2; mt++)
                ldsm_x4(a[mt][0], a[mt][1], a[mt][2], a[mt][3], cAa + aoff[mt] + kbB);
            #pragma unroll
            for (int pr = 0; pr < 4; pr++) {
                uint32_t b00, b01, b10, b11;
                ldsm_x4(b00, b01, b10, b11, cBa + boff[pr] + kbB);
                #pragma unroll
                for (int mt = 0; mt < 2; mt++) {
                    asm volatile(
                        "mma.sync.aligned.m16n8k16.row.col.f32.bf16.bf16.f32 "
                        "{%0,%1,%2,%3}, {%4,%5,%6,%7}, {%8,%9}, {%0,%1,%2,%3};"
                        : "+f"(acc[mt][2*pr][0]), "+f"(acc[mt][2*pr][1]),
                          "+f"(acc[mt][2*pr][2]), "+f"(acc[mt][2*pr][3])
                        : "r"(a[mt][0]), "r"(a[mt][1]), "r"(a[mt][2]), "r"(a[mt][3]),
                          "r"(b00), "r"(b01));
                    asm volatile(
                        "mma.sync.aligned.m16n8k16.row.col.f32.bf16.bf16.f32 "
                        "{%0,%1,%2,%3}, {%4,%5,%6,%7}, {%8,%9}, {%0,%1,%2,%3};"
                        : "+f"(acc[mt][2*pr+1][0]), "+f"(acc[mt][2*pr+1][1]),
                          "+f"(acc[mt][2*pr+1][2]), "+f"(acc[mt][2*pr+1][3])
                        : "r"(a[mt][0]), "r"(a[mt][1]), "r"(a[mt][2]), "r"(a[mt][3]),
                          "r"(b10), "r"(b11));
                }
            }
        }
    }
    #pragma unroll
    for (int mt = 0; mt < 2; mt++) {
        #pragma unroll
        for (int half = 0; half < 2; half++) {
            int il = wm*32 + mt*16 + half*8 + g;
            int ci = b*NS + i0 + il;
            int gi = i0 + il;
            int si = d_sel[ci], spi = d_spv[ci];
            float wi = d_attn[ci];
            float ri = 1.f / fmaxf(sqrtf(d_ss[ci]), 1e-12f);
            float rA = 0.f, rB = 0.f, rD = 0.f;
            #pragma unroll
            for (int nt = 0; nt < 8; nt++) {
                #pragma unroll
                for (int c = 0; c < 2; c++) {
                    int jl = wn*64 + nt*8 + tig*2 + c;
                    float s = acc[mt][nt][half*2 + c] * ri * rnJ[jl];
                    if (seJ[jl]) {
                        rD += __expf(10.0f * s);      // 1/TEMP = 10
                        if (si && (gi != j0 + jl) && (spi == spJ[jl]) && (s > 0.7f)) {
                            float pw = wi * wJ[jl];
                            rB += pw; rA = fmaf(pw, s, rA);
                        }
                    }
                }
            }
            rA += __shfl_down_sync(0xffffffffu, rA, 2, 4);
            rA += __shfl_down_sync(0xffffffffu, rA, 1, 4);
            rB += __shfl_down_sync(0xffffffffu, rB, 2, 4);
            rB += __shfl_down_sync(0xffffffffu, rB, 1, 4);
            rD += __shfl_down_sync(0xffffffffu, rD, 2, 4);
            rD += __shfl_down_sync(0xffffffffu, rD, 1, 4);
            if (tig == 0) {
                atomicAdd(&d_rowA[ci], rA);
                atomicAdd(&d_rowB[ci], rB);
                atomicAdd(&d_rowD[ci], rD);
            }
        }
    }

    // ---- last-block fused final reduction ----
    __syncthreads();
    if (t == 0) {
        __threadfence();
        int prev = atomicAdd(&d_cnt, 1);
        s_last = (prev == 8*8*NB - 1);
    }
    __syncthreads();
    if (!s_last) return;
    __threadfence();

    __shared__ float red[256];
    __shared__ float s_num, s_ps;
    float totLoss = 0.f;
    int nHas = 0;
    for (int b2i = 0; b2i < NB; b2i++) {
        float num = 0.f, ps = 0.f;
        for (int i = t; i < NS; i += 256) {
            float Ai = d_rowA[b2i*NS+i], Bi = d_rowB[b2i*NS+i], Di = d_rowD[b2i*NS+i];
            float ld = logf(Di > 0.f ? Di : 1.f);
            num += Ai * 10.0f - ld * Bi;
            ps  += Bi;
        }
        red[t] = num; __syncthreads();
        for (int o = 128; o > 0; o >>= 1) { if (t < o) red[t] += red[t+o]; __syncthreads(); }
        if (t == 0) s_num = red[0];
        __syncthreads();
        red[t] = ps; __syncthreads();
        for (int o = 128; o > 0; o >>= 1) { if (t < o) red[t] += red[t+o]; __syncthreads(); }
        if (t == 0) s_ps = red[0];
        __syncthreads();
        if (t == 0) {
            if (s_ps > 0.f) {
                totLoss += -(0.1f/0.07f) * s_num / s_ps;
                nHas++;
            }
        }
        __syncthreads();
    }
    if (t == 0) out[0] = (nHas > 0) ? (totLoss / fmaxf((float)nHas, 1.f)) : 0.f;
}

extern "C" void kernel_launch(void* const* d_in, const int* in_sizes, int n_in,
                              void* d_out, int out_size) {
    const float*     feats  = (const float*)d_in[0];
    const long long* labels = (const long long*)d_in[1];
    const long long* sp     = (const long long*)d_in[2];
    const float*     w1     = (const float*)d_in[3];
    const float*     b1     = (const float*)d_in[4];
    const float*     w2     = (const float*)d_in[5];
    const float*     b2     = (const float*)d_in[6];
    const float*     wa1    = (const float*)d_in[7];
    const float*     ba1    = (const float*)d_in[8];
    const float*     wa2    = (const float*)d_in[9];
    const float*     ba2    = (const float*)d_in[10];
    float* out = (float*)d_out;

    static bool inited = false;
    if (!inited) {
        cudaFuncSetAttribute(k_simt, cudaFuncAttributeMaxDynamicSharedMemorySize, SIMT_SMEM);
        inited = true;
    }

    k_prep  <<<NB + 36, 1024>>>(labels, sp, w1, w2, wa1);
    k_gather<<<dim3(NS/256, NC/16, NB), 256>>>(feats);
    k_mma1  <<<dim3(64, 5), 256>>>(b1, ba1, wa2, ba2);
    k_mma2  <<<dim3(64, 4), 256>>>(b2);
    k_simt  <<<dim3(8, 8, NB), 256, SIMT_SMEM>>>(out);
}

// round 15
// speedup vs baseline: 2.3616x; 1.0332x over previous
#include <cuda_runtime.h>
#include <cuda_bf16.h>
#include <math.h>
#include <stdint.h>

#define NB 4
#define NC 256
#define HWP 25600
#define NS 1024
#define NT 4096   // NB*NS

typedef __nv_bfloat16 bf16;

__device__ __forceinline__ void cp16(void* sdst, const void* gsrc) {
    uint32_t s = (uint32_t)__cvta_generic_to_shared(sdst);
    asm volatile("cp.async.cg.shared.global [%0], [%1], 16;" :: "r"(s), "l"(gsrc));
}
#define CP_COMMIT() asm volatile("cp.async.commit_group;")
#define CP_WAIT2()  asm volatile("cp.async.wait_group 2;")

__device__ __forceinline__ void ldsm_x4(uint32_t& r0, uint32_t& r1, uint32_t& r2, uint32_t& r3,
                                        uint32_t addr) {
    asm volatile("ldmatrix.sync.aligned.m8n8.x4.shared.b16 {%0,%1,%2,%3}, [%4];"
                 : "=r"(r0), "=r"(r1), "=r"(r2), "=r"(r3) : "r"(addr));
}

// ---------- scratch ----------
__device__ __align__(16) bf16  d_Gbf[(size_t)NT*NC];   // gathered feats, [col][c]
__device__ __align__(16) bf16  d_Hbf[(size_t)NT*NC];   // hidden,         [col][m]
__device__ __align__(16) bf16  d_Ptbf[(size_t)NT*NC];  // proj (unnorm),  [col][m]
__device__ __align__(16) bf16  d_w1bf[NC*NC];
__device__ __align__(16) bf16  d_w2bf[NC*NC];
__device__ __align__(16) bf16  d_wa1bf[64*NC];
__device__ float d_attn[NT];
__device__ float d_ss[NT];
__device__ int   d_idx[NT];
__device__ int   d_sel[NT];
__device__ int   d_spv[NT];
__device__ int   d_vlist[NT];
__device__ int   d_ilist[NT];
__device__ float d_rowA[NT];
__device__ float d_rowB[NT];
__device__ float d_rowD[NT];
__device__ int   d_cnt;

// ---------- fused selection (blocks 0-3) + weight bf16 convert (blocks 4-39) ----------
__global__ void k_prep(const long long* __restrict__ labels, const long long* __restrict__ sp,
                       const float* __restrict__ w1, const float* __restrict__ w2,
                       const float* __restrict__ wa1) {
    int blk = blockIdx.x, t = threadIdx.x;   // 1024 threads
    if (blk >= NB) {
        int i = ((blk - NB)*1024 + t)*4;
        const float* src; bf16* dst; int off;
        if (i < 65536)        { src = w1;  dst = d_w1bf;  off = i; }
        else if (i < 131072)  { src = w2;  dst = d_w2bf;  off = i - 65536; }
        else                  { src = wa1; dst = d_wa1bf; off = i - 131072; }
        float4 v = *(const float4*)&src[off];
        __nv_bfloat162 lo = __floats2bfloat162_rn(v.x, v.y);
        __nv_bfloat162 hi = __floats2bfloat162_rn(v.z, v.w);
        *(uint2*)&dst[off] = make_uint2(*(uint32_t*)&lo, *(uint32_t*)&hi);
        return;
    }
    int b = blk;
    if (b == 0 && t == 0) d_cnt = 0;
    const long long* lb = labels + (long long)b*HWP;
    int base = t*25;
    unsigned flags = 0; int cnt = 0;
    #pragma unroll
    for (int j = 0; j < 25; j++) {
        int f = (lb[base+j] == 1);
        flags |= (unsigned)f << j; cnt += f;
    }
    __shared__ int wsum[32];
    __shared__ int s_nv;
    int lane = t & 31, w = t >> 5;
    int incl = cnt;
    #pragma unroll
    for (int o = 1; o < 32; o <<= 1) {
        int n = __shfl_up_sync(0xffffffffu, incl, o);
        if (lane >= o) incl += n;
    }
    if (lane == 31) wsum[w] = incl;
    __syncthreads();
    if (t < 32) {
        int v = wsum[t]; int inc2 = v;
        #pragma unroll
        for (int o = 1; o < 32; o <<= 1) {
            int n = __shfl_up_sync(0xffffffffu, inc2, o);
            if (t >= o) inc2 += n;
        }
        wsum[t] = inc2 - v;
        if (t == 31) s_nv = inc2;
    }
    __syncthreads();
    int v_run = (incl - cnt) + wsum[w];
    #pragma unroll
    for (int j = 0; j < 25; j++) {
        int p = base + j;
        if ((flags >> j) & 1u) {
            if (v_run < NS) d_vlist[b*NS + v_run] = p;
            v_run++;
        } else {
            int ir = p - v_run;
            if (ir < NS) d_ilist[b*NS + ir] = p;
        }
    }
    __syncthreads();
    int nv = s_nv; if (nv > NS) nv = NS;
    int s = t;
    int p, se;
    if (s < nv) { p = d_vlist[b*NS + s];        se = 1; }
    else        { p = d_ilist[b*NS + (s - nv)]; se = 0; }
    int col = b*NS + s;
    d_idx[col] = p;
    d_sel[col] = se;
    d_spv[col] = (int)sp[(long long)b*HWP + p];
    d_rowA[col] = 0.f; d_rowB[col] = 0.f; d_rowD[col] = 0.f; d_ss[col] = 0.f;
}

// ---------- gather feats -> Gbf[col][c] bf16 ----------
__global__ void k_gather(const float* __restrict__ feats) {
    int t = threadIdx.x;
    int s = blockIdx.x*256 + t;
    int b = blockIdx.z;
    int c0 = blockIdx.y*16;
    int col = b*NS + s;
    int p = d_idx[col];
    const float* fb = feats + ((long long)b*NC + c0)*HWP + p;
    uint32_t pk[8];
    #pragma unroll
    for (int cc = 0; cc < 8; cc++) {
        float v0 = __ldg(&fb[(long long)(2*cc  )*HWP]);
        float v1 = __ldg(&fb[(long long)(2*cc+1)*HWP]);
        __nv_bfloat162 pr = __floats2bfloat162_rn(v0, v1);
        pk[cc] = *(uint32_t*)&pr;
    }
    uint4* dst = (uint4*)&d_Gbf[(size_t)col*NC + c0];
    dst[0] = make_uint4(pk[0], pk[1], pk[2], pk[3]);
    dst[1] = make_uint4(pk[4], pk[5], pk[6], pk[7]);
}

// ---------- mma mainloop: 64x64 tile, K=256, 4-stage cp.async, ldmatrix fragments ----------
__device__ __forceinline__ void mma_mainloop(const bf16* __restrict__ A,
                                             const bf16* __restrict__ X,
                                             bf16* sA, bf16* sB,
                                             int m0, int n0, float acc[2][2][4]) {
    int t = threadIdx.x;
    int w = t >> 5, lane = t & 31;
    int wm = w >> 2, wn = w & 3;
    int frow = t >> 2, fchk = (t & 3)*8;
    const bf16* gA = &A[(size_t)(m0+frow)*NC + fchk];
    const bf16* gB = &X[(size_t)(n0+frow)*NC + fchk];
    #pragma unroll
    for (int pc = 0; pc < 3; pc++) {
        cp16(&sA[pc*2560 + frow*40 + fchk], gA + pc*32);
        cp16(&sB[pc*2560 + frow*40 + fchk], gB + pc*32);
        CP_COMMIT();
    }
    uint32_t sAb = (uint32_t)__cvta_generic_to_shared(sA);
    uint32_t sBb = (uint32_t)__cvta_generic_to_shared(sB);
    int lane7 = lane & 7;
    uint32_t aoff[2];
    #pragma unroll
    for (int mt = 0; mt < 2; mt++) {
        int rb = wm*32 + mt*16;
        aoff[mt] = ((rb + ((lane>>3)&1)*8 + lane7)*40 + (lane>>4)*8)*2;
    }
    uint32_t boff = ((wn*16 + ((lane>>4)&1)*8 + lane7)*40 + ((lane>>3)&1)*8)*2;

    for (int kc = 0; kc < 8; kc++) {
        int cur = kc & 3;
        CP_WAIT2();
        __syncthreads();
        if (kc + 3 < 8) {
            int nxt = (kc + 3) & 3;
            cp16(&sA[nxt*2560 + frow*40 + fchk], gA + (kc+3)*32);
            cp16(&sB[nxt*2560 + frow*40 + fchk], gB + (kc+3)*32);
        }
        CP_COMMIT();
        uint32_t cAa = sAb + cur*5120;
        uint32_t cBa = sBb + cur*5120;
        #pragma unroll
        for (int ks = 0; ks < 2; ks++) {
            uint32_t kbB = ks*32;
            uint32_t a[2][4], bb[2][2];
            #pragma unroll
            for (int mt = 0; mt < 2; mt++)
                ldsm_x4(a[mt][0], a[mt][1], a[mt][2], a[mt][3], cAa + aoff[mt] + kbB);
            ldsm_x4(bb[0][0], bb[0][1], bb[1][0], bb[1][1], cBa + boff + kbB);
            #pragma unroll
            for (int mt = 0; mt < 2; mt++)
                #pragma unroll
                for (int nt = 0; nt < 2; nt++)
                    asm volatile(
                        "mma.sync.aligned.m16n8k16.row.col.f32.bf16.bf16.f32 "
                        "{%0,%1,%2,%3}, {%4,%5,%6,%7}, {%8,%9}, {%0,%1,%2,%3};"
                        : "+f"(acc[mt][nt][0]), "+f"(acc[mt][nt][1]),
                          "+f"(acc[mt][nt][2]), "+f"(acc[mt][nt][3])
                        : "r"(a[mt][0]), "r"(a[mt][1]), "r"(a[mt][2]), "r"(a[mt][3]),
                          "r"(bb[nt][0]), "r"(bb[nt][1]));
        }
    }
}

// ---------- transposed bf16 store epilogue ----------
template<bool RELU, bool SS>
__device__ __forceinline__ void store_T(float acc[2][2][4], const float* __restrict__ bias,
                                        bf16* sT /*64 x 72*/, float* s_ss,
                                        bf16* __restrict__ Y, int m0, int n0) {
    int t = threadIdx.x;
    int w = t >> 5, lane = t & 31;
    int g = lane >> 2, tig = lane & 3;
    int wm = w >> 2, wn = w & 3;
    if (SS && t < 64) s_ss[t] = 0.f;
    __syncthreads();
    #pragma unroll
    for (int mt = 0; mt < 2; mt++) {
        #pragma unroll
        for (int half = 0; half < 2; half++) {
            int r = wm*32 + mt*16 + half*8 + g;
            float bv = bias[m0 + r];
            #pragma unroll
            for (int nt = 0; nt < 2; nt++) {
                #pragma unroll
                for (int c = 0; c < 2; c++) {
                    int cl = wn*16 + nt*8 + tig*2 + c;
                    float v = acc[mt][nt][half*2 + c] + bv;
                    if (RELU) v = fmaxf(v, 0.f);
                    sT[cl*72 + r] = __float2bfloat16(v);
                }
            }
        }
    }
    __syncthreads();
    #pragma unroll
    for (int i = 0; i < 2; i++) {
        int e = t*2 + i;
        int row = e >> 3, chk = (e & 7)*8;
        uint4 v = *(uint4*)&sT[row*72 + chk];
        *(uint4*)&Y[(size_t)(n0+row)*NC + m0 + chk] = v;
        if (SS) {
            bf16* h = (bf16*)&v;
            float p = 0.f;
            #pragma unroll
            for (int q = 0; q < 8; q++) {
                float f = __bfloat162float(h[q]);
                p = fmaf(f, f, p);
            }
            atomicAdd(&s_ss[row], p);
        }
    }
    if (SS) {
        __syncthreads();
        if (t < 64) atomicAdd(&d_ss[n0 + t], s_ss[t]);
    }
}

// ---------- gemm1 (tensor) + attn (tensor) ----------
__global__ __launch_bounds__(256) void k_mma1(const float* __restrict__ b1,
                      const float* __restrict__ ba1, const float* __restrict__ wa2,
                      const float* __restrict__ ba2) {
    __shared__ __align__(16) char buf[40960];
    __shared__ float sRed[2][64];
    bf16* sA = (bf16*)buf;
    bf16* sB = (bf16*)(buf + 20480);
    bf16* sT = (bf16*)buf;
    int x = blockIdx.x, y = blockIdx.y;
    int n0 = x*64;
    float acc[2][2][4] = {};
    if (y < 4) {
        int m0 = y*64;
        mma_mainloop(d_w1bf, d_Gbf, sA, sB, m0, n0, acc);
        store_T<true, false>(acc, b1, sT, nullptr, d_Hbf, m0, n0);
    } else {
        mma_mainloop(d_wa1bf, d_Gbf, sA, sB, 0, n0, acc);
        int t = threadIdx.x;
        int w = t >> 5, lane = t & 31;
        int g = lane >> 2, tig = lane & 3;
        int wm = w >> 2, wn = w & 3;
        float part[2][2] = {};
        #pragma unroll
        for (int mt = 0; mt < 2; mt++) {
            #pragma unroll
            for (int half = 0; half < 2; half++) {
                int r = wm*32 + mt*16 + half*8 + g;
                float bm = ba1[r], wmv = wa2[r];
                #pragma unroll
                for (int nt = 0; nt < 2; nt++)
                    #pragma unroll
                    for (int c = 0; c < 2; c++)
                        part[nt][c] = fmaf(wmv, fmaxf(acc[mt][nt][half*2+c] + bm, 0.f), part[nt][c]);
            }
        }
        #pragma unroll
        for (int nt = 0; nt < 2; nt++)
            #pragma unroll
            for (int c = 0; c < 2; c++) {
                part[nt][c] += __shfl_down_sync(0xffffffffu, part[nt][c], 16);
                part[nt][c] += __shfl_down_sync(0xffffffffu, part[nt][c], 8);
                part[nt][c] += __shfl_down_sync(0xffffffffu, part[nt][c], 4);
            }
        if (g == 0) {
            #pragma unroll
            for (int nt = 0; nt < 2; nt++)
                #pragma unroll
                for (int c = 0; c < 2; c++)
                    sRed[wm][wn*16 + nt*8 + tig*2 + c] = part[nt][c];
        }
        __syncthreads();
        if (t < 64) {
            float z = sRed[0][t] + sRed[1][t] + ba2[0];
            d_attn[n0 + t] = 1.f / (1.f + expf(-z));
        }
    }
}

// ---------- gemm2 (tensor) ----------
__global__ __launch_bounds__(256) void k_mma2(const float* __restrict__ b2) {
    __shared__ __align__(16) char buf[40960];
    __shared__ float s_ss[64];
    bf16* sA = (bf16*)buf;
    bf16* sB = (bf16*)(buf + 20480);
    bf16* sT = (bf16*)buf;
    int m0 = blockIdx.y*64, n0 = blockIdx.x*64;
    float acc[2][2][4] = {};
    mma_mainloop(d_w2bf, d_Hbf, sA, sB, m0, n0, acc);
    store_T<false, true>(acc, b2, sT, s_ss, d_Ptbf, m0, n0);
}

// ---------- symmetric tensor-core sim + fused final ----------
#define SIMT_SMEM (4*10240*2)
#define NPAIR 36

__global__ __launch_bounds__(256) void k_simt(float* __restrict__ out) {
    extern __shared__ __align__(16) char dbuf[];
    bf16* sA = (bf16*)dbuf;                      // 4 stages x 5120 halves
    bf16* sB = (bf16*)(dbuf + 4*10240);
    __shared__ int   spJ[128];
    __shared__ int   seJ[128];
    __shared__ float wJ[128];
    __shared__ float rnJ[128];
    __shared__ float stageC[3][4][128];
    __shared__ int   s_last;
    int t = threadIdx.x;
    int pid = blockIdx.x, b = blockIdx.z;
    int I = 0, rem = pid;
    while (rem >= (8 - I)) { rem -= (8 - I); I++; }
    int J = I + rem;
    int i0 = I*128, j0 = J*128;
    bool diag = (I == J);
    if (t < 128) {
        int cj = b*NS + j0 + t;
        spJ[t] = d_spv[cj]; seJ[t] = d_sel[cj]; wJ[t] = d_attn[cj];
        rnJ[t] = 1.f / fmaxf(sqrtf(d_ss[cj]), 1e-12f);
    }
    int w = t >> 5, lane = t & 31;
    int g = lane >> 2, tig = lane & 3;
    int wm = w >> 1, wn = w & 1;
    const bf16* TA = d_Ptbf + (size_t)(b*NS + i0)*NC;
    const bf16* TB = d_Ptbf + (size_t)(b*NS + j0)*NC;
    int lrow = t >> 1, lpart = (t & 1)*16;

    #pragma unroll
    for (int pc = 0; pc < 3; pc++) {
        int kk = pc*32;
        cp16(&sA[pc*5120 + lrow*40 + lpart],     &TA[lrow*NC + kk + lpart]);
        cp16(&sA[pc*5120 + lrow*40 + lpart + 8], &TA[lrow*NC + kk + lpart + 8]);
        cp16(&sB[pc*5120 + lrow*40 + lpart],     &TB[lrow*NC + kk + lpart]);
        cp16(&sB[pc*5120 + lrow*40 + lpart + 8], &TB[lrow*NC + kk + lpart + 8]);
        CP_COMMIT();
    }

    uint32_t sAb = (uint32_t)__cvta_generic_to_shared(sA);
    uint32_t sBb = (uint32_t)__cvta_generic_to_shared(sB);
    int lane7 = lane & 7;
    uint32_t aoff[2];
    #pragma unroll
    for (int mt = 0; mt < 2; mt++) {
        int rb = wm*32 + mt*16;
        aoff[mt] = ((rb + ((lane>>3)&1)*8 + lane7)*40 + (lane>>4)*8)*2;
    }
    uint32_t boff[4];
    #pragma unroll
    for (int pr = 0; pr < 4; pr++) {
        int nb = wn*64 + pr*16;
        boff[pr] = ((nb + ((lane>>4)&1)*8 + lane7)*40 + ((lane>>3)&1)*8)*2;
    }

    float acc[2][8][4] = {};
    for (int kc = 0; kc < 8; kc++) {
        int cur = kc & 3;
        CP_WAIT2();
        __syncthreads();
        if (kc + 3 < 8) {
            int nxt = (kc + 3) & 3;
            int kk = (kc+3)*32;
            cp16(&sA[nxt*5120 + lrow*40 + lpart],     &TA[lrow*NC + kk + lpart]);
            cp16(&sA[nxt*5120 + lrow*40 + lpart + 8], &TA[lrow*NC + kk + lpart + 8]);
            cp16(&sB[nxt*5120 + lrow*40 + lpart],     &TB[lrow*NC + kk + lpart]);
            cp16(&sB[nxt*5120 + lrow*40 + lpart + 8], &TB[lrow*NC + kk + lpart + 8]);
        }
        CP_COMMIT();
        uint32_t cAa = sAb + cur*10240;
        uint32_t cBa = sBb + cur*10240;
        #pragma unroll
        for (int ks = 0; ks < 2; ks++) {
            uint32_t kbB = ks*32;
            uint32_t a[2][4];
            #pragma unroll
            for (int mt = 0; mt < 2; mt++)
                ldsm_x4(a[mt][0], a[mt][1], a[mt][2], a[mt][3], cAa + aoff[mt] + kbB);
            #pragma unroll
            for (int pr = 0; pr < 4; pr++) {
                uint32_t b00, b01, b10, b11;
                ldsm_x4(b00, b01, b10, b11, cBa + boff[pr] + kbB);
                #pragma unroll
                for (int mt = 0; mt < 2; mt++) {
                    asm volatile(
                        "mma.sync.aligned.m16n8k16.row.col.f32.bf16.bf16.f32 "
                        "{%0,%1,%2,%3}, {%4,%5,%6,%7}, {%8,%9}, {%0,%1,%2,%3};"
                        : "+f"(acc[mt][2*pr][0]), "+f"(acc[mt][2*pr][1]),
                          "+f"(acc[mt][2*pr][2]), "+f"(acc[mt][2*pr][3])
                        : "r"(a[mt][0]), "r"(a[mt][1]), "r"(a[mt][2]), "r"(a[mt][3]),
                          "r"(b00), "r"(b01));
                    asm volatile(
                        "mma.sync.aligned.m16n8k16.row.col.f32.bf16.bf16.f32 "
                        "{%0,%1,%2,%3}, {%4,%5,%6,%7}, {%8,%9}, {%0,%1,%2,%3};"
                        : "+f"(acc[mt][2*pr+1][0]), "+f"(acc[mt][2*pr+1][1]),
                          "+f"(acc[mt][2*pr+1][2]), "+f"(acc[mt][2*pr+1][3])
                        : "r"(a[mt][0]), "r"(a[mt][1]), "r"(a[mt][2]), "r"(a[mt][3]),
                          "r"(b10), "r"(b11));
                }
            }
        }
    }

    // epilogue: row stats always; column stats for off-diag tiles (mirrored pairs)
    float colA[8][2] = {}, colB[8][2] = {}, colD[8][2] = {};
    #pragma unroll
    for (int mt = 0; mt < 2; mt++) {
        #pragma unroll
        for (int half = 0; half < 2; half++) {
            int il = wm*32 + mt*16 + half*8 + g;
            int ci = b*NS + i0 + il;
            int gi = i0 + il;
            int si = d_sel[ci], spi = d_spv[ci];
            float wi = d_attn[ci];
            float ri = 1.f / fmaxf(sqrtf(d_ss[ci]), 1e-12f);
            float rA = 0.f, rB = 0.f, rD = 0.f;
            #pragma unroll
            for (int nt = 0; nt < 8; nt++) {
                #pragma unroll
                for (int c = 0; c < 2; c++) {
                    int jl = wn*64 + nt*8 + tig*2 + c;
                    float s = acc[mt][nt][half*2 + c] * ri * rnJ[jl];
                    float e = __expf(10.0f * s);      // 1/TEMP = 10
                    int sj = seJ[jl];
                    if (sj) rD += e;
                    if (!diag && si) colD[nt][c] += e;
                    if (si && sj && (gi != j0 + jl) && (spi == spJ[jl]) && (s > 0.7f)) {
                        float pw = wi * wJ[jl];
                        rB += pw; rA = fmaf(pw, s, rA);
                        if (!diag) { colB[nt][c] += pw; colA[nt][c] = fmaf(pw, s, colA[nt][c]); }
                    }
                }
            }
            rA += __shfl_down_sync(0xffffffffu, rA, 2, 4);
            rA += __shfl_down_sync(0xffffffffu, rA, 1, 4);
            rB += __shfl_down_sync(0xffffffffu, rB, 2, 4);
            rB += __shfl_down_sync(0xffffffffu, rB, 1, 4);
            rD += __shfl_down_sync(0xffffffffu, rD, 2, 4);
            rD += __shfl_down_sync(0xffffffffu, rD, 1, 4);
            if (tig == 0) {
                atomicAdd(&d_rowA[ci], rA);
                atomicAdd(&d_rowB[ci], rB);
                atomicAdd(&d_rowD[ci], rD);
            }
        }
    }
    if (!diag) {
        // reduce column stats across the 8 g-lanes (same tig share columns)
        #pragma unroll
        for (int nt = 0; nt < 8; nt++) {
            #pragma unroll
            for (int c = 0; c < 2; c++) {
                #pragma unroll
                for (int off = 4; off <= 16; off <<= 1) {
                    colA[nt][c] += __shfl_down_sync(0xffffffffu, colA[nt][c], off);
                    colB[nt][c] += __shfl_down_sync(0xffffffffu, colB[nt][c], off);
                    colD[nt][c] += __shfl_down_sync(0xffffffffu, colD[nt][c], off);
                }
            }
        }
        if (g == 0) {   // lanes 0..3 hold sums for their tig
            #pragma unroll
            for (int nt = 0; nt < 8; nt++) {
                #pragma unroll
                for (int c = 0; c < 2; c++) {
                    int jl = wn*64 + nt*8 + tig*2 + c;
                    stageC[0][wm][jl] = colA[nt][c];
                    stageC[1][wm][jl] = colB[nt][c];
                    stageC[2][wm][jl] = colD[nt][c];
                }
            }
        }
        __syncthreads();
        if (t < 128) {
            float a0 = 0.f, b0 = 0.f, d0 = 0.f;
            #pragma unroll
            for (int ww = 0; ww < 4; ww++) {
                a0 += stageC[0][ww][t]; b0 += stageC[1][ww][t]; d0 += stageC[2][ww][t];
            }
            int cj = b*NS + j0 + t;
            atomicAdd(&d_rowA[cj], a0);
            atomicAdd(&d_rowB[cj], b0);
            atomicAdd(&d_rowD[cj], d0);
        }
    }

    // ---- last-block fused final reduction ----
    __syncthreads();
    if (t == 0) {
        __threadfence();
        int prev = atomicAdd(&d_cnt, 1);
        s_last = (prev == NPAIR*NB - 1);
    }
    __syncthreads();
    if (!s_last) return;
    __threadfence();

    __shared__ float red[256];
    __shared__ float s_num, s_ps;
    float totLoss = 0.f;
    int nHas = 0;
    for (int b2i = 0; b2i < NB; b2i++) {
        float num = 0.f, ps = 0.f;
        for (int i = t; i < NS; i += 256) {
            float Ai = d_rowA[b2i*NS+i], Bi = d_rowB[b2i*NS+i], Di = d_rowD[b2i*NS+i];
            float ld = logf(Di > 0.f ? Di : 1.f);
            num += Ai * 10.0f - ld * Bi;
            ps  += Bi;
        }
        red[t] = num; __syncthreads();
        for (int o = 128; o > 0; o >>= 1) { if (t < o) red[t] += red[t+o]; __syncthreads(); }
        if (t == 0) s_num = red[0];
        __syncthreads();
        red[t] = ps; __syncthreads();
        for (int o = 128; o > 0; o >>= 1) { if (t < o) red[t] += red[t+o]; __syncthreads(); }
        if (t == 0) s_ps = red[0];
        __syncthreads();
        if (t == 0) {
            if (s_ps > 0.f) {
                totLoss += -(0.1f/0.07f) * s_num / s_ps;
                nHas++;
            }
        }
        __syncthreads();
    }
    if (t == 0) out[0] = (nHas > 0) ? (totLoss / fmaxf((float)nHas, 1.f)) : 0.f;
}

extern "C" void kernel_launch(void* const* d_in, const int* in_sizes, int n_in,
                              void* d_out, int out_size) {
    const float*     feats  = (const float*)d_in[0];
    const long long* labels = (const long long*)d_in[1];
    const long long* sp     = (const long long*)d_in[2];
    const float*     w1     = (const float*)d_in[3];
    const float*     b1     = (const float*)d_in[4];
    const float*     w2     = (const float*)d_in[5];
    const float*     b2     = (const float*)d_in[6];
    const float*     wa1    = (const float*)d_in[7];
    const float*     ba1    = (const float*)d_in[8];
    const float*     wa2    = (const float*)d_in[9];
    const float*     ba2    = (const float*)d_in[10];
    float* out = (float*)d_out;

    static bool inited = false;
    if (!inited) {
        cudaFuncSetAttribute(k_simt, cudaFuncAttributeMaxDynamicSharedMemorySize, SIMT_SMEM);
        inited = true;
    }

    k_prep  <<<NB + 36, 1024>>>(labels, sp, w1, w2, wa1);
    k_gather<<<dim3(NS/256, NC/16, NB), 256>>>(feats);
    k_mma1  <<<dim3(64, 5), 256>>>(b1, ba1, wa2, ba2);
    k_mma2  <<<dim3(64, 4), 256>>>(b2);
    k_simt  <<<dim3(NPAIR, 1, NB), 256, SIMT_SMEM>>>(out);
}